// round 1
// baseline (speedup 1.0000x reference)
#include <cuda_runtime.h>
#include <math.h>

// Problem constants
#define Bb 4
#define Tt 2048
#define Cc 1024
#define Hh 8
#define HKV 4
#define Dd 128
#define Gg 512
#define HIi 8
#define DIi 64
#define RANKr 512
#define NEGv (-1e30f)

#define NTOK (Bb*Tt)   // 8192

// ---------------- scratch (static device allocations) ----------------
__device__ alignas(256) float g_Pq [NTOK*1024];
__device__ alignas(256) float g_Pck[NTOK*512];
__device__ alignas(256) float g_Pcv[NTOK*512];
__device__ alignas(256) float g_Pcg[NTOK*512];
__device__ alignas(256) float g_Piq[NTOK*512];
__device__ alignas(256) float g_Pik[NTOK*512];
__device__ alignas(256) float g_Pig[NTOK*512];
__device__ alignas(256) float g_ck [Bb*Gg*HKV*Dd];
__device__ alignas(256) float g_cv [Bb*Gg*HKV*Dd];
__device__ alignas(256) float g_ik [Bb*Gg*HIi*DIi];
__device__ alignas(256) float g_iq [NTOK*512];
__device__ alignas(256) float g_isc[NTOK*Gg];
__device__ alignas(256) float g_thr[NTOK];
__device__ alignas(256) float g_at [NTOK*1024];
__device__ alignas(256) float g_r  [NTOK*512];
__device__ alignas(256) float g_rn [NTOK*512];

// ---------------- SGEMM (NN): C[M,N] = alpha * A[M,K] @ B[K,N] ----------------
// BM=BN=128, BK=8, 256 threads, 8x8 per thread. Requires M%128==0, N%128==0, K%8==0.
__global__ void sgemm_nn(int M, int N, int K, float alpha,
                         const float* __restrict__ A,
                         const float* __restrict__ B,
                         float* __restrict__ C) {
    __shared__ alignas(16) float As[8][128];
    __shared__ alignas(16) float Bs[8][128];
    const int tid = threadIdx.x;
    const int bx = blockIdx.x, by = blockIdx.y;
    const int aRow = tid >> 1, aK = (tid & 1) * 4;
    const int bK = tid >> 5, bCol = (tid & 31) * 4;
    const int tx = tid & 15, ty = tid >> 4;

    const float* Ab = A + (size_t)(by * 128) * K;
    const float* Bbp = B + bx * 128;
    float acc[8][8];
    #pragma unroll
    for (int i = 0; i < 8; i++)
        #pragma unroll
        for (int j = 0; j < 8; j++) acc[i][j] = 0.f;

    for (int k0 = 0; k0 < K; k0 += 8) {
        float4 av = *(const float4*)(Ab + (size_t)aRow * K + k0 + aK);
        As[aK+0][aRow] = av.x; As[aK+1][aRow] = av.y;
        As[aK+2][aRow] = av.z; As[aK+3][aRow] = av.w;
        float4 bv = *(const float4*)(Bbp + (size_t)(k0 + bK) * N + bCol);
        *(float4*)&Bs[bK][bCol] = bv;
        __syncthreads();
        #pragma unroll
        for (int k = 0; k < 8; k++) {
            float ar[8], br[8];
            #pragma unroll
            for (int i = 0; i < 8; i++) ar[i] = As[k][ty*8 + i];
            #pragma unroll
            for (int j = 0; j < 8; j++) br[j] = Bs[k][tx*8 + j];
            #pragma unroll
            for (int i = 0; i < 8; i++)
                #pragma unroll
                for (int j = 0; j < 8; j++) acc[i][j] += ar[i] * br[j];
        }
        __syncthreads();
    }
    float* Cb = C + (size_t)(by*128 + ty*8) * N + bx*128 + tx*8;
    #pragma unroll
    for (int i = 0; i < 8; i++)
        #pragma unroll
        for (int j = 0; j < 8; j += 4) {
            float4 v = make_float4(acc[i][j]*alpha, acc[i][j+1]*alpha,
                                   acc[i][j+2]*alpha, acc[i][j+3]*alpha);
            *(float4*)(Cb + (size_t)i * N + j) = v;
        }
}

// ---------------- SGEMM (NT): C[M,N] = alpha * A[M,K] @ B[N,K]^T ----------------
__global__ void sgemm_nt(int M, int N, int K, float alpha,
                         const float* __restrict__ A,
                         const float* __restrict__ B,
                         float* __restrict__ C) {
    __shared__ alignas(16) float As[8][128];
    __shared__ alignas(16) float Bs[8][128];
    const int tid = threadIdx.x;
    const int bx = blockIdx.x, by = blockIdx.y;
    const int aRow = tid >> 1, aK = (tid & 1) * 4;
    const int tx = tid & 15, ty = tid >> 4;

    const float* Ab = A + (size_t)(by * 128) * K;
    const float* Bbp = B + (size_t)(bx * 128) * K;
    float acc[8][8];
    #pragma unroll
    for (int i = 0; i < 8; i++)
        #pragma unroll
        for (int j = 0; j < 8; j++) acc[i][j] = 0.f;

    for (int k0 = 0; k0 < K; k0 += 8) {
        float4 av = *(const float4*)(Ab + (size_t)aRow * K + k0 + aK);
        As[aK+0][aRow] = av.x; As[aK+1][aRow] = av.y;
        As[aK+2][aRow] = av.z; As[aK+3][aRow] = av.w;
        float4 bv = *(const float4*)(Bbp + (size_t)aRow * K + k0 + aK);
        Bs[aK+0][aRow] = bv.x; Bs[aK+1][aRow] = bv.y;
        Bs[aK+2][aRow] = bv.z; Bs[aK+3][aRow] = bv.w;
        __syncthreads();
        #pragma unroll
        for (int k = 0; k < 8; k++) {
            float ar[8], br[8];
            #pragma unroll
            for (int i = 0; i < 8; i++) ar[i] = As[k][ty*8 + i];
            #pragma unroll
            for (int j = 0; j < 8; j++) br[j] = Bs[k][tx*8 + j];
            #pragma unroll
            for (int i = 0; i < 8; i++)
                #pragma unroll
                for (int j = 0; j < 8; j++) acc[i][j] += ar[i] * br[j];
        }
        __syncthreads();
    }
    float* Cb = C + (size_t)(by*128 + ty*8) * N + bx*128 + tx*8;
    #pragma unroll
    for (int i = 0; i < 8; i++)
        #pragma unroll
        for (int j = 0; j < 8; j += 4) {
            float4 v = make_float4(acc[i][j]*alpha, acc[i][j+1]*alpha,
                                   acc[i][j+2]*alpha, acc[i][j+3]*alpha);
            *(float4*)(Cb + (size_t)i * N + j) = v;
        }
}

// ---------------- rope helper ----------------
__device__ __forceinline__ void rope_cs(int i, float pos, float& c, float& s) {
    float f = powf(160000.0f, (float)i * (1.0f / 32.0f));
    float ang = pos / f;
    sincosf(ang, &s, &c);
}

// ---------------- gated compress (coarse KV, HKV=4, D=128) + rope on ck ----------------
// grid: Bb*Gg*HKV, block 128
__global__ void compress_c(const float* __restrict__ ape) {
    int blk = blockIdx.x;
    int h = blk & 3;
    int bg = blk >> 2;               // b*Gg + g
    int g = bg & (Gg - 1);
    int d = threadIdx.x;
    size_t base = (size_t)bg * 4 * 512 + h * 128 + d;   // row b*T + 4g
    float gv[4], m = -1e30f;
    #pragma unroll
    for (int r = 0; r < 4; r++) {
        gv[r] = g_Pcg[base + (size_t)r * 512] + ape[(r * HKV + h) * 128 + d];
        m = fmaxf(m, gv[r]);
    }
    float ssum = 0.f;
    #pragma unroll
    for (int r = 0; r < 4; r++) { gv[r] = expf(gv[r] - m); ssum += gv[r]; }
    float inv = 1.f / ssum;
    float ka = 0.f, va = 0.f;
    #pragma unroll
    for (int r = 0; r < 4; r++) {
        float w = gv[r] * inv;
        ka += w * g_Pck[base + (size_t)r * 512];
        va += w * g_Pcv[base + (size_t)r * 512];
    }
    __shared__ float sk[128];
    sk[d] = ka;
    __syncthreads();
    float pos = (float)(4 * g + 3);
    float outk = ka;
    if (d >= 64 && d < 96) {
        int i = d - 64; float c, s; rope_cs(i, pos, c, s);
        outk = sk[d] * c - sk[d + 32] * s;
    } else if (d >= 96) {
        int i = d - 96; float c, s; rope_cs(i, pos, c, s);
        outk = sk[d - 32] * s + sk[d] * c;
    }
    size_t ob = ((size_t)bg * 4 + h) * 128 + d;
    g_ck[ob] = outk;
    g_cv[ob] = va;
}

// ---------------- gated compress (index KV, HI=8, DI=64) + rmsnorm ----------------
// grid: Bb*Gg*HIi, block 64
__global__ void compress_i(const float* __restrict__ ape) {
    int blk = blockIdx.x;
    int h = blk & 7;
    int bg = blk >> 3;
    int d = threadIdx.x;
    size_t base = (size_t)bg * 4 * 512 + h * 64 + d;
    float gv[4], m = -1e30f;
    #pragma unroll
    for (int r = 0; r < 4; r++) {
        gv[r] = g_Pig[base + (size_t)r * 512] + ape[(r * HIi + h) * 64 + d];
        m = fmaxf(m, gv[r]);
    }
    float ssum = 0.f;
    #pragma unroll
    for (int r = 0; r < 4; r++) { gv[r] = expf(gv[r] - m); ssum += gv[r]; }
    float inv = 1.f / ssum;
    float ka = 0.f;
    #pragma unroll
    for (int r = 0; r < 4; r++) ka += gv[r] * inv * g_Pik[base + (size_t)r * 512];
    __shared__ float red[64];
    red[d] = ka * ka;
    __syncthreads();
    #pragma unroll
    for (int s2 = 32; s2 > 0; s2 >>= 1) {
        if (d < s2) red[d] += red[d + s2];
        __syncthreads();
    }
    float sc = rsqrtf(red[0] / 64.f + 1e-6f);
    g_ik[((size_t)bg * 8 + h) * 64 + d] = ka * sc;
}

// ---------------- per-head rmsnorm of iq ---------------- grid NTOK*HIi, block 64
__global__ void iq_rms() {
    int blk = blockIdx.x;
    int h = blk & 7;
    int row = blk >> 3;
    int d = threadIdx.x;
    size_t idx = (size_t)row * 512 + h * 64 + d;
    float v = g_Piq[idx];
    __shared__ float red[64];
    red[d] = v * v;
    __syncthreads();
    #pragma unroll
    for (int s2 = 32; s2 > 0; s2 >>= 1) {
        if (d < s2) red[d] += red[d + s2];
        __syncthreads();
    }
    float sc = rsqrtf(red[0] / 64.f + 1e-6f);
    g_iq[idx] = v * sc;
}

// ---------------- in-place partial rope of q ---------------- grid NTOK*Hh, block 32
__global__ void q_rope() {
    int blk = blockIdx.x;
    int h = blk & 7;
    int row = blk >> 3;
    int t = row & (Tt - 1);
    int i = threadIdx.x;
    size_t base = (size_t)row * 1024 + h * 128;
    float x1 = g_Pq[base + 64 + i];
    float x2 = g_Pq[base + 96 + i];
    float c, s; rope_cs(i, (float)t, c, s);
    g_Pq[base + 64 + i] = x1 * c - x2 * s;
    g_Pq[base + 96 + i] = x1 * s + x2 * c;
}

// ---------------- top-k(64) threshold via bitonic sort ---------------- grid NTOK, block 512
__global__ void topk_thresh() {
    __shared__ float s[512];
    int row = blockIdx.x;
    int t = row & (Tt - 1);
    int tid = threadIdx.x;
    float v = g_isc[(size_t)row * Gg + tid];
    if (4 * tid + 3 > t) v = NEGv;          // causal mask
    s[tid] = v;
    __syncthreads();
    for (int k = 2; k <= 512; k <<= 1) {
        for (int j = k >> 1; j > 0; j >>= 1) {
            int ixj = tid ^ j;
            if (ixj > tid) {
                float a = s[tid], b = s[ixj];
                bool down = ((tid & k) == 0);   // descending sort
                bool sw = down ? (a < b) : (a > b);
                if (sw) { s[tid] = b; s[ixj] = a; }
            }
            __syncthreads();
        }
    }
    if (tid == 0) g_thr[row] = s[63];
}

// ---------------- sparse attention over selected groups ---------------- grid NTOK*Hh, block 128
__global__ void attn_kernel() {
    int blk = blockIdx.x;
    int h = blk & 7;
    int row = blk >> 3;                 // b*T + t
    int t = row & (Tt - 1);
    int b = row >> 11;
    int tid = threadIdx.x;
    __shared__ int sg[96];
    __shared__ float sw[96];
    __shared__ int cnt;
    __shared__ alignas(16) float qsh[128];
    if (tid == 0) cnt = 0;
    __syncthreads();

    int nc = (t >= 3) ? (((t - 3) >> 2) + 1) : 0;
    float th = g_thr[row];
    const float* iscr = g_isc + (size_t)row * Gg;
    for (int g = tid; g < nc; g += 128) {
        if (iscr[g] >= th) {
            int p = atomicAdd(&cnt, 1);
            if (p < 96) sg[p] = g;
        }
    }
    qsh[tid] = g_Pq[(size_t)row * 1024 + h * 128 + tid];
    __syncthreads();
    int n = min(cnt, 96);
    int hkv = h >> 1;
    int warp = tid >> 5, lane = tid & 31;
    for (int i = warp; i < n; i += 4) {
        const float* kp = g_ck + ((size_t)(b * Gg + sg[i]) * 4 + hkv) * 128;
        float4 kv = *(const float4*)(kp + lane * 4);
        float4 qv = *(const float4*)(qsh + lane * 4);
        float p = qv.x * kv.x + qv.y * kv.y + qv.z * kv.z + qv.w * kv.w;
        #pragma unroll
        for (int o = 16; o > 0; o >>= 1) p += __shfl_xor_sync(0xffffffffu, p, o);
        if (lane == 0) sw[i] = p * 0.0883883476483184f;   // D^-0.5
    }
    __syncthreads();
    if (tid == 0 && n > 0) {
        float m = -1e30f;
        for (int i = 0; i < n; i++) m = fmaxf(m, sw[i]);
        float ssum = 0.f;
        for (int i = 0; i < n; i++) { float e = expf(sw[i] - m); sw[i] = e; ssum += e; }
        float inv = 1.f / ssum;
        for (int i = 0; i < n; i++) sw[i] *= inv;
    }
    __syncthreads();
    float acc = 0.f;
    for (int i = 0; i < n; i++)
        acc += sw[i] * g_cv[((size_t)(b * Gg + sg[i]) * 4 + hkv) * 128 + tid];
    g_at[(size_t)row * 1024 + h * 128 + tid] = acc;
}

// ---------------- rmsnorm over RANK=512 ---------------- grid NTOK, block 256
__global__ void rmsnorm512() {
    int row = blockIdx.x;
    int tid = threadIdx.x;
    size_t base = (size_t)row * 512;
    float a = g_r[base + tid], b = g_r[base + 256 + tid];
    __shared__ float red[256];
    red[tid] = a * a + b * b;
    __syncthreads();
    #pragma unroll
    for (int s2 = 128; s2 > 0; s2 >>= 1) {
        if (tid < s2) red[tid] += red[tid + s2];
        __syncthreads();
    }
    float sc = rsqrtf(red[0] / 512.f + 1e-6f);
    g_rn[base + tid] = a * sc;
    g_rn[base + 256 + tid] = b * sc;
}

// ---------------- launch ----------------
extern "C" void kernel_launch(void* const* d_in, const int* in_sizes, int n_in,
                              void* d_out, int out_size) {
    const float* x     = (const float*)d_in[0];
    const float* Wq    = (const float*)d_in[1];
    const float* Wck   = (const float*)d_in[2];
    const float* Wcv   = (const float*)d_in[3];
    const float* Wcg   = (const float*)d_in[4];
    const float* ape_c = (const float*)d_in[5];
    const float* Wiq   = (const float*)d_in[6];
    const float* Wik   = (const float*)d_in[7];
    const float* Wig   = (const float*)d_in[8];
    const float* ape_i = (const float*)d_in[9];
    const float* Wa    = (const float*)d_in[10];
    const float* Wb    = (const float*)d_in[11];
    float* out = (float*)d_out;

    float *Pq, *Pck, *Pcv, *Pcg, *Piq, *Pik, *Pig, *ik, *iq, *isc, *at, *r, *rn;
    cudaGetSymbolAddress((void**)&Pq,  g_Pq);
    cudaGetSymbolAddress((void**)&Pck, g_Pck);
    cudaGetSymbolAddress((void**)&Pcv, g_Pcv);
    cudaGetSymbolAddress((void**)&Pcg, g_Pcg);
    cudaGetSymbolAddress((void**)&Piq, g_Piq);
    cudaGetSymbolAddress((void**)&Pik, g_Pik);
    cudaGetSymbolAddress((void**)&Pig, g_Pig);
    cudaGetSymbolAddress((void**)&ik,  g_ik);
    cudaGetSymbolAddress((void**)&iq,  g_iq);
    cudaGetSymbolAddress((void**)&isc, g_isc);
    cudaGetSymbolAddress((void**)&at,  g_at);
    cudaGetSymbolAddress((void**)&r,   g_r);
    cudaGetSymbolAddress((void**)&rn,  g_rn);

    dim3 blk(256);
    // Projections
    sgemm_nn<<<dim3(1024/128, NTOK/128), blk>>>(NTOK, 1024, 1024, 1.f, x, Wq,  Pq);
    sgemm_nn<<<dim3( 512/128, NTOK/128), blk>>>(NTOK,  512, 1024, 1.f, x, Wck, Pck);
    sgemm_nn<<<dim3( 512/128, NTOK/128), blk>>>(NTOK,  512, 1024, 1.f, x, Wcv, Pcv);
    sgemm_nn<<<dim3( 512/128, NTOK/128), blk>>>(NTOK,  512, 1024, 1.f, x, Wcg, Pcg);
    sgemm_nn<<<dim3( 512/128, NTOK/128), blk>>>(NTOK,  512, 1024, 1.f, x, Wiq, Piq);
    sgemm_nn<<<dim3( 512/128, NTOK/128), blk>>>(NTOK,  512, 1024, 1.f, x, Wik, Pik);
    sgemm_nn<<<dim3( 512/128, NTOK/128), blk>>>(NTOK,  512, 1024, 1.f, x, Wig, Pig);

    // Compress + norms + rope
    compress_c<<<Bb*Gg*HKV, 128>>>(ape_c);
    compress_i<<<Bb*Gg*HIi, 64>>>(ape_i);
    iq_rms<<<NTOK*HIi, 64>>>();
    q_rope<<<NTOK*Hh, 32>>>();

    // Index scores: per-batch NT GEMM, alpha = DI^-0.5 / HI = 1/64
    for (int b = 0; b < Bb; b++) {
        sgemm_nt<<<dim3(512/128, 2048/128), blk>>>(
            2048, 512, 512, 1.f/64.f,
            iq + (size_t)b * 2048 * 512,
            ik + (size_t)b * 512 * 512,
            isc + (size_t)b * 2048 * 512);
    }

    topk_thresh<<<NTOK, 512>>>();
    attn_kernel<<<NTOK*Hh, 128>>>();

    // r = attn @ Wa^T  (Wa is (RANK, C) row-major)
    sgemm_nt<<<dim3(512/128, NTOK/128), blk>>>(NTOK, 512, 1024, 1.f, at, Wa, r);
    rmsnorm512<<<NTOK, 256>>>();
    // out = rn @ Wb
    sgemm_nn<<<dim3(1024/128, NTOK/128), blk>>>(NTOK, 1024, 512, 1.f, rn, Wb, out);
}

// round 4
// speedup vs baseline: 1.5172x; 1.5172x over previous
#include <cuda_runtime.h>
#include <math.h>
#include <stdint.h>

// Problem constants
#define Bb 4
#define Tt 2048
#define Cc 1024
#define Hh 8
#define HKV 4
#define Dd 128
#define Gg 512
#define HIi 8
#define DIi 64
#define RANKr 512
#define NEGv (-1e30f)

#define NTOK (Bb*Tt)   // 8192
#define NCOL 4096      // fused projection width: q|ck|cv|cg|iq|ik|ig
#define OFF_Q  0
#define OFF_CK 1024
#define OFF_CV 1536
#define OFF_CG 2048
#define OFF_IQ 2560
#define OFF_IK 3072
#define OFF_IG 3584

// ---------------- scratch (static device allocations) ----------------
__device__ alignas(256) float g_W   [1024*NCOL];
__device__ alignas(256) float g_Pall[(size_t)NTOK*NCOL];
__device__ alignas(256) float g_ck [Bb*Gg*HKV*Dd];
__device__ alignas(256) float g_cv [Bb*Gg*HKV*Dd];
__device__ alignas(256) float g_ik [Bb*Gg*HIi*DIi];
__device__ alignas(256) float g_iq [NTOK*512];
__device__ alignas(256) float g_isc[NTOK*Gg];
__device__ alignas(256) float g_thr[NTOK];
__device__ alignas(256) float g_at [NTOK*1024];
__device__ alignas(256) float g_r  [NTOK*512];
__device__ alignas(256) float g_rn [NTOK*512];

// ---------------- helpers ----------------
__device__ __forceinline__ void cpa16(uint32_t dst, const float* src) {
    asm volatile("cp.async.cg.shared.global [%0], [%1], 16;\n"
                 :: "r"(dst), "l"((const void*)src));
}
__device__ __forceinline__ void cp_commit() {
    asm volatile("cp.async.commit_group;\n");
}
__device__ __forceinline__ uint32_t f2tf(float f) {
    uint32_t u;
    asm("cvt.rna.tf32.f32 %0, %1;" : "=r"(u) : "f"(f));
    return u;
}
// 3xTF32 split: v = hi + lo (each representable in tf32)
__device__ __forceinline__ void split_tf(float v, uint32_t& hi, uint32_t& lo) {
    uint32_t h = f2tf(v);
    hi = h;
    lo = f2tf(v - __uint_as_float(h));
}
__device__ __forceinline__ void mma_tf32(float* c,
    uint32_t a0, uint32_t a1, uint32_t a2, uint32_t a3,
    uint32_t b0, uint32_t b1) {
    asm volatile(
        "mma.sync.aligned.m16n8k8.row.col.f32.tf32.tf32.f32 "
        "{%0,%1,%2,%3},{%4,%5,%6,%7},{%8,%9},{%0,%1,%2,%3};"
        : "+f"(c[0]), "+f"(c[1]), "+f"(c[2]), "+f"(c[3])
        : "r"(a0), "r"(a1), "r"(a2), "r"(a3), "r"(b0), "r"(b1));
}

// ---------------- 3xTF32 MMA GEMM (fp32-accurate) ----------------
// TB=0: C[M,N] = alpha*A[M,K]@B[K,N]   TB=1: C[M,N]=alpha*A[M,K]@B[N,K]^T
// BM=BN=128, BK=32, 256 threads (8 warps, 2x4), warp tile 64x32.
// Requires M%128==0, N%128==0, K%32==0. Batched via blockIdx.z with strides.
template<int TB>
__global__ void mma_gemm(int M, int N, int K, float alpha,
                         const float* __restrict__ A,
                         const float* __restrict__ B,
                         float* __restrict__ C,
                         long strA, long strB, long strC) {
    extern __shared__ char smraw[];
    float* sm = (float*)smraw;
    constexpr int ASTR = 36;
    constexpr int ASZ  = 128 * ASTR;          // 4608 floats per buf
    constexpr int BSTR = TB ? 36 : 136;
    constexpr int BSZ  = TB ? 128 * 36 : 32 * 136;

    const int tid  = threadIdx.x;
    const int wid  = tid >> 5;
    const int lane = tid & 31;
    const int lm   = lane >> 2;     // 0..7
    const int lk   = lane & 3;      // 0..3
    const int warp_m = (wid & 1) * 64;
    const int warp_n = (wid >> 1) * 32;
    const int bm = blockIdx.y * 128;
    const int bn = blockIdx.x * 128;
    const int z  = blockIdx.z;

    const float* Aptr = A + (size_t)z * strA + (size_t)bm * K;
    const float* Bptr = B + (size_t)z * strB + (TB ? (size_t)bn * K : (size_t)bn);
    float* Cptr = C + (size_t)z * strC + (size_t)(bm + warp_m) * N + bn + warp_n;

    uint32_t sbase = (uint32_t)__cvta_generic_to_shared(sm);

    float c[4][4][4];
    #pragma unroll
    for (int mt = 0; mt < 4; mt++)
        #pragma unroll
        for (int nt = 0; nt < 4; nt++)
            #pragma unroll
            for (int i = 0; i < 4; i++) c[mt][nt][i] = 0.f;

    const int nIter = K >> 5;

    // stage tile 'it' into buffer 'buf'
    auto stage = [&](int it, int buf) {
        const int k0 = it * 32;
        uint32_t sa = sbase + (uint32_t)(buf * ASZ) * 4u;
        uint32_t sb = sbase + (uint32_t)(2 * ASZ + buf * BSZ) * 4u;
        #pragma unroll
        for (int i = 0; i < 4; i++) {
            int idx = tid + i * 256;
            int m = idx >> 3, kq = idx & 7;
            cpa16(sa + (uint32_t)(m * ASTR + kq * 4) * 4u,
                  Aptr + (size_t)m * K + k0 + kq * 4);
        }
        if (TB == 0) {
            #pragma unroll
            for (int i = 0; i < 4; i++) {
                int idx = tid + i * 256;
                int k = idx >> 5, nq = idx & 31;
                cpa16(sb + (uint32_t)(k * BSTR + nq * 4) * 4u,
                      Bptr + (size_t)(k0 + k) * N + nq * 4);
            }
        } else {
            #pragma unroll
            for (int i = 0; i < 4; i++) {
                int idx = tid + i * 256;
                int n = idx >> 3, kq = idx & 7;
                cpa16(sb + (uint32_t)(n * BSTR + kq * 4) * 4u,
                      Bptr + (size_t)n * K + k0 + kq * 4);
            }
        }
        cp_commit();
    };

    stage(0, 0);

    for (int it = 0; it < nIter; it++) {
        const int buf = it & 1;
        if (it + 1 < nIter) {
            stage(it + 1, buf ^ 1);
            asm volatile("cp.async.wait_group 1;\n");
        } else {
            asm volatile("cp.async.wait_group 0;\n");
        }
        __syncthreads();

        const float* Asm = sm + buf * ASZ;
        const float* Bsm = sm + 2 * ASZ + buf * BSZ;

        #pragma unroll
        for (int kc = 0; kc < 4; kc++) {
            uint32_t afh[4][4], afl[4][4];
            #pragma unroll
            for (int mt = 0; mt < 4; mt++) {
                const float* p = Asm + (warp_m + mt * 16 + lm) * ASTR + kc * 8 + lk;
                split_tf(p[0],            afh[mt][0], afl[mt][0]);
                split_tf(p[8 * ASTR],     afh[mt][1], afl[mt][1]);
                split_tf(p[4],            afh[mt][2], afl[mt][2]);
                split_tf(p[8 * ASTR + 4], afh[mt][3], afl[mt][3]);
            }
            uint32_t bfh[4][2], bfl[4][2];
            #pragma unroll
            for (int nt = 0; nt < 4; nt++) {
                if (TB == 0) {
                    const float* p = Bsm + (kc * 8 + lk) * BSTR + warp_n + nt * 8 + lm;
                    split_tf(p[0],        bfh[nt][0], bfl[nt][0]);
                    split_tf(p[4 * BSTR], bfh[nt][1], bfl[nt][1]);
                } else {
                    const float* p = Bsm + (warp_n + nt * 8 + lm) * BSTR + kc * 8 + lk;
                    split_tf(p[0], bfh[nt][0], bfl[nt][0]);
                    split_tf(p[4], bfh[nt][1], bfl[nt][1]);
                }
            }
            #pragma unroll
            for (int mt = 0; mt < 4; mt++)
                #pragma unroll
                for (int nt = 0; nt < 4; nt++) {
                    // hi*lo + lo*hi first (small terms), then hi*hi
                    mma_tf32(c[mt][nt], afh[mt][0], afh[mt][1], afh[mt][2], afh[mt][3],
                             bfl[nt][0], bfl[nt][1]);
                    mma_tf32(c[mt][nt], afl[mt][0], afl[mt][1], afl[mt][2], afl[mt][3],
                             bfh[nt][0], bfh[nt][1]);
                    mma_tf32(c[mt][nt], afh[mt][0], afh[mt][1], afh[mt][2], afh[mt][3],
                             bfh[nt][0], bfh[nt][1]);
                }
        }
        __syncthreads();
    }

    #pragma unroll
    for (int mt = 0; mt < 4; mt++) {
        #pragma unroll
        for (int nt = 0; nt < 4; nt++) {
            int r0 = mt * 16 + lm;
            int cc = nt * 8 + 2 * lk;
            float2 v;
            v.x = c[mt][nt][0] * alpha; v.y = c[mt][nt][1] * alpha;
            *(float2*)(Cptr + (size_t)r0 * N + cc) = v;
            v.x = c[mt][nt][2] * alpha; v.y = c[mt][nt][3] * alpha;
            *(float2*)(Cptr + (size_t)(r0 + 8) * N + cc) = v;
        }
    }
}

// ---------------- weight concat: g_W[k][0..4095] = [Wq|Wck|Wcv|Wcg|Wiq|Wik|Wig]
__global__ void concat_w(const float* __restrict__ Wq,  const float* __restrict__ Wck,
                         const float* __restrict__ Wcv, const float* __restrict__ Wcg,
                         const float* __restrict__ Wiq, const float* __restrict__ Wik,
                         const float* __restrict__ Wig) {
    int idx = blockIdx.x * 256 + threadIdx.x;       // over 1024*4096
    int k = idx >> 12, col = idx & 4095;
    float v;
    if      (col < 1024) v = Wq [k * 1024 + col];
    else if (col < 1536) v = Wck[k * 512 + col - 1024];
    else if (col < 2048) v = Wcv[k * 512 + col - 1536];
    else if (col < 2560) v = Wcg[k * 512 + col - 2048];
    else if (col < 3072) v = Wiq[k * 512 + col - 2560];
    else if (col < 3584) v = Wik[k * 512 + col - 3072];
    else                 v = Wig[k * 512 + col - 3584];
    g_W[idx] = v;
}

// ---------------- rope helper ----------------
__device__ __forceinline__ void rope_cs(int i, float pos, float& c, float& s) {
    float f = powf(160000.0f, (float)i * (1.0f / 32.0f));
    float ang = pos / f;
    sincosf(ang, &s, &c);
}

// ---------------- gated compress (coarse KV) + rope on ck ---------------- grid Bb*Gg*HKV, block 128
__global__ void compress_c(const float* __restrict__ ape) {
    int blk = blockIdx.x;
    int h = blk & 3;
    int bg = blk >> 2;
    int g = bg & (Gg - 1);
    int d = threadIdx.x;
    size_t base = (size_t)bg * 4 * NCOL + h * 128 + d;
    float gv[4], m = -1e30f;
    #pragma unroll
    for (int r = 0; r < 4; r++) {
        gv[r] = g_Pall[base + (size_t)r * NCOL + OFF_CG] + ape[(r * HKV + h) * 128 + d];
        m = fmaxf(m, gv[r]);
    }
    float ssum = 0.f;
    #pragma unroll
    for (int r = 0; r < 4; r++) { gv[r] = expf(gv[r] - m); ssum += gv[r]; }
    float inv = 1.f / ssum;
    float ka = 0.f, va = 0.f;
    #pragma unroll
    for (int r = 0; r < 4; r++) {
        float w = gv[r] * inv;
        ka += w * g_Pall[base + (size_t)r * NCOL + OFF_CK];
        va += w * g_Pall[base + (size_t)r * NCOL + OFF_CV];
    }
    __shared__ float sk[128];
    sk[d] = ka;
    __syncthreads();
    float pos = (float)(4 * g + 3);
    float outk = ka;
    if (d >= 64 && d < 96) {
        int i = d - 64; float c, s; rope_cs(i, pos, c, s);
        outk = sk[d] * c - sk[d + 32] * s;
    } else if (d >= 96) {
        int i = d - 96; float c, s; rope_cs(i, pos, c, s);
        outk = sk[d - 32] * s + sk[d] * c;
    }
    size_t ob = ((size_t)bg * 4 + h) * 128 + d;
    g_ck[ob] = outk;
    g_cv[ob] = va;
}

// ---------------- gated compress (index KV) + rmsnorm ---------------- grid Bb*Gg*HIi, block 64
__global__ void compress_i(const float* __restrict__ ape) {
    int blk = blockIdx.x;
    int h = blk & 7;
    int bg = blk >> 3;
    int d = threadIdx.x;
    size_t base = (size_t)bg * 4 * NCOL + h * 64 + d;
    float gv[4], m = -1e30f;
    #pragma unroll
    for (int r = 0; r < 4; r++) {
        gv[r] = g_Pall[base + (size_t)r * NCOL + OFF_IG] + ape[(r * HIi + h) * 64 + d];
        m = fmaxf(m, gv[r]);
    }
    float ssum = 0.f;
    #pragma unroll
    for (int r = 0; r < 4; r++) { gv[r] = expf(gv[r] - m); ssum += gv[r]; }
    float inv = 1.f / ssum;
    float ka = 0.f;
    #pragma unroll
    for (int r = 0; r < 4; r++)
        ka += gv[r] * inv * g_Pall[base + (size_t)r * NCOL + OFF_IK];
    __shared__ float red[64];
    red[d] = ka * ka;
    __syncthreads();
    #pragma unroll
    for (int s2 = 32; s2 > 0; s2 >>= 1) {
        if (d < s2) red[d] += red[d + s2];
        __syncthreads();
    }
    float sc = rsqrtf(red[0] / 64.f + 1e-6f);
    g_ik[((size_t)bg * 8 + h) * 64 + d] = ka * sc;
}

// ---------------- per-head rmsnorm of iq ---------------- grid NTOK*HIi, block 64
__global__ void iq_rms() {
    int blk = blockIdx.x;
    int h = blk & 7;
    int row = blk >> 3;
    int d = threadIdx.x;
    float v = g_Pall[(size_t)row * NCOL + OFF_IQ + h * 64 + d];
    __shared__ float red[64];
    red[d] = v * v;
    __syncthreads();
    #pragma unroll
    for (int s2 = 32; s2 > 0; s2 >>= 1) {
        if (d < s2) red[d] += red[d + s2];
        __syncthreads();
    }
    float sc = rsqrtf(red[0] / 64.f + 1e-6f);
    g_iq[(size_t)row * 512 + h * 64 + d] = v * sc;
}

// ---------------- in-place partial rope of q ---------------- grid NTOK*Hh, block 32
__global__ void q_rope() {
    int blk = blockIdx.x;
    int h = blk & 7;
    int row = blk >> 3;
    int t = row & (Tt - 1);
    int i = threadIdx.x;
    size_t base = (size_t)row * NCOL + OFF_Q + h * 128;
    float x1 = g_Pall[base + 64 + i];
    float x2 = g_Pall[base + 96 + i];
    float c, s; rope_cs(i, (float)t, c, s);
    g_Pall[base + 64 + i] = x1 * c - x2 * s;
    g_Pall[base + 96 + i] = x1 * s + x2 * c;
}

// ---------------- top-k(64) threshold via bitonic sort ---------------- grid NTOK, block 512
__global__ void topk_thresh() {
    __shared__ float s[512];
    int row = blockIdx.x;
    int t = row & (Tt - 1);
    int tid = threadIdx.x;
    float v = g_isc[(size_t)row * Gg + tid];
    if (4 * tid + 3 > t) v = NEGv;
    s[tid] = v;
    __syncthreads();
    for (int k = 2; k <= 512; k <<= 1) {
        for (int j = k >> 1; j > 0; j >>= 1) {
            int ixj = tid ^ j;
            if (ixj > tid) {
                float a = s[tid], b = s[ixj];
                bool down = ((tid & k) == 0);
                bool sw = down ? (a < b) : (a > b);
                if (sw) { s[tid] = b; s[ixj] = a; }
            }
            __syncthreads();
        }
    }
    if (tid == 0) g_thr[row] = s[63];
}

// ---------------- sparse attention over selected groups ---------------- grid NTOK*Hh, block 128
__global__ void attn_kernel() {
    int blk = blockIdx.x;
    int h = blk & 7;
    int row = blk >> 3;
    int t = row & (Tt - 1);
    int b = row >> 11;
    int tid = threadIdx.x;
    __shared__ int sg[96];
    __shared__ float sw[96];
    __shared__ int cnt;
    __shared__ alignas(16) float qsh[128];
    if (tid == 0) cnt = 0;
    __syncthreads();

    int nc = (t >= 3) ? (((t - 3) >> 2) + 1) : 0;
    float th = g_thr[row];
    const float* iscr = g_isc + (size_t)row * Gg;
    for (int g = tid; g < nc; g += 128) {
        if (iscr[g] >= th) {
            int p = atomicAdd(&cnt, 1);
            if (p < 96) sg[p] = g;
        }
    }
    qsh[tid] = g_Pall[(size_t)row * NCOL + OFF_Q + h * 128 + tid];
    __syncthreads();
    int n = min(cnt, 96);
    int hkv = h >> 1;
    int warp = tid >> 5, lane = tid & 31;
    for (int i = warp; i < n; i += 4) {
        const float* kp = g_ck + ((size_t)(b * Gg + sg[i]) * 4 + hkv) * 128;
        float4 kv = *(const float4*)(kp + lane * 4);
        float4 qv = *(const float4*)(qsh + lane * 4);
        float p = qv.x * kv.x + qv.y * kv.y + qv.z * kv.z + qv.w * kv.w;
        #pragma unroll
        for (int o = 16; o > 0; o >>= 1) p += __shfl_xor_sync(0xffffffffu, p, o);
        if (lane == 0) sw[i] = p * 0.0883883476483184f;
    }
    __syncthreads();
    if (tid == 0 && n > 0) {
        float m = -1e30f;
        for (int i = 0; i < n; i++) m = fmaxf(m, sw[i]);
        float ssum = 0.f;
        for (int i = 0; i < n; i++) { float e = expf(sw[i] - m); sw[i] = e; ssum += e; }
        float inv = 1.f / ssum;
        for (int i = 0; i < n; i++) sw[i] *= inv;
    }
    __syncthreads();
    float acc = 0.f;
    for (int i = 0; i < n; i++)
        acc += sw[i] * g_cv[((size_t)(b * Gg + sg[i]) * 4 + hkv) * 128 + tid];
    g_at[(size_t)row * 1024 + h * 128 + tid] = acc;
}

// ---------------- rmsnorm over RANK=512 ---------------- grid NTOK, block 256
__global__ void rmsnorm512() {
    int row = blockIdx.x;
    int tid = threadIdx.x;
    size_t base = (size_t)row * 512;
    float a = g_r[base + tid], b = g_r[base + 256 + tid];
    __shared__ float red[256];
    red[tid] = a * a + b * b;
    __syncthreads();
    #pragma unroll
    for (int s2 = 128; s2 > 0; s2 >>= 1) {
        if (tid < s2) red[tid] += red[tid + s2];
        __syncthreads();
    }
    float sc = rsqrtf(red[0] / 512.f + 1e-6f);
    g_rn[base + tid] = a * sc;
    g_rn[base + 256 + tid] = b * sc;
}

// ---------------- launch ----------------
extern "C" void kernel_launch(void* const* d_in, const int* in_sizes, int n_in,
                              void* d_out, int out_size) {
    const float* x     = (const float*)d_in[0];
    const float* Wq    = (const float*)d_in[1];
    const float* Wck   = (const float*)d_in[2];
    const float* Wcv   = (const float*)d_in[3];
    const float* Wcg   = (const float*)d_in[4];
    const float* ape_c = (const float*)d_in[5];
    const float* Wiq   = (const float*)d_in[6];
    const float* Wik   = (const float*)d_in[7];
    const float* Wig   = (const float*)d_in[8];
    const float* ape_i = (const float*)d_in[9];
    const float* Wa    = (const float*)d_in[10];
    const float* Wb    = (const float*)d_in[11];
    float* out = (float*)d_out;

    float *W, *Pall, *ik, *iq, *isc, *at, *r, *rn;
    cudaGetSymbolAddress((void**)&W,    g_W);
    cudaGetSymbolAddress((void**)&Pall, g_Pall);
    cudaGetSymbolAddress((void**)&ik,   g_ik);
    cudaGetSymbolAddress((void**)&iq,   g_iq);
    cudaGetSymbolAddress((void**)&isc,  g_isc);
    cudaGetSymbolAddress((void**)&at,   g_at);
    cudaGetSymbolAddress((void**)&r,    g_r);
    cudaGetSymbolAddress((void**)&rn,   g_rn);

    const int SMEM_NN = (2 * 128 * 36 + 2 * 32 * 136) * 4;   // 71680
    const int SMEM_NT = (2 * 128 * 36 + 2 * 128 * 36) * 4;   // 73728
    static int attr_set = 0;
    if (!attr_set) {
        cudaFuncSetAttribute(mma_gemm<0>, cudaFuncAttributeMaxDynamicSharedMemorySize, SMEM_NN);
        cudaFuncSetAttribute(mma_gemm<1>, cudaFuncAttributeMaxDynamicSharedMemorySize, SMEM_NT);
        attr_set = 1;
    }

    // Concatenate weights, then one fused projection GEMM: Pall = x @ W  (8192x4096x1024)
    concat_w<<<(1024 * 4096) / 256, 256>>>(Wq, Wck, Wcv, Wcg, Wiq, Wik, Wig);
    mma_gemm<0><<<dim3(NCOL / 128, NTOK / 128, 1), 256, SMEM_NN>>>(
        NTOK, NCOL, 1024, 1.f, x, W, Pall, 0, 0, 0);

    // Compress + norms + rope
    compress_c<<<Bb * Gg * HKV, 128>>>(ape_c);
    compress_i<<<Bb * Gg * HIi, 64>>>(ape_i);
    iq_rms<<<NTOK * HIi, 64>>>();
    q_rope<<<NTOK * Hh, 32>>>();

    // Index scores: batched NT GEMM, alpha = DI^-0.5 / HI = 1/64
    mma_gemm<1><<<dim3(512 / 128, 2048 / 128, Bb), 256, SMEM_NT>>>(
        2048, 512, 512, 1.f / 64.f, iq, ik, isc,
        (long)2048 * 512, (long)512 * 512, (long)2048 * 512);

    topk_thresh<<<NTOK, 512>>>();
    attn_kernel<<<NTOK * Hh, 128>>>();

    // r = attn @ Wa^T
    mma_gemm<1><<<dim3(512 / 128, NTOK / 128, 1), 256, SMEM_NT>>>(
        NTOK, 512, 1024, 1.f, at, Wa, r, 0, 0, 0);
    rmsnorm512<<<NTOK, 256>>>();
    // out = rn @ Wb
    mma_gemm<0><<<dim3(1024 / 128, NTOK / 128, 1), 256, SMEM_NN>>>(
        NTOK, 1024, 512, 1.f, rn, Wb, out, 0, 0, 0);
}

// round 6
// speedup vs baseline: 2.0253x; 1.3349x over previous
#include <cuda_runtime.h>
#include <cuda_fp16.h>
#include <math.h>
#include <stdint.h>

// Problem constants
#define Bb 4
#define Tt 2048
#define Cc 1024
#define Hh 8
#define HKV 4
#define Dd 128
#define Gg 512
#define HIi 8
#define DIi 64
#define NEGv (-1e30f)

#define NTOK (Bb*Tt)   // 8192
#define NCOL 4096      // fused projection width: q|ck|cv|cg|iq|ik|ig
#define OFF_Q  0
#define OFF_CK 1024
#define OFF_CV 1536
#define OFF_CG 2048
#define OFF_IQ 2560
#define OFF_IK 3072
#define OFF_IG 3584

// plane strides (elements)
#define PL_X   ((long)NTOK*1024)
#define PL_WT  ((long)NCOL*1024)
#define PL_IQ  ((long)NTOK*512)
#define PL_IK  ((long)Bb*512*512)
#define PL_AT  ((long)NTOK*1024)
#define PL_WA  ((long)512*1024)
#define PL_RN  ((long)NTOK*512)
#define PL_WB  ((long)1024*512)

// ---------------- scratch (static device allocations) ----------------
__device__ alignas(256) __half g_xs [2*PL_X];
__device__ alignas(256) __half g_WTs[2*PL_WT];
__device__ alignas(256) float g_Pall[(size_t)NTOK*NCOL];
__device__ alignas(256) float g_ck [Bb*Gg*HKV*Dd];
__device__ alignas(256) float g_cv [Bb*Gg*HKV*Dd];
__device__ alignas(256) __half g_iks[2*PL_IK];
__device__ alignas(256) __half g_iqs[2*PL_IQ];
__device__ alignas(256) float g_isc[NTOK*Gg];
__device__ alignas(256) float g_thr[NTOK];
__device__ alignas(256) __half g_ats[2*PL_AT];
__device__ alignas(256) __half g_Was[2*PL_WA];
__device__ alignas(256) float g_r  [NTOK*512];
__device__ alignas(256) __half g_rns[2*PL_RN];
__device__ alignas(256) __half g_Wbs[2*PL_WB];

// ---------------- helpers ----------------
__device__ __forceinline__ void cpa16(uint32_t dst, const void* src) {
    asm volatile("cp.async.cg.shared.global [%0], [%1], 16;\n" :: "r"(dst), "l"(src));
}
__device__ __forceinline__ void cp_commit() {
    asm volatile("cp.async.commit_group;\n");
}
// fp16 2-way split: v = h0 + h1 + O(2^-24 v)
__device__ __forceinline__ void split2(float v, __half* p, size_t idx, long plane) {
    __half h0 = __float2half_rn(v);
    float r1 = v - __half2float(h0);
    p[idx]         = h0;
    p[idx + plane] = __float2half_rn(r1);
}
__device__ __forceinline__ void mma_f16(float* c,
    uint32_t a0, uint32_t a1, uint32_t a2, uint32_t a3,
    uint32_t b0, uint32_t b1) {
    asm volatile(
        "mma.sync.aligned.m16n8k16.row.col.f32.f16.f16.f32 "
        "{%0,%1,%2,%3},{%4,%5,%6,%7},{%8,%9},{%0,%1,%2,%3};"
        : "+f"(c[0]), "+f"(c[1]), "+f"(c[2]), "+f"(c[3])
        : "r"(a0), "r"(a1), "r"(a2), "r"(a3), "r"(b0), "r"(b1));
}

// ---------------- fp16x3 MMA GEMM (fp32-accurate): C = alpha * A[M,K] @ B[N,K]^T ----------------
// A, B given as 2 fp16 split planes, row-major [rows][K]. BM=BN=128, BK=32.
// 256 threads (8 warps 2x4), warp tile 64x32. Requires M,N % 128 == 0, K % 32 == 0.
// smem layout (u32 units): per row 16 pairs + 4 pad = stride 20.
#define HPLANE 2560          // 128 rows * 20 u32
#define HBUF   5120          // 2 planes
#define HTOT   10240         // A + B per buffer
#define HSMEM  (2 * HTOT * 4)  // 81920 bytes

__global__ void mma_gemm_hx(int M, int N, int K, float alpha,
                            const __half* __restrict__ A0, long planeA, long batA,
                            const __half* __restrict__ B0, long planeB, long batB,
                            float* __restrict__ C, long batC) {
    extern __shared__ char smraw[];
    uint32_t* sm32 = (uint32_t*)smraw;
    uint32_t sbase = (uint32_t)__cvta_generic_to_shared(smraw);

    const int tid  = threadIdx.x;
    const int wid  = tid >> 5;
    const int lane = tid & 31;
    const int lm   = lane >> 2;     // 0..7
    const int lk   = lane & 3;      // 0..3
    const int warp_m = (wid & 1) * 64;
    const int warp_n = (wid >> 1) * 32;
    const int bm = blockIdx.y * 128;
    const int bn = blockIdx.x * 128;
    const int z  = blockIdx.z;

    const __half* Abase = A0 + (size_t)z * batA;
    const __half* Bbase = B0 + (size_t)z * batB;
    float* Cptr = C + (size_t)z * batC + (size_t)(bm + warp_m) * N + bn + warp_n;

    float c[4][4][4];
    #pragma unroll
    for (int mt = 0; mt < 4; mt++)
        #pragma unroll
        for (int nt = 0; nt < 4; nt++)
            #pragma unroll
            for (int i = 0; i < 4; i++) c[mt][nt][i] = 0.f;

    const int nIter = K >> 5;

    auto stage = [&](int it, int buf) {
        const int k0 = it * 32;
        const uint32_t abase = sbase + (uint32_t)(buf * HTOT) * 4u;
        const uint32_t bbase = abase + HBUF * 4u;
        #pragma unroll
        for (int i = 0; i < 4; i++) {
            int id = tid + i * 256;
            int p = id >> 9, rem = id & 511, row = rem >> 2, cc = rem & 3;
            cpa16(abase + (uint32_t)(p * HPLANE + row * 20) * 4u + cc * 16,
                  Abase + (size_t)p * planeA + (size_t)(bm + row) * K + k0 + cc * 8);
        }
        #pragma unroll
        for (int i = 0; i < 4; i++) {
            int id = tid + i * 256;
            int p = id >> 9, rem = id & 511, row = rem >> 2, cc = rem & 3;
            cpa16(bbase + (uint32_t)(p * HPLANE + row * 20) * 4u + cc * 16,
                  Bbase + (size_t)p * planeB + (size_t)(bn + row) * K + k0 + cc * 8);
        }
        cp_commit();
    };

    stage(0, 0);

    for (int it = 0; it < nIter; it++) {
        const int buf = it & 1;
        if (it + 1 < nIter) {
            stage(it + 1, buf ^ 1);
            asm volatile("cp.async.wait_group 1;\n" ::: "memory");
        } else {
            asm volatile("cp.async.wait_group 0;\n" ::: "memory");
        }
        __syncthreads();

        const uint32_t* Asm = sm32 + buf * HTOT;
        const uint32_t* Bsm = Asm + HBUF;

        #pragma unroll
        for (int kc = 0; kc < 2; kc++) {       // two k16 slices of the 32-K chunk
            uint32_t a0f[4][4], a1f[4][4];
            #pragma unroll
            for (int mt = 0; mt < 4; mt++) {
                int r = warp_m + mt * 16 + lm;
                int o = kc * 8 + lk;
                a0f[mt][0] = Asm[r * 20 + o];
                a0f[mt][1] = Asm[(r + 8) * 20 + o];
                a0f[mt][2] = Asm[r * 20 + o + 4];
                a0f[mt][3] = Asm[(r + 8) * 20 + o + 4];
                a1f[mt][0] = Asm[HPLANE + r * 20 + o];
                a1f[mt][1] = Asm[HPLANE + (r + 8) * 20 + o];
                a1f[mt][2] = Asm[HPLANE + r * 20 + o + 4];
                a1f[mt][3] = Asm[HPLANE + (r + 8) * 20 + o + 4];
            }
            #pragma unroll
            for (int nt = 0; nt < 4; nt++) {
                int n = warp_n + nt * 8 + lm;
                int o = kc * 8 + lk;
                uint32_t b00 = Bsm[n * 20 + o];
                uint32_t b01 = Bsm[n * 20 + o + 4];
                uint32_t b10 = Bsm[HPLANE + n * 20 + o];
                uint32_t b11 = Bsm[HPLANE + n * 20 + o + 4];
                #pragma unroll
                for (int mt = 0; mt < 4; mt++) {
                    mma_f16(c[mt][nt], a0f[mt][0], a0f[mt][1], a0f[mt][2], a0f[mt][3], b00, b01);
                    mma_f16(c[mt][nt], a0f[mt][0], a0f[mt][1], a0f[mt][2], a0f[mt][3], b10, b11);
                    mma_f16(c[mt][nt], a1f[mt][0], a1f[mt][1], a1f[mt][2], a1f[mt][3], b00, b01);
                }
            }
        }
        __syncthreads();
    }

    #pragma unroll
    for (int mt = 0; mt < 4; mt++) {
        #pragma unroll
        for (int nt = 0; nt < 4; nt++) {
            int r0 = mt * 16 + lm;
            int cc = nt * 8 + 2 * lk;
            float2 v;
            v.x = c[mt][nt][0] * alpha; v.y = c[mt][nt][1] * alpha;
            *(float2*)(Cptr + (size_t)r0 * N + cc) = v;
            v.x = c[mt][nt][2] * alpha; v.y = c[mt][nt][3] * alpha;
            *(float2*)(Cptr + (size_t)(r0 + 8) * N + cc) = v;
        }
    }
}

// ---------------- split kernels ----------------
__global__ void split_plain(const float* __restrict__ src, __half* dst,
                            long plane, int n) {
    int idx = blockIdx.x * 256 + threadIdx.x;
    if (idx < n) split2(src[idx], dst, idx, plane);
}

// fused 7-weight concat + transpose + split: out planes [4096][1024]
__global__ void splitT_w7(const float* __restrict__ Wq,  const float* __restrict__ Wck,
                          const float* __restrict__ Wcv, const float* __restrict__ Wcg,
                          const float* __restrict__ Wiq, const float* __restrict__ Wik,
                          const float* __restrict__ Wig, __half* out) {
    __shared__ float tile[32][33];
    int k0 = blockIdx.x * 32, n0 = blockIdx.y * 32;
    int tx = threadIdx.x, ty = threadIdx.y;
    {
        int k = k0 + ty, n = n0 + tx;
        float v;
        if      (n < 1024) v = Wq [k * 1024 + n];
        else if (n < 1536) v = Wck[k * 512 + n - 1024];
        else if (n < 2048) v = Wcv[k * 512 + n - 1536];
        else if (n < 2560) v = Wcg[k * 512 + n - 2048];
        else if (n < 3072) v = Wiq[k * 512 + n - 2560];
        else if (n < 3584) v = Wik[k * 512 + n - 3072];
        else               v = Wig[k * 512 + n - 3584];
        tile[ty][tx] = v;
    }
    __syncthreads();
    int n = n0 + ty, k = k0 + tx;
    split2(tile[tx][ty], out, (size_t)n * 1024 + k, PL_WT);
}

// generic transpose+split: src [Kd][Nd] -> out planes [Nd][Kd]
__global__ void splitT_gen(const float* __restrict__ src, __half* out,
                           int Kd, int Nd, long plane) {
    __shared__ float tile[32][33];
    int k0 = blockIdx.x * 32, n0 = blockIdx.y * 32;
    int tx = threadIdx.x, ty = threadIdx.y;
    tile[ty][tx] = src[(size_t)(k0 + ty) * Nd + n0 + tx];
    __syncthreads();
    int n = n0 + ty, k = k0 + tx;
    split2(tile[tx][ty], out, (size_t)n * Kd + k, plane);
}

// ---------------- rope helper ----------------
__device__ __forceinline__ void rope_cs(int i, float pos, float& c, float& s) {
    float f = powf(160000.0f, (float)i * (1.0f / 32.0f));
    float ang = pos / f;
    sincosf(ang, &s, &c);
}

// ---------------- gated compress (coarse KV) + rope on ck ---------------- grid Bb*Gg*HKV, block 128
__global__ void compress_c(const float* __restrict__ ape) {
    int blk = blockIdx.x;
    int h = blk & 3;
    int bg = blk >> 2;
    int g = bg & (Gg - 1);
    int d = threadIdx.x;
    size_t base = (size_t)bg * 4 * NCOL + h * 128 + d;
    float gv[4], m = -1e30f;
    #pragma unroll
    for (int r = 0; r < 4; r++) {
        gv[r] = g_Pall[base + (size_t)r * NCOL + OFF_CG] + ape[(r * HKV + h) * 128 + d];
        m = fmaxf(m, gv[r]);
    }
    float ssum = 0.f;
    #pragma unroll
    for (int r = 0; r < 4; r++) { gv[r] = expf(gv[r] - m); ssum += gv[r]; }
    float inv = 1.f / ssum;
    float ka = 0.f, va = 0.f;
    #pragma unroll
    for (int r = 0; r < 4; r++) {
        float w = gv[r] * inv;
        ka += w * g_Pall[base + (size_t)r * NCOL + OFF_CK];
        va += w * g_Pall[base + (size_t)r * NCOL + OFF_CV];
    }
    __shared__ float sk[128];
    sk[d] = ka;
    __syncthreads();
    float pos = (float)(4 * g + 3);
    float outk = ka;
    if (d >= 64 && d < 96) {
        int i = d - 64; float c, s; rope_cs(i, pos, c, s);
        outk = sk[d] * c - sk[d + 32] * s;
    } else if (d >= 96) {
        int i = d - 96; float c, s; rope_cs(i, pos, c, s);
        outk = sk[d - 32] * s + sk[d] * c;
    }
    size_t ob = ((size_t)bg * 4 + h) * 128 + d;
    g_ck[ob] = outk;
    g_cv[ob] = va;
}

// ---------------- gated compress (index KV) + rmsnorm -> ik splits ---------------- grid Bb*Gg*HIi, block 64
__global__ void compress_i(const float* __restrict__ ape) {
    int blk = blockIdx.x;
    int h = blk & 7;
    int bg = blk >> 3;
    int d = threadIdx.x;
    size_t base = (size_t)bg * 4 * NCOL + h * 64 + d;
    float gv[4], m = -1e30f;
    #pragma unroll
    for (int r = 0; r < 4; r++) {
        gv[r] = g_Pall[base + (size_t)r * NCOL + OFF_IG] + ape[(r * HIi + h) * 64 + d];
        m = fmaxf(m, gv[r]);
    }
    float ssum = 0.f;
    #pragma unroll
    for (int r = 0; r < 4; r++) { gv[r] = expf(gv[r] - m); ssum += gv[r]; }
    float inv = 1.f / ssum;
    float ka = 0.f;
    #pragma unroll
    for (int r = 0; r < 4; r++)
        ka += gv[r] * inv * g_Pall[base + (size_t)r * NCOL + OFF_IK];
    __shared__ float red[64];
    red[d] = ka * ka;
    __syncthreads();
    #pragma unroll
    for (int s2 = 32; s2 > 0; s2 >>= 1) {
        if (d < s2) red[d] += red[d + s2];
        __syncthreads();
    }
    float sc = rsqrtf(red[0] / 64.f + 1e-6f);
    split2(ka * sc, g_iks, ((size_t)bg * 8 + h) * 64 + d, PL_IK);
}

// ---------------- per-head rmsnorm of iq -> iq splits ---------------- grid NTOK*HIi, block 64
__global__ void iq_rms() {
    int blk = blockIdx.x;
    int h = blk & 7;
    int row = blk >> 3;
    int d = threadIdx.x;
    float v = g_Pall[(size_t)row * NCOL + OFF_IQ + h * 64 + d];
    __shared__ float red[64];
    red[d] = v * v;
    __syncthreads();
    #pragma unroll
    for (int s2 = 32; s2 > 0; s2 >>= 1) {
        if (d < s2) red[d] += red[d + s2];
        __syncthreads();
    }
    float sc = rsqrtf(red[0] / 64.f + 1e-6f);
    split2(v * sc, g_iqs, (size_t)row * 512 + h * 64 + d, PL_IQ);
}

// ---------------- in-place partial rope of q ---------------- grid NTOK*Hh, block 32
__global__ void q_rope() {
    int blk = blockIdx.x;
    int h = blk & 7;
    int row = blk >> 3;
    int t = row & (Tt - 1);
    int i = threadIdx.x;
    size_t base = (size_t)row * NCOL + OFF_Q + h * 128;
    float x1 = g_Pall[base + 64 + i];
    float x2 = g_Pall[base + 96 + i];
    float c, s; rope_cs(i, (float)t, c, s);
    g_Pall[base + 64 + i] = x1 * c - x2 * s;
    g_Pall[base + 96 + i] = x1 * s + x2 * c;
}

// ---------------- top-k(64) threshold via bitonic sort ---------------- grid NTOK, block 512
__global__ void topk_thresh() {
    __shared__ float s[512];
    int row = blockIdx.x;
    int t = row & (Tt - 1);
    int tid = threadIdx.x;
    float v = g_isc[(size_t)row * Gg + tid];
    if (4 * tid + 3 > t) v = NEGv;
    s[tid] = v;
    __syncthreads();
    for (int k = 2; k <= 512; k <<= 1) {
        for (int j = k >> 1; j > 0; j >>= 1) {
            int ixj = tid ^ j;
            if (ixj > tid) {
                float a = s[tid], b = s[ixj];
                bool down = ((tid & k) == 0);
                bool sw = down ? (a < b) : (a > b);
                if (sw) { s[tid] = b; s[ixj] = a; }
            }
            __syncthreads();
        }
    }
    if (tid == 0) g_thr[row] = s[63];
}

// ---------------- sparse attention -> at splits ---------------- grid NTOK*Hh, block 128
__global__ void attn_kernel() {
    int blk = blockIdx.x;
    int h = blk & 7;
    int row = blk >> 3;
    int t = row & (Tt - 1);
    int b = row >> 11;
    int tid = threadIdx.x;
    __shared__ int sg[96];
    __shared__ float sw[96];
    __shared__ int cnt;
    __shared__ alignas(16) float qsh[128];
    if (tid == 0) cnt = 0;
    __syncthreads();

    int nc = (t >= 3) ? (((t - 3) >> 2) + 1) : 0;
    float th = g_thr[row];
    const float* iscr = g_isc + (size_t)row * Gg;
    for (int g = tid; g < nc; g += 128) {
        if (iscr[g] >= th) {
            int p = atomicAdd(&cnt, 1);
            if (p < 96) sg[p] = g;
        }
    }
    qsh[tid] = g_Pall[(size_t)row * NCOL + OFF_Q + h * 128 + tid];
    __syncthreads();
    int n = min(cnt, 96);
    int hkv = h >> 1;
    int warp = tid >> 5, lane = tid & 31;
    for (int i = warp; i < n; i += 4) {
        const float* kp = g_ck + ((size_t)(b * Gg + sg[i]) * 4 + hkv) * 128;
        float4 kv = *(const float4*)(kp + lane * 4);
        float4 qv = *(const float4*)(qsh + lane * 4);
        float p = qv.x * kv.x + qv.y * kv.y + qv.z * kv.z + qv.w * kv.w;
        #pragma unroll
        for (int o = 16; o > 0; o >>= 1) p += __shfl_xor_sync(0xffffffffu, p, o);
        if (lane == 0) sw[i] = p * 0.0883883476483184f;
    }
    __syncthreads();
    if (tid == 0 && n > 0) {
        float m = -1e30f;
        for (int i = 0; i < n; i++) m = fmaxf(m, sw[i]);
        float ssum = 0.f;
        for (int i = 0; i < n; i++) { float e = expf(sw[i] - m); sw[i] = e; ssum += e; }
        float inv = 1.f / ssum;
        for (int i = 0; i < n; i++) sw[i] *= inv;
    }
    __syncthreads();
    float acc = 0.f;
    for (int i = 0; i < n; i++)
        acc += sw[i] * g_cv[((size_t)(b * Gg + sg[i]) * 4 + hkv) * 128 + tid];
    split2(acc, g_ats, (size_t)row * 1024 + h * 128 + tid, PL_AT);
}

// ---------------- rmsnorm over RANK=512 -> rn splits ---------------- grid NTOK, block 256
__global__ void rmsnorm512() {
    int row = blockIdx.x;
    int tid = threadIdx.x;
    size_t base = (size_t)row * 512;
    float a = g_r[base + tid], b = g_r[base + 256 + tid];
    __shared__ float red[256];
    red[tid] = a * a + b * b;
    __syncthreads();
    #pragma unroll
    for (int s2 = 128; s2 > 0; s2 >>= 1) {
        if (tid < s2) red[tid] += red[tid + s2];
        __syncthreads();
    }
    float sc = rsqrtf(red[0] / 512.f + 1e-6f);
    split2(a * sc, g_rns, base + tid, PL_RN);
    split2(b * sc, g_rns, base + 256 + tid, PL_RN);
}

// ---------------- launch ----------------
extern "C" void kernel_launch(void* const* d_in, const int* in_sizes, int n_in,
                              void* d_out, int out_size) {
    const float* x     = (const float*)d_in[0];
    const float* Wq    = (const float*)d_in[1];
    const float* Wck   = (const float*)d_in[2];
    const float* Wcv   = (const float*)d_in[3];
    const float* Wcg   = (const float*)d_in[4];
    const float* ape_c = (const float*)d_in[5];
    const float* Wiq   = (const float*)d_in[6];
    const float* Wik   = (const float*)d_in[7];
    const float* Wig   = (const float*)d_in[8];
    const float* ape_i = (const float*)d_in[9];
    const float* Wa    = (const float*)d_in[10];
    const float* Wb    = (const float*)d_in[11];
    float* out = (float*)d_out;

    __half *xs, *WTs, *iks, *iqs, *ats, *Was, *rns, *Wbs;
    float *Pall, *isc, *r;
    cudaGetSymbolAddress((void**)&xs,   g_xs);
    cudaGetSymbolAddress((void**)&WTs,  g_WTs);
    cudaGetSymbolAddress((void**)&Pall, g_Pall);
    cudaGetSymbolAddress((void**)&iks,  g_iks);
    cudaGetSymbolAddress((void**)&iqs,  g_iqs);
    cudaGetSymbolAddress((void**)&isc,  g_isc);
    cudaGetSymbolAddress((void**)&ats,  g_ats);
    cudaGetSymbolAddress((void**)&Was,  g_Was);
    cudaGetSymbolAddress((void**)&r,    g_r);
    cudaGetSymbolAddress((void**)&rns,  g_rns);
    cudaGetSymbolAddress((void**)&Wbs,  g_Wbs);

    static int attr_set = 0;
    if (!attr_set) {
        cudaFuncSetAttribute(mma_gemm_hx, cudaFuncAttributeMaxDynamicSharedMemorySize, HSMEM);
        attr_set = 1;
    }

    // operand splits
    split_plain<<<(NTOK * 1024) / 256, 256>>>(x, xs, PL_X, NTOK * 1024);
    splitT_w7<<<dim3(1024 / 32, NCOL / 32), dim3(32, 32)>>>(Wq, Wck, Wcv, Wcg, Wiq, Wik, Wig, WTs);
    split_plain<<<(512 * 1024) / 256, 256>>>(Wa, Was, PL_WA, 512 * 1024);
    splitT_gen<<<dim3(512 / 32, 1024 / 32), dim3(32, 32)>>>(Wb, Wbs, 512, 1024, PL_WB);

    // fused projection GEMM: Pall = x @ W  (8192 x 4096 x 1024)
    mma_gemm_hx<<<dim3(NCOL / 128, NTOK / 128, 1), 256, HSMEM>>>(
        NTOK, NCOL, 1024, 1.f, xs, PL_X, 0, WTs, PL_WT, 0, Pall, 0);

    // compress + norms + rope
    compress_c<<<Bb * Gg * HKV, 128>>>(ape_c);
    compress_i<<<Bb * Gg * HIi, 64>>>(ape_i);
    iq_rms<<<NTOK * HIi, 64>>>();
    q_rope<<<NTOK * Hh, 32>>>();

    // index scores: batched, alpha = DI^-0.5 / HI = 1/64
    mma_gemm_hx<<<dim3(512 / 128, 2048 / 128, Bb), 256, HSMEM>>>(
        2048, 512, 512, 1.f / 64.f,
        iqs, PL_IQ, (long)2048 * 512,
        iks, PL_IK, (long)512 * 512,
        isc, (long)2048 * 512);

    topk_thresh<<<NTOK, 512>>>();
    attn_kernel<<<NTOK * Hh, 128>>>();

    // r = attn @ Wa^T  (8192 x 512 x 1024)
    mma_gemm_hx<<<dim3(512 / 128, NTOK / 128, 1), 256, HSMEM>>>(
        NTOK, 512, 1024, 1.f, ats, PL_AT, 0, Was, PL_WA, 0, r, 0);

    rmsnorm512<<<NTOK, 256>>>();

    // out = rn @ Wb  (8192 x 1024 x 512)
    mma_gemm_hx<<<dim3(1024 / 128, NTOK / 128, 1), 256, HSMEM>>>(
        NTOK, 1024, 512, 1.f, rns, PL_RN, 0, Wbs, PL_WB, 0, out, 0);
}

// round 8
// speedup vs baseline: 2.1537x; 1.0634x over previous
#include <cuda_runtime.h>
#include <cuda_fp16.h>
#include <math.h>
#include <stdint.h>

// Problem constants
#define Bb 4
#define Tt 2048
#define Cc 1024
#define Hh 8
#define HKV 4
#define Dd 128
#define Gg 512
#define HIi 8
#define DIi 64
#define NEGv (-1e30f)

#define NTOK (Bb*Tt)   // 8192
#define NCOL 4096      // fused projection width: q|ck|cv|cg|iq|ik|ig
#define OFF_Q  0
#define OFF_CK 1024
#define OFF_CV 1536
#define OFF_CG 2048
#define OFF_IQ 2560
#define OFF_IK 3072
#define OFF_IG 3584

// plane strides (elements)
#define PL_X   ((long)NTOK*1024)
#define PL_WT  ((long)NCOL*1024)
#define PL_IQ  ((long)NTOK*512)
#define PL_IK  ((long)Bb*512*512)
#define PL_AT  ((long)NTOK*1024)
#define PL_WA  ((long)512*1024)
#define PL_RN  ((long)NTOK*512)
#define PL_WB  ((long)1024*512)

// ---------------- scratch (static device allocations) ----------------
__device__ alignas(256) __half g_xs [2*PL_X];
__device__ alignas(256) __half g_WTs[2*PL_WT];
__device__ alignas(256) float g_Pall[(size_t)NTOK*NCOL];
__device__ alignas(256) float g_ck [Bb*Gg*HKV*Dd];
__device__ alignas(256) float g_cv [Bb*Gg*HKV*Dd];
__device__ alignas(256) __half g_iks[2*PL_IK];
__device__ alignas(256) __half g_iqs[2*PL_IQ];
__device__ alignas(256) float g_isc[NTOK*Gg];
__device__ alignas(256) float g_thr[NTOK];
__device__ alignas(256) __half g_ats[2*PL_AT];
__device__ alignas(256) __half g_Was[2*PL_WA];
__device__ alignas(256) float g_r  [NTOK*512];
__device__ alignas(256) __half g_rns[2*PL_RN];
__device__ alignas(256) __half g_Wbs[2*PL_WB];

// ---------------- helpers ----------------
__device__ __forceinline__ void cpa16(uint32_t dst, const void* src) {
    asm volatile("cp.async.cg.shared.global [%0], [%1], 16;\n" :: "r"(dst), "l"(src));
}
__device__ __forceinline__ void cp_commit() {
    asm volatile("cp.async.commit_group;\n");
}
// fp16 2-way split: v = h0 + h1 + O(2^-24 v)
__device__ __forceinline__ void split2(float v, __half* p, size_t idx, long plane) {
    __half h0 = __float2half_rn(v);
    float r1 = v - __half2float(h0);
    p[idx]         = h0;
    p[idx + plane] = __float2half_rn(r1);
}
__device__ __forceinline__ void mma_f16(float* c,
    uint32_t a0, uint32_t a1, uint32_t a2, uint32_t a3,
    uint32_t b0, uint32_t b1) {
    asm volatile(
        "mma.sync.aligned.m16n8k16.row.col.f32.f16.f16.f32 "
        "{%0,%1,%2,%3},{%4,%5,%6,%7},{%8,%9},{%0,%1,%2,%3};"
        : "+f"(c[0]), "+f"(c[1]), "+f"(c[2]), "+f"(c[3])
        : "r"(a0), "r"(a1), "r"(a2), "r"(a3), "r"(b0), "r"(b1));
}

// ---------------- fp16x3 MMA GEMM (fp32-accurate): C = alpha * A[M,K] @ B[N,K]^T ----------------
// A, B given as 2 fp16 split planes, row-major [rows][K]. BM=BN=128, BK=32.
// 256 threads (8 warps 2x4), warp tile 64x32. Requires M,N % 128 == 0, K % 32 == 0.
// smem layout (u32 units): per row 16 pairs + 4 pad = stride 20.
#define HPLANE 2560          // 128 rows * 20 u32
#define HBUF   5120          // 2 planes
#define HTOT   10240         // A + B per buffer
#define HSMEM  (2 * HTOT * 4)  // 81920 bytes

__global__ void __launch_bounds__(256, 2) mma_gemm_hx(
    int M, int N, int K, float alpha,
    const __half* __restrict__ A0, long planeA, long batA,
    const __half* __restrict__ B0, long planeB, long batB,
    float* __restrict__ C, long batC) {
    extern __shared__ char smraw[];
    uint32_t* sm32 = (uint32_t*)smraw;
    uint32_t sbase = (uint32_t)__cvta_generic_to_shared(smraw);

    const int tid  = threadIdx.x;
    const int wid  = tid >> 5;
    const int lane = tid & 31;
    const int lm   = lane >> 2;     // 0..7
    const int lk   = lane & 3;      // 0..3
    const int warp_m = (wid & 1) * 64;
    const int warp_n = (wid >> 1) * 32;
    const int bm = blockIdx.y * 128;
    const int bn = blockIdx.x * 128;
    const int z  = blockIdx.z;

    const __half* Abase = A0 + (size_t)z * batA;
    const __half* Bbase = B0 + (size_t)z * batB;
    float* Cptr = C + (size_t)z * batC + (size_t)(bm + warp_m) * N + bn + warp_n;

    float c[4][4][4];
    #pragma unroll
    for (int mt = 0; mt < 4; mt++)
        #pragma unroll
        for (int nt = 0; nt < 4; nt++)
            #pragma unroll
            for (int i = 0; i < 4; i++) c[mt][nt][i] = 0.f;

    const int nIter = K >> 5;

    auto stage = [&](int it, int buf) {
        const int k0 = it * 32;
        const uint32_t abase = sbase + (uint32_t)(buf * HTOT) * 4u;
        const uint32_t bbase = abase + HBUF * 4u;
        #pragma unroll
        for (int i = 0; i < 4; i++) {
            int id = tid + i * 256;
            int p = id >> 9, rem = id & 511, row = rem >> 2, cc = rem & 3;
            cpa16(abase + (uint32_t)(p * HPLANE + row * 20) * 4u + cc * 16,
                  Abase + (size_t)p * planeA + (size_t)(bm + row) * K + k0 + cc * 8);
        }
        #pragma unroll
        for (int i = 0; i < 4; i++) {
            int id = tid + i * 256;
            int p = id >> 9, rem = id & 511, row = rem >> 2, cc = rem & 3;
            cpa16(bbase + (uint32_t)(p * HPLANE + row * 20) * 4u + cc * 16,
                  Bbase + (size_t)p * planeB + (size_t)(bn + row) * K + k0 + cc * 8);
        }
        cp_commit();
    };

    stage(0, 0);

    for (int it = 0; it < nIter; it++) {
        const int buf = it & 1;
        if (it + 1 < nIter) {
            stage(it + 1, buf ^ 1);
            asm volatile("cp.async.wait_group 1;\n" ::: "memory");
        } else {
            asm volatile("cp.async.wait_group 0;\n" ::: "memory");
        }
        __syncthreads();

        const uint32_t* Asm = sm32 + buf * HTOT;
        const uint32_t* Bsm = Asm + HBUF;

        #pragma unroll
        for (int kc = 0; kc < 2; kc++) {       // two k16 slices of the 32-K chunk
            uint32_t a0f[4][4], a1f[4][4];
            #pragma unroll
            for (int mt = 0; mt < 4; mt++) {
                int r = warp_m + mt * 16 + lm;
                int o = kc * 8 + lk;
                a0f[mt][0] = Asm[r * 20 + o];
                a0f[mt][1] = Asm[(r + 8) * 20 + o];
                a0f[mt][2] = Asm[r * 20 + o + 4];
                a0f[mt][3] = Asm[(r + 8) * 20 + o + 4];
                a1f[mt][0] = Asm[HPLANE + r * 20 + o];
                a1f[mt][1] = Asm[HPLANE + (r + 8) * 20 + o];
                a1f[mt][2] = Asm[HPLANE + r * 20 + o + 4];
                a1f[mt][3] = Asm[HPLANE + (r + 8) * 20 + o + 4];
            }
            #pragma unroll
            for (int nt = 0; nt < 4; nt++) {
                int n = warp_n + nt * 8 + lm;
                int o = kc * 8 + lk;
                uint32_t b00 = Bsm[n * 20 + o];
                uint32_t b01 = Bsm[n * 20 + o + 4];
                uint32_t b10 = Bsm[HPLANE + n * 20 + o];
                uint32_t b11 = Bsm[HPLANE + n * 20 + o + 4];
                #pragma unroll
                for (int mt = 0; mt < 4; mt++) {
                    mma_f16(c[mt][nt], a0f[mt][0], a0f[mt][1], a0f[mt][2], a0f[mt][3], b00, b01);
                    mma_f16(c[mt][nt], a0f[mt][0], a0f[mt][1], a0f[mt][2], a0f[mt][3], b10, b11);
                    mma_f16(c[mt][nt], a1f[mt][0], a1f[mt][1], a1f[mt][2], a1f[mt][3], b00, b01);
                }
            }
        }
        __syncthreads();
    }

    #pragma unroll
    for (int mt = 0; mt < 4; mt++) {
        #pragma unroll
        for (int nt = 0; nt < 4; nt++) {
            int r0 = mt * 16 + lm;
            int cc = nt * 8 + 2 * lk;
            float2 v;
            v.x = c[mt][nt][0] * alpha; v.y = c[mt][nt][1] * alpha;
            *(float2*)(Cptr + (size_t)r0 * N + cc) = v;
            v.x = c[mt][nt][2] * alpha; v.y = c[mt][nt][3] * alpha;
            *(float2*)(Cptr + (size_t)(r0 + 8) * N + cc) = v;
        }
    }
}

// ---------------- split kernels ----------------
__global__ void split_plain(const float* __restrict__ src, __half* dst,
                            long plane, int n) {
    int idx = blockIdx.x * 256 + threadIdx.x;
    if (idx < n) split2(src[idx], dst, idx, plane);
}

// fused 7-weight concat + transpose + split: out planes [4096][1024]
__global__ void splitT_w7(const float* __restrict__ Wq,  const float* __restrict__ Wck,
                          const float* __restrict__ Wcv, const float* __restrict__ Wcg,
                          const float* __restrict__ Wiq, const float* __restrict__ Wik,
                          const float* __restrict__ Wig, __half* out) {
    __shared__ float tile[32][33];
    int k0 = blockIdx.x * 32, n0 = blockIdx.y * 32;
    int tx = threadIdx.x, ty = threadIdx.y;
    {
        int k = k0 + ty, n = n0 + tx;
        float v;
        if      (n < 1024) v = Wq [k * 1024 + n];
        else if (n < 1536) v = Wck[k * 512 + n - 1024];
        else if (n < 2048) v = Wcv[k * 512 + n - 1536];
        else if (n < 2560) v = Wcg[k * 512 + n - 2048];
        else if (n < 3072) v = Wiq[k * 512 + n - 2560];
        else if (n < 3584) v = Wik[k * 512 + n - 3072];
        else               v = Wig[k * 512 + n - 3584];
        tile[ty][tx] = v;
    }
    __syncthreads();
    int n = n0 + ty, k = k0 + tx;
    split2(tile[tx][ty], out, (size_t)n * 1024 + k, PL_WT);
}

// generic transpose+split: src [Kd][Nd] -> out planes [Nd][Kd]
__global__ void splitT_gen(const float* __restrict__ src, __half* out,
                           int Kd, int Nd, long plane) {
    __shared__ float tile[32][33];
    int k0 = blockIdx.x * 32, n0 = blockIdx.y * 32;
    int tx = threadIdx.x, ty = threadIdx.y;
    tile[ty][tx] = src[(size_t)(k0 + ty) * Nd + n0 + tx];
    __syncthreads();
    int n = n0 + ty, k = k0 + tx;
    split2(tile[tx][ty], out, (size_t)n * Kd + k, plane);
}

// ---------------- rope helper ----------------
__device__ __forceinline__ void rope_cs(int i, float pos, float& c, float& s) {
    float f = powf(160000.0f, (float)i * (1.0f / 32.0f));
    float ang = pos / f;
    sincosf(ang, &s, &c);
}

// ---------------- gated compress (coarse KV) + rope on ck ---------------- grid Bb*Gg*HKV, block 128
__global__ void compress_c(const float* __restrict__ ape) {
    int blk = blockIdx.x;
    int h = blk & 3;
    int bg = blk >> 2;
    int g = bg & (Gg - 1);
    int d = threadIdx.x;
    size_t base = (size_t)bg * 4 * NCOL + h * 128 + d;
    float gv[4], m = -1e30f;
    #pragma unroll
    for (int r = 0; r < 4; r++) {
        gv[r] = g_Pall[base + (size_t)r * NCOL + OFF_CG] + ape[(r * HKV + h) * 128 + d];
        m = fmaxf(m, gv[r]);
    }
    float ssum = 0.f;
    #pragma unroll
    for (int r = 0; r < 4; r++) { gv[r] = expf(gv[r] - m); ssum += gv[r]; }
    float inv = 1.f / ssum;
    float ka = 0.f, va = 0.f;
    #pragma unroll
    for (int r = 0; r < 4; r++) {
        float w = gv[r] * inv;
        ka += w * g_Pall[base + (size_t)r * NCOL + OFF_CK];
        va += w * g_Pall[base + (size_t)r * NCOL + OFF_CV];
    }
    __shared__ float sk[128];
    sk[d] = ka;
    __syncthreads();
    float pos = (float)(4 * g + 3);
    float outk = ka;
    if (d >= 64 && d < 96) {
        int i = d - 64; float c, s; rope_cs(i, pos, c, s);
        outk = sk[d] * c - sk[d + 32] * s;
    } else if (d >= 96) {
        int i = d - 96; float c, s; rope_cs(i, pos, c, s);
        outk = sk[d - 32] * s + sk[d] * c;
    }
    size_t ob = ((size_t)bg * 4 + h) * 128 + d;
    g_ck[ob] = outk;
    g_cv[ob] = va;
}

// ---------------- gated compress (index KV) + rmsnorm -> ik splits ---------------- grid Bb*Gg*HIi, block 64
__global__ void compress_i(const float* __restrict__ ape) {
    int blk = blockIdx.x;
    int h = blk & 7;
    int bg = blk >> 3;
    int d = threadIdx.x;
    size_t base = (size_t)bg * 4 * NCOL + h * 64 + d;
    float gv[4], m = -1e30f;
    #pragma unroll
    for (int r = 0; r < 4; r++) {
        gv[r] = g_Pall[base + (size_t)r * NCOL + OFF_IG] + ape[(r * HIi + h) * 64 + d];
        m = fmaxf(m, gv[r]);
    }
    float ssum = 0.f;
    #pragma unroll
    for (int r = 0; r < 4; r++) { gv[r] = expf(gv[r] - m); ssum += gv[r]; }
    float inv = 1.f / ssum;
    float ka = 0.f;
    #pragma unroll
    for (int r = 0; r < 4; r++)
        ka += gv[r] * inv * g_Pall[base + (size_t)r * NCOL + OFF_IK];
    __shared__ float red[64];
    red[d] = ka * ka;
    __syncthreads();
    #pragma unroll
    for (int s2 = 32; s2 > 0; s2 >>= 1) {
        if (d < s2) red[d] += red[d + s2];
        __syncthreads();
    }
    float sc = rsqrtf(red[0] / 64.f + 1e-6f);
    split2(ka * sc, g_iks, ((size_t)bg * 8 + h) * 64 + d, PL_IK);
}

// ---------------- per-head rmsnorm of iq -> iq splits ---------------- grid NTOK*HIi, block 64
__global__ void iq_rms() {
    int blk = blockIdx.x;
    int h = blk & 7;
    int row = blk >> 3;
    int d = threadIdx.x;
    float v = g_Pall[(size_t)row * NCOL + OFF_IQ + h * 64 + d];
    __shared__ float red[64];
    red[d] = v * v;
    __syncthreads();
    #pragma unroll
    for (int s2 = 32; s2 > 0; s2 >>= 1) {
        if (d < s2) red[d] += red[d + s2];
        __syncthreads();
    }
    float sc = rsqrtf(red[0] / 64.f + 1e-6f);
    split2(v * sc, g_iqs, (size_t)row * 512 + h * 64 + d, PL_IQ);
}

// ---------------- in-place partial rope of q ---------------- grid NTOK*Hh, block 32
__global__ void q_rope() {
    int blk = blockIdx.x;
    int h = blk & 7;
    int row = blk >> 3;
    int t = row & (Tt - 1);
    int i = threadIdx.x;
    size_t base = (size_t)row * NCOL + OFF_Q + h * 128;
    float x1 = g_Pall[base + 64 + i];
    float x2 = g_Pall[base + 96 + i];
    float c, s; rope_cs(i, (float)t, c, s);
    g_Pall[base + 64 + i] = x1 * c - x2 * s;
    g_Pall[base + 96 + i] = x1 * s + x2 * c;
}

// ---------------- top-k(64) threshold via bitonic sort ---------------- grid NTOK, block 512
__global__ void topk_thresh() {
    __shared__ float s[512];
    int row = blockIdx.x;
    int t = row & (Tt - 1);
    int tid = threadIdx.x;
    float v = g_isc[(size_t)row * Gg + tid];
    if (4 * tid + 3 > t) v = NEGv;
    s[tid] = v;
    __syncthreads();
    for (int k = 2; k <= 512; k <<= 1) {
        for (int j = k >> 1; j > 0; j >>= 1) {
            int ixj = tid ^ j;
            if (ixj > tid) {
                float a = s[tid], b = s[ixj];
                bool down = ((tid & k) == 0);
                bool sw = down ? (a < b) : (a > b);
                if (sw) { s[tid] = b; s[ixj] = a; }
            }
            __syncthreads();
        }
    }
    if (tid == 0) g_thr[row] = s[63];
}

// ---------------- sparse attention -> at splits ---------------- grid NTOK*Hh, block 128
__global__ void attn_kernel() {
    int blk = blockIdx.x;
    int h = blk & 7;
    int row = blk >> 3;
    int t = row & (Tt - 1);
    int b = row >> 11;
    int tid = threadIdx.x;
    __shared__ int sg[96];
    __shared__ float sw[96];
    __shared__ int cnt;
    __shared__ alignas(16) float qsh[128];
    if (tid == 0) cnt = 0;
    __syncthreads();

    int nc = (t >= 3) ? (((t - 3) >> 2) + 1) : 0;
    float th = g_thr[row];
    const float* iscr = g_isc + (size_t)row * Gg;
    for (int g = tid; g < nc; g += 128) {
        if (iscr[g] >= th) {
            int p = atomicAdd(&cnt, 1);
            if (p < 96) sg[p] = g;
        }
    }
    qsh[tid] = g_Pall[(size_t)row * NCOL + OFF_Q + h * 128 + tid];
    __syncthreads();
    int n = min(cnt, 96);
    int hkv = h >> 1;
    int warp = tid >> 5, lane = tid & 31;
    for (int i = warp; i < n; i += 4) {
        const float* kp = g_ck + ((size_t)(b * Gg + sg[i]) * 4 + hkv) * 128;
        float4 kv = *(const float4*)(kp + lane * 4);
        float4 qv = *(const float4*)(qsh + lane * 4);
        float p = qv.x * kv.x + qv.y * kv.y + qv.z * kv.z + qv.w * kv.w;
        #pragma unroll
        for (int o = 16; o > 0; o >>= 1) p += __shfl_xor_sync(0xffffffffu, p, o);
        if (lane == 0) sw[i] = p * 0.0883883476483184f;
    }
    __syncthreads();
    if (tid == 0 && n > 0) {
        float m = -1e30f;
        for (int i = 0; i < n; i++) m = fmaxf(m, sw[i]);
        float ssum = 0.f;
        for (int i = 0; i < n; i++) { float e = expf(sw[i] - m); sw[i] = e; ssum += e; }
        float inv = 1.f / ssum;
        for (int i = 0; i < n; i++) sw[i] *= inv;
    }
    __syncthreads();
    float acc = 0.f;
    for (int i = 0; i < n; i++)
        acc += sw[i] * g_cv[((size_t)(b * Gg + sg[i]) * 4 + hkv) * 128 + tid];
    split2(acc, g_ats, (size_t)row * 1024 + h * 128 + tid, PL_AT);
}

// ---------------- rmsnorm over RANK=512 -> rn splits ---------------- grid NTOK, block 256
__global__ void rmsnorm512() {
    int row = blockIdx.x;
    int tid = threadIdx.x;
    size_t base = (size_t)row * 512;
    float a = g_r[base + tid], b = g_r[base + 256 + tid];
    __shared__ float red[256];
    red[tid] = a * a + b * b;
    __syncthreads();
    #pragma unroll
    for (int s2 = 128; s2 > 0; s2 >>= 1) {
        if (tid < s2) red[tid] += red[tid + s2];
        __syncthreads();
    }
    float sc = rsqrtf(red[0] / 512.f + 1e-6f);
    split2(a * sc, g_rns, base + tid, PL_RN);
    split2(b * sc, g_rns, base + 256 + tid, PL_RN);
}

// ---------------- launch ----------------
extern "C" void kernel_launch(void* const* d_in, const int* in_sizes, int n_in,
                              void* d_out, int out_size) {
    const float* x     = (const float*)d_in[0];
    const float* Wq    = (const float*)d_in[1];
    const float* Wck   = (const float*)d_in[2];
    const float* Wcv   = (const float*)d_in[3];
    const float* Wcg   = (const float*)d_in[4];
    const float* ape_c = (const float*)d_in[5];
    const float* Wiq   = (const float*)d_in[6];
    const float* Wik   = (const float*)d_in[7];
    const float* Wig   = (const float*)d_in[8];
    const float* ape_i = (const float*)d_in[9];
    const float* Wa    = (const float*)d_in[10];
    const float* Wb    = (const float*)d_in[11];
    float* out = (float*)d_out;

    __half *xs, *WTs, *iks, *iqs, *ats, *Was, *rns, *Wbs;
    float *Pall, *isc, *r;
    cudaGetSymbolAddress((void**)&xs,   g_xs);
    cudaGetSymbolAddress((void**)&WTs,  g_WTs);
    cudaGetSymbolAddress((void**)&Pall, g_Pall);
    cudaGetSymbolAddress((void**)&iks,  g_iks);
    cudaGetSymbolAddress((void**)&iqs,  g_iqs);
    cudaGetSymbolAddress((void**)&isc,  g_isc);
    cudaGetSymbolAddress((void**)&ats,  g_ats);
    cudaGetSymbolAddress((void**)&Was,  g_Was);
    cudaGetSymbolAddress((void**)&r,    g_r);
    cudaGetSymbolAddress((void**)&rns,  g_rns);
    cudaGetSymbolAddress((void**)&Wbs,  g_Wbs);

    static int attr_set = 0;
    if (!attr_set) {
        cudaFuncSetAttribute(mma_gemm_hx, cudaFuncAttributeMaxDynamicSharedMemorySize, HSMEM);
        attr_set = 1;
    }

    // operand splits
    split_plain<<<(NTOK * 1024) / 256, 256>>>(x, xs, PL_X, NTOK * 1024);
    splitT_w7<<<dim3(1024 / 32, NCOL / 32), dim3(32, 32)>>>(Wq, Wck, Wcv, Wcg, Wiq, Wik, Wig, WTs);
    split_plain<<<(512 * 1024) / 256, 256>>>(Wa, Was, PL_WA, 512 * 1024);
    splitT_gen<<<dim3(512 / 32, 1024 / 32), dim3(32, 32)>>>(Wb, Wbs, 512, 1024, PL_WB);

    // fused projection GEMM: Pall = x @ W  (8192 x 4096 x 1024)
    mma_gemm_hx<<<dim3(NCOL / 128, NTOK / 128, 1), 256, HSMEM>>>(
        NTOK, NCOL, 1024, 1.f, xs, PL_X, 0, WTs, PL_WT, 0, Pall, 0);

    // compress + norms + rope
    compress_c<<<Bb * Gg * HKV, 128>>>(ape_c);
    compress_i<<<Bb * Gg * HIi, 64>>>(ape_i);
    iq_rms<<<NTOK * HIi, 64>>>();
    q_rope<<<NTOK * Hh, 32>>>();

    // index scores: batched, alpha = DI^-0.5 / HI = 1/64
    mma_gemm_hx<<<dim3(512 / 128, 2048 / 128, Bb), 256, HSMEM>>>(
        2048, 512, 512, 1.f / 64.f,
        iqs, PL_IQ, (long)2048 * 512,
        iks, PL_IK, (long)512 * 512,
        isc, (long)2048 * 512);

    topk_thresh<<<NTOK, 512>>>();
    attn_kernel<<<NTOK * Hh, 128>>>();

    // r = attn @ Wa^T  (8192 x 512 x 1024)
    mma_gemm_hx<<<dim3(512 / 128, NTOK / 128, 1), 256, HSMEM>>>(
        NTOK, 512, 1024, 1.f, ats, PL_AT, 0, Was, PL_WA, 0, r, 0);

    rmsnorm512<<<NTOK, 256>>>();

    // out = rn @ Wb  (8192 x 1024 x 512)
    mma_gemm_hx<<<dim3(1024 / 128, NTOK / 128, 1), 256, HSMEM>>>(
        NTOK, 1024, 512, 1.f, rns, PL_RN, 0, Wbs, PL_WB, 0, out, 0);
}

// round 9
// speedup vs baseline: 2.2661x; 1.0522x over previous
#include <cuda_runtime.h>
#include <cuda_fp16.h>
#include <math.h>
#include <stdint.h>

// Problem constants
#define Bb 4
#define Tt 2048
#define Cc 1024
#define Hh 8
#define HKV 4
#define Dd 128
#define Gg 512
#define HIi 8
#define DIi 64
#define NEGv (-1e30f)

#define NTOK (Bb*Tt)   // 8192
#define NCOL 4096      // fused projection width: q|ck|cv|cg|iq|ik|ig
#define OFF_Q  0
#define OFF_CK 1024
#define OFF_CV 1536
#define OFF_CG 2048
#define OFF_IQ 2560
#define OFF_IK 3072
#define OFF_IG 3584

// plane strides (elements)
#define PL_X   ((long)NTOK*1024)
#define PL_WT  ((long)NCOL*1024)
#define PL_IQ  ((long)NTOK*512)
#define PL_IK  ((long)Bb*512*512)
#define PL_AT  ((long)NTOK*1024)
#define PL_WA  ((long)512*1024)
#define PL_RN  ((long)NTOK*512)
#define PL_WB  ((long)1024*512)

// ---------------- scratch (static device allocations) ----------------
__device__ alignas(256) __half g_xs [2*PL_X];
__device__ alignas(256) __half g_WTs[2*PL_WT];
__device__ alignas(256) float g_Pall[(size_t)NTOK*NCOL];
__device__ alignas(256) float g_ck [Bb*Gg*HKV*Dd];
__device__ alignas(256) float g_cv [Bb*Gg*HKV*Dd];
__device__ alignas(256) __half g_iks[2*PL_IK];
__device__ alignas(256) __half g_iqs[2*PL_IQ];
__device__ alignas(256) float g_isc[NTOK*Gg];
__device__ alignas(256) float g_thr[NTOK];
__device__ alignas(256) __half g_ats[2*PL_AT];
__device__ alignas(256) __half g_Was[2*PL_WA];
__device__ alignas(256) float g_r  [NTOK*512];
__device__ alignas(256) __half g_rns[2*PL_RN];
__device__ alignas(256) __half g_Wbs[2*PL_WB];

// ---------------- helpers ----------------
__device__ __forceinline__ void cpa16(uint32_t dst, const void* src) {
    asm volatile("cp.async.cg.shared.global [%0], [%1], 16;\n" :: "r"(dst), "l"(src));
}
__device__ __forceinline__ void cp_commit() {
    asm volatile("cp.async.commit_group;\n");
}
// fp16 2-way split: v = h0 + h1 + O(2^-24 v)
__device__ __forceinline__ void split2(float v, __half* p, size_t idx, long plane) {
    __half h0 = __float2half_rn(v);
    float r1 = v - __half2float(h0);
    p[idx]         = h0;
    p[idx + plane] = __float2half_rn(r1);
}
__device__ __forceinline__ void mma_f16(float* c,
    uint32_t a0, uint32_t a1, uint32_t a2, uint32_t a3,
    uint32_t b0, uint32_t b1) {
    asm volatile(
        "mma.sync.aligned.m16n8k16.row.col.f32.f16.f16.f32 "
        "{%0,%1,%2,%3},{%4,%5,%6,%7},{%8,%9},{%0,%1,%2,%3};"
        : "+f"(c[0]), "+f"(c[1]), "+f"(c[2]), "+f"(c[3])
        : "r"(a0), "r"(a1), "r"(a2), "r"(a3), "r"(b0), "r"(b1));
}

// ---------------- fp16x3 MMA GEMM (fp32-accurate): C = alpha * A[M,K] @ B[N,K]^T ----------------
// A, B given as 2 fp16 split planes, row-major [rows][K]. BM=BN=128, BK=32.
// 256 threads (8 warps 2x4), warp tile 64x32. Requires M,N % 128 == 0, K % 32 == 0.
// smem layout (u32 units): per row 16 pairs + 4 pad = stride 20.
#define HPLANE 2560          // 128 rows * 20 u32
#define HBUF   5120          // 2 planes
#define HTOT   10240         // A + B per buffer
#define HSMEM  (2 * HTOT * 4)  // 81920 bytes

__global__ void __launch_bounds__(256, 2) mma_gemm_hx(
    int M, int N, int K, float alpha,
    const __half* __restrict__ A0, long planeA, long batA,
    const __half* __restrict__ B0, long planeB, long batB,
    float* __restrict__ C, long batC) {
    extern __shared__ char smraw[];
    uint32_t* sm32 = (uint32_t*)smraw;
    uint32_t sbase = (uint32_t)__cvta_generic_to_shared(smraw);

    const int tid  = threadIdx.x;
    const int wid  = tid >> 5;
    const int lane = tid & 31;
    const int lm   = lane >> 2;     // 0..7
    const int lk   = lane & 3;      // 0..3
    const int warp_m = (wid & 1) * 64;
    const int warp_n = (wid >> 1) * 32;
    const int bm = blockIdx.y * 128;
    const int bn = blockIdx.x * 128;
    const int z  = blockIdx.z;

    const __half* Abase = A0 + (size_t)z * batA;
    const __half* Bbase = B0 + (size_t)z * batB;
    float* Cptr = C + (size_t)z * batC + (size_t)(bm + warp_m) * N + bn + warp_n;

    float c[4][4][4];
    #pragma unroll
    for (int mt = 0; mt < 4; mt++)
        #pragma unroll
        for (int nt = 0; nt < 4; nt++)
            #pragma unroll
            for (int i = 0; i < 4; i++) c[mt][nt][i] = 0.f;

    const int nIter = K >> 5;

    auto stage = [&](int it, int buf) {
        const int k0 = it * 32;
        const uint32_t abase = sbase + (uint32_t)(buf * HTOT) * 4u;
        const uint32_t bbase = abase + HBUF * 4u;
        #pragma unroll
        for (int i = 0; i < 4; i++) {
            int id = tid + i * 256;
            int p = id >> 9, rem = id & 511, row = rem >> 2, cc = rem & 3;
            cpa16(abase + (uint32_t)(p * HPLANE + row * 20) * 4u + cc * 16,
                  Abase + (size_t)p * planeA + (size_t)(bm + row) * K + k0 + cc * 8);
        }
        #pragma unroll
        for (int i = 0; i < 4; i++) {
            int id = tid + i * 256;
            int p = id >> 9, rem = id & 511, row = rem >> 2, cc = rem & 3;
            cpa16(bbase + (uint32_t)(p * HPLANE + row * 20) * 4u + cc * 16,
                  Bbase + (size_t)p * planeB + (size_t)(bn + row) * K + k0 + cc * 8);
        }
        cp_commit();
    };

    stage(0, 0);

    for (int it = 0; it < nIter; it++) {
        const int buf = it & 1;
        if (it + 1 < nIter) {
            stage(it + 1, buf ^ 1);
            asm volatile("cp.async.wait_group 1;\n" ::: "memory");
        } else {
            asm volatile("cp.async.wait_group 0;\n" ::: "memory");
        }
        __syncthreads();

        const uint32_t* Asm = sm32 + buf * HTOT;
        const uint32_t* Bsm = Asm + HBUF;

        #pragma unroll
        for (int kc = 0; kc < 2; kc++) {       // two k16 slices of the 32-K chunk
            const int o = kc * 8 + lk;
            // B fragments for all 4 nt tiles (16 regs), loaded once per k16 slice
            uint32_t bf[4][4];
            #pragma unroll
            for (int nt = 0; nt < 4; nt++) {
                int n = warp_n + nt * 8 + lm;
                bf[nt][0] = Bsm[n * 20 + o];               // plane0 k0-7
                bf[nt][1] = Bsm[n * 20 + o + 4];           // plane0 k8-15
                bf[nt][2] = Bsm[HPLANE + n * 20 + o];      // plane1 k0-7
                bf[nt][3] = Bsm[HPLANE + n * 20 + o + 4];  // plane1 k8-15
            }
            #pragma unroll
            for (int mt = 0; mt < 4; mt++) {
                // A fragments for this mt tile only (8 regs)
                const int r = warp_m + mt * 16 + lm;
                uint32_t a0[4], a1[4];
                a0[0] = Asm[r * 20 + o];
                a0[1] = Asm[(r + 8) * 20 + o];
                a0[2] = Asm[r * 20 + o + 4];
                a0[3] = Asm[(r + 8) * 20 + o + 4];
                a1[0] = Asm[HPLANE + r * 20 + o];
                a1[1] = Asm[HPLANE + (r + 8) * 20 + o];
                a1[2] = Asm[HPLANE + r * 20 + o + 4];
                a1[3] = Asm[HPLANE + (r + 8) * 20 + o + 4];
                // term-major ordering: 4 independent accumulator chains between
                // dependent MMAs (covers HMMA latency)
                #pragma unroll
                for (int nt = 0; nt < 4; nt++)
                    mma_f16(c[mt][nt], a0[0], a0[1], a0[2], a0[3], bf[nt][0], bf[nt][1]);
                #pragma unroll
                for (int nt = 0; nt < 4; nt++)
                    mma_f16(c[mt][nt], a0[0], a0[1], a0[2], a0[3], bf[nt][2], bf[nt][3]);
                #pragma unroll
                for (int nt = 0; nt < 4; nt++)
                    mma_f16(c[mt][nt], a1[0], a1[1], a1[2], a1[3], bf[nt][0], bf[nt][1]);
            }
        }
        __syncthreads();
    }

    #pragma unroll
    for (int mt = 0; mt < 4; mt++) {
        #pragma unroll
        for (int nt = 0; nt < 4; nt++) {
            int r0 = mt * 16 + lm;
            int cc = nt * 8 + 2 * lk;
            float2 v;
            v.x = c[mt][nt][0] * alpha; v.y = c[mt][nt][1] * alpha;
            *(float2*)(Cptr + (size_t)r0 * N + cc) = v;
            v.x = c[mt][nt][2] * alpha; v.y = c[mt][nt][3] * alpha;
            *(float2*)(Cptr + (size_t)(r0 + 8) * N + cc) = v;
        }
    }
}

// ---------------- split kernels ----------------
__global__ void split_plain(const float* __restrict__ src, __half* dst,
                            long plane, int n) {
    int idx = blockIdx.x * 256 + threadIdx.x;
    if (idx < n) split2(src[idx], dst, idx, plane);
}

// fused 7-weight concat + transpose + split: out planes [4096][1024]
__global__ void splitT_w7(const float* __restrict__ Wq,  const float* __restrict__ Wck,
                          const float* __restrict__ Wcv, const float* __restrict__ Wcg,
                          const float* __restrict__ Wiq, const float* __restrict__ Wik,
                          const float* __restrict__ Wig, __half* out) {
    __shared__ float tile[32][33];
    int k0 = blockIdx.x * 32, n0 = blockIdx.y * 32;
    int tx = threadIdx.x, ty = threadIdx.y;
    {
        int k = k0 + ty, n = n0 + tx;
        float v;
        if      (n < 1024) v = Wq [k * 1024 + n];
        else if (n < 1536) v = Wck[k * 512 + n - 1024];
        else if (n < 2048) v = Wcv[k * 512 + n - 1536];
        else if (n < 2560) v = Wcg[k * 512 + n - 2048];
        else if (n < 3072) v = Wiq[k * 512 + n - 2560];
        else if (n < 3584) v = Wik[k * 512 + n - 3072];
        else               v = Wig[k * 512 + n - 3584];
        tile[ty][tx] = v;
    }
    __syncthreads();
    int n = n0 + ty, k = k0 + tx;
    split2(tile[tx][ty], out, (size_t)n * 1024 + k, PL_WT);
}

// generic transpose+split: src [Kd][Nd] -> out planes [Nd][Kd]
__global__ void splitT_gen(const float* __restrict__ src, __half* out,
                           int Kd, int Nd, long plane) {
    __shared__ float tile[32][33];
    int k0 = blockIdx.x * 32, n0 = blockIdx.y * 32;
    int tx = threadIdx.x, ty = threadIdx.y;
    tile[ty][tx] = src[(size_t)(k0 + ty) * Nd + n0 + tx];
    __syncthreads();
    int n = n0 + ty, k = k0 + tx;
    split2(tile[tx][ty], out, (size_t)n * Kd + k, plane);
}

// ---------------- rope helper ----------------
__device__ __forceinline__ void rope_cs(int i, float pos, float& c, float& s) {
    float f = powf(160000.0f, (float)i * (1.0f / 32.0f));
    float ang = pos / f;
    sincosf(ang, &s, &c);
}

// ---------------- gated compress (coarse KV) + rope on ck ---------------- grid Bb*Gg*HKV, block 128
__global__ void compress_c(const float* __restrict__ ape) {
    int blk = blockIdx.x;
    int h = blk & 3;
    int bg = blk >> 2;
    int g = bg & (Gg - 1);
    int d = threadIdx.x;
    size_t base = (size_t)bg * 4 * NCOL + h * 128 + d;
    float gv[4], m = -1e30f;
    #pragma unroll
    for (int r = 0; r < 4; r++) {
        gv[r] = g_Pall[base + (size_t)r * NCOL + OFF_CG] + ape[(r * HKV + h) * 128 + d];
        m = fmaxf(m, gv[r]);
    }
    float ssum = 0.f;
    #pragma unroll
    for (int r = 0; r < 4; r++) { gv[r] = expf(gv[r] - m); ssum += gv[r]; }
    float inv = 1.f / ssum;
    float ka = 0.f, va = 0.f;
    #pragma unroll
    for (int r = 0; r < 4; r++) {
        float w = gv[r] * inv;
        ka += w * g_Pall[base + (size_t)r * NCOL + OFF_CK];
        va += w * g_Pall[base + (size_t)r * NCOL + OFF_CV];
    }
    __shared__ float sk[128];
    sk[d] = ka;
    __syncthreads();
    float pos = (float)(4 * g + 3);
    float outk = ka;
    if (d >= 64 && d < 96) {
        int i = d - 64; float c, s; rope_cs(i, pos, c, s);
        outk = sk[d] * c - sk[d + 32] * s;
    } else if (d >= 96) {
        int i = d - 96; float c, s; rope_cs(i, pos, c, s);
        outk = sk[d - 32] * s + sk[d] * c;
    }
    size_t ob = ((size_t)bg * 4 + h) * 128 + d;
    g_ck[ob] = outk;
    g_cv[ob] = va;
}

// ---------------- gated compress (index KV) + rmsnorm -> ik splits ---------------- grid Bb*Gg*HIi, block 64
__global__ void compress_i(const float* __restrict__ ape) {
    int blk = blockIdx.x;
    int h = blk & 7;
    int bg = blk >> 3;
    int d = threadIdx.x;
    size_t base = (size_t)bg * 4 * NCOL + h * 64 + d;
    float gv[4], m = -1e30f;
    #pragma unroll
    for (int r = 0; r < 4; r++) {
        gv[r] = g_Pall[base + (size_t)r * NCOL + OFF_IG] + ape[(r * HIi + h) * 64 + d];
        m = fmaxf(m, gv[r]);
    }
    float ssum = 0.f;
    #pragma unroll
    for (int r = 0; r < 4; r++) { gv[r] = expf(gv[r] - m); ssum += gv[r]; }
    float inv = 1.f / ssum;
    float ka = 0.f;
    #pragma unroll
    for (int r = 0; r < 4; r++)
        ka += gv[r] * inv * g_Pall[base + (size_t)r * NCOL + OFF_IK];
    __shared__ float red[64];
    red[d] = ka * ka;
    __syncthreads();
    #pragma unroll
    for (int s2 = 32; s2 > 0; s2 >>= 1) {
        if (d < s2) red[d] += red[d + s2];
        __syncthreads();
    }
    float sc = rsqrtf(red[0] / 64.f + 1e-6f);
    split2(ka * sc, g_iks, ((size_t)bg * 8 + h) * 64 + d, PL_IK);
}

// ---------------- per-head rmsnorm of iq -> iq splits ---------------- grid NTOK*HIi, block 64
__global__ void iq_rms() {
    int blk = blockIdx.x;
    int h = blk & 7;
    int row = blk >> 3;
    int d = threadIdx.x;
    float v = g_Pall[(size_t)row * NCOL + OFF_IQ + h * 64 + d];
    __shared__ float red[64];
    red[d] = v * v;
    __syncthreads();
    #pragma unroll
    for (int s2 = 32; s2 > 0; s2 >>= 1) {
        if (d < s2) red[d] += red[d + s2];
        __syncthreads();
    }
    float sc = rsqrtf(red[0] / 64.f + 1e-6f);
    split2(v * sc, g_iqs, (size_t)row * 512 + h * 64 + d, PL_IQ);
}

// ---------------- in-place partial rope of q ---------------- grid NTOK*Hh, block 32
__global__ void q_rope() {
    int blk = blockIdx.x;
    int h = blk & 7;
    int row = blk >> 3;
    int t = row & (Tt - 1);
    int i = threadIdx.x;
    size_t base = (size_t)row * NCOL + OFF_Q + h * 128;
    float x1 = g_Pall[base + 64 + i];
    float x2 = g_Pall[base + 96 + i];
    float c, s; rope_cs(i, (float)t, c, s);
    g_Pall[base + 64 + i] = x1 * c - x2 * s;
    g_Pall[base + 96 + i] = x1 * s + x2 * c;
}

// ---------------- top-k(64) threshold via bitonic sort ---------------- grid NTOK, block 512
__global__ void topk_thresh() {
    __shared__ float s[512];
    int row = blockIdx.x;
    int t = row & (Tt - 1);
    int tid = threadIdx.x;
    float v = g_isc[(size_t)row * Gg + tid];
    if (4 * tid + 3 > t) v = NEGv;
    s[tid] = v;
    __syncthreads();
    for (int k = 2; k <= 512; k <<= 1) {
        for (int j = k >> 1; j > 0; j >>= 1) {
            int ixj = tid ^ j;
            if (ixj > tid) {
                float a = s[tid], b = s[ixj];
                bool down = ((tid & k) == 0);
                bool sw = down ? (a < b) : (a > b);
                if (sw) { s[tid] = b; s[ixj] = a; }
            }
            __syncthreads();
        }
    }
    if (tid == 0) g_thr[row] = s[63];
}

// ---------------- sparse attention -> at splits ---------------- grid NTOK*Hh, block 128
__global__ void attn_kernel() {
    int blk = blockIdx.x;
    int h = blk & 7;
    int row = blk >> 3;
    int t = row & (Tt - 1);
    int b = row >> 11;
    int tid = threadIdx.x;
    __shared__ int sg[96];
    __shared__ float sw[96];
    __shared__ int cnt;
    __shared__ alignas(16) float qsh[128];
    if (tid == 0) cnt = 0;
    __syncthreads();

    int nc = (t >= 3) ? (((t - 3) >> 2) + 1) : 0;
    float th = g_thr[row];
    const float* iscr = g_isc + (size_t)row * Gg;
    for (int g = tid; g < nc; g += 128) {
        if (iscr[g] >= th) {
            int p = atomicAdd(&cnt, 1);
            if (p < 96) sg[p] = g;
        }
    }
    qsh[tid] = g_Pall[(size_t)row * NCOL + OFF_Q + h * 128 + tid];
    __syncthreads();
    int n = min(cnt, 96);
    int hkv = h >> 1;
    int warp = tid >> 5, lane = tid & 31;
    for (int i = warp; i < n; i += 4) {
        const float* kp = g_ck + ((size_t)(b * Gg + sg[i]) * 4 + hkv) * 128;
        float4 kv = *(const float4*)(kp + lane * 4);
        float4 qv = *(const float4*)(qsh + lane * 4);
        float p = qv.x * kv.x + qv.y * kv.y + qv.z * kv.z + qv.w * kv.w;
        #pragma unroll
        for (int o = 16; o > 0; o >>= 1) p += __shfl_xor_sync(0xffffffffu, p, o);
        if (lane == 0) sw[i] = p * 0.0883883476483184f;
    }
    __syncthreads();
    if (tid == 0 && n > 0) {
        float m = -1e30f;
        for (int i = 0; i < n; i++) m = fmaxf(m, sw[i]);
        float ssum = 0.f;
        for (int i = 0; i < n; i++) { float e = expf(sw[i] - m); sw[i] = e; ssum += e; }
        float inv = 1.f / ssum;
        for (int i = 0; i < n; i++) sw[i] *= inv;
    }
    __syncthreads();
    float acc = 0.f;
    for (int i = 0; i < n; i++)
        acc += sw[i] * g_cv[((size_t)(b * Gg + sg[i]) * 4 + hkv) * 128 + tid];
    split2(acc, g_ats, (size_t)row * 1024 + h * 128 + tid, PL_AT);
}

// ---------------- rmsnorm over RANK=512 -> rn splits ---------------- grid NTOK, block 256
__global__ void rmsnorm512() {
    int row = blockIdx.x;
    int tid = threadIdx.x;
    size_t base = (size_t)row * 512;
    float a = g_r[base + tid], b = g_r[base + 256 + tid];
    __shared__ float red[256];
    red[tid] = a * a + b * b;
    __syncthreads();
    #pragma unroll
    for (int s2 = 128; s2 > 0; s2 >>= 1) {
        if (tid < s2) red[tid] += red[tid + s2];
        __syncthreads();
    }
    float sc = rsqrtf(red[0] / 512.f + 1e-6f);
    split2(a * sc, g_rns, base + tid, PL_RN);
    split2(b * sc, g_rns, base + 256 + tid, PL_RN);
}

// ---------------- launch ----------------
extern "C" void kernel_launch(void* const* d_in, const int* in_sizes, int n_in,
                              void* d_out, int out_size) {
    const float* x     = (const float*)d_in[0];
    const float* Wq    = (const float*)d_in[1];
    const float* Wck   = (const float*)d_in[2];
    const float* Wcv   = (const float*)d_in[3];
    const float* Wcg   = (const float*)d_in[4];
    const float* ape_c = (const float*)d_in[5];
    const float* Wiq   = (const float*)d_in[6];
    const float* Wik   = (const float*)d_in[7];
    const float* Wig   = (const float*)d_in[8];
    const float* ape_i = (const float*)d_in[9];
    const float* Wa    = (const float*)d_in[10];
    const float* Wb    = (const float*)d_in[11];
    float* out = (float*)d_out;

    __half *xs, *WTs, *iks, *iqs, *ats, *Was, *rns, *Wbs;
    float *Pall, *isc, *r;
    cudaGetSymbolAddress((void**)&xs,   g_xs);
    cudaGetSymbolAddress((void**)&WTs,  g_WTs);
    cudaGetSymbolAddress((void**)&Pall, g_Pall);
    cudaGetSymbolAddress((void**)&iks,  g_iks);
    cudaGetSymbolAddress((void**)&iqs,  g_iqs);
    cudaGetSymbolAddress((void**)&isc,  g_isc);
    cudaGetSymbolAddress((void**)&ats,  g_ats);
    cudaGetSymbolAddress((void**)&Was,  g_Was);
    cudaGetSymbolAddress((void**)&r,    g_r);
    cudaGetSymbolAddress((void**)&rns,  g_rns);
    cudaGetSymbolAddress((void**)&Wbs,  g_Wbs);

    static int attr_set = 0;
    if (!attr_set) {
        cudaFuncSetAttribute(mma_gemm_hx, cudaFuncAttributeMaxDynamicSharedMemorySize, HSMEM);
        attr_set = 1;
    }

    // operand splits
    split_plain<<<(NTOK * 1024) / 256, 256>>>(x, xs, PL_X, NTOK * 1024);
    splitT_w7<<<dim3(1024 / 32, NCOL / 32), dim3(32, 32)>>>(Wq, Wck, Wcv, Wcg, Wiq, Wik, Wig, WTs);
    split_plain<<<(512 * 1024) / 256, 256>>>(Wa, Was, PL_WA, 512 * 1024);
    splitT_gen<<<dim3(512 / 32, 1024 / 32), dim3(32, 32)>>>(Wb, Wbs, 512, 1024, PL_WB);

    // fused projection GEMM: Pall = x @ W  (8192 x 4096 x 1024)
    mma_gemm_hx<<<dim3(NCOL / 128, NTOK / 128, 1), 256, HSMEM>>>(
        NTOK, NCOL, 1024, 1.f, xs, PL_X, 0, WTs, PL_WT, 0, Pall, 0);

    // compress + norms + rope
    compress_c<<<Bb * Gg * HKV, 128>>>(ape_c);
    compress_i<<<Bb * Gg * HIi, 64>>>(ape_i);
    iq_rms<<<NTOK * HIi, 64>>>();
    q_rope<<<NTOK * Hh, 32>>>();

    // index scores: batched, alpha = DI^-0.5 / HI = 1/64
    mma_gemm_hx<<<dim3(512 / 128, 2048 / 128, Bb), 256, HSMEM>>>(
        2048, 512, 512, 1.f / 64.f,
        iqs, PL_IQ, (long)2048 * 512,
        iks, PL_IK, (long)512 * 512,
        isc, (long)2048 * 512);

    topk_thresh<<<NTOK, 512>>>();
    attn_kernel<<<NTOK * Hh, 128>>>();

    // r = attn @ Wa^T  (8192 x 512 x 1024)
    mma_gemm_hx<<<dim3(512 / 128, NTOK / 128, 1), 256, HSMEM>>>(
        NTOK, 512, 1024, 1.f, ats, PL_AT, 0, Was, PL_WA, 0, r, 0);

    rmsnorm512<<<NTOK, 256>>>();

    // out = rn @ Wb  (8192 x 1024 x 512)
    mma_gemm_hx<<<dim3(1024 / 128, NTOK / 128, 1), 256, HSMEM>>>(
        NTOK, 1024, 512, 1.f, rns, PL_RN, 0, Wbs, PL_WB, 0, out, 0);
}

// round 10
// speedup vs baseline: 2.2852x; 1.0084x over previous
#include <cuda_runtime.h>
#include <cuda_fp16.h>
#include <math.h>
#include <stdint.h>

// Problem constants
#define Bb 4
#define Tt 2048
#define Cc 1024
#define Hh 8
#define HKV 4
#define Dd 128
#define Gg 512
#define HIi 8
#define DIi 64
#define NEGv (-1e30f)

#define NTOK (Bb*Tt)   // 8192
#define NCOL 4096      // fused projection width: q|ck|cv|cg|iq|ik|ig
#define OFF_Q  0
#define OFF_CK 1024
#define OFF_CV 1536
#define OFF_CG 2048
#define OFF_IQ 2560
#define OFF_IK 3072
#define OFF_IG 3584

// plane strides (elements)
#define PL_X   ((long)NTOK*1024)
#define PL_WT  ((long)NCOL*1024)
#define PL_IQ  ((long)NTOK*512)
#define PL_IK  ((long)Bb*512*512)
#define PL_AT  ((long)NTOK*1024)
#define PL_WA  ((long)512*1024)
#define PL_RN  ((long)NTOK*512)
#define PL_WB  ((long)1024*512)

// ---------------- scratch (static device allocations) ----------------
__device__ alignas(256) __half g_xs [2*PL_X];
__device__ alignas(256) __half g_WTs[2*PL_WT];
__device__ alignas(256) float g_Pall[(size_t)NTOK*NCOL];
__device__ alignas(256) float g_ck [Bb*Gg*HKV*Dd];
__device__ alignas(256) float g_cv [Bb*Gg*HKV*Dd];
__device__ alignas(256) __half g_iks[2*PL_IK];
__device__ alignas(256) __half g_iqs[2*PL_IQ];
__device__ alignas(256) float g_isc[NTOK*Gg];
__device__ alignas(256) float g_thr[NTOK];
__device__ alignas(256) __half g_ats[2*PL_AT];
__device__ alignas(256) __half g_Was[2*PL_WA];
__device__ alignas(256) float g_r  [NTOK*512];
__device__ alignas(256) __half g_rns[2*PL_RN];
__device__ alignas(256) __half g_Wbs[2*PL_WB];

// ---------------- helpers ----------------
__device__ __forceinline__ void cpa16(uint32_t dst, const void* src) {
    asm volatile("cp.async.cg.shared.global [%0], [%1], 16;\n" :: "r"(dst), "l"(src));
}
__device__ __forceinline__ void cp_commit() {
    asm volatile("cp.async.commit_group;\n");
}
// k-permutation within a 32-element group: u32 j -> ((j&3)<<2)|(j>>2)
__device__ __forceinline__ int permk(int idx) {
    int kk = idx & 31;
    int j = kk >> 1;
    int jn = ((j & 3) << 2) | (j >> 2);
    return (idx & ~31) | (jn << 1) | (kk & 1);
}
// fp16 2-way split with permuted k index
__device__ __forceinline__ void split2(float v, __half* p, size_t base, int kidx, long plane) {
    __half h0 = __float2half_rn(v);
    float r1 = v - __half2float(h0);
    size_t idx = base + (size_t)permk(kidx);
    p[idx]         = h0;
    p[idx + plane] = __float2half_rn(r1);
}
__device__ __forceinline__ void mma_f16(float* c,
    uint32_t a0, uint32_t a1, uint32_t a2, uint32_t a3,
    uint32_t b0, uint32_t b1) {
    asm volatile(
        "mma.sync.aligned.m16n8k16.row.col.f32.f16.f16.f32 "
        "{%0,%1,%2,%3},{%4,%5,%6,%7},{%8,%9},{%0,%1,%2,%3};"
        : "+f"(c[0]), "+f"(c[1]), "+f"(c[2]), "+f"(c[3])
        : "r"(a0), "r"(a1), "r"(a2), "r"(a3), "r"(b0), "r"(b1));
}
__device__ __forceinline__ uint4 lds128(uint32_t addr) {
    uint4 v;
    asm volatile("ld.shared.v4.u32 {%0,%1,%2,%3}, [%4];"
                 : "=r"(v.x), "=r"(v.y), "=r"(v.z), "=r"(v.w) : "r"(addr));
    return v;
}

// ---------------- fp16x3 MMA GEMM (fp32-accurate): C = alpha * A[M,K] @ B[N,K]^T ----------------
// A, B given as 2 fp16 split planes, row-major [rows][K], K elements permuted per 32-group
// by permk. BM=BN=128, BK=32, 256 threads (8 warps 2x4), warp tile 64x32.
// smem: stride 16 u32 per row (no pad; LDS.128-conflict-free under permuted layout).
#define HPLANE 2048          // 128 rows * 16 u32
#define HBUF   4096          // 2 planes
#define HTOT   8192          // A + B per buffer
#define HSMEM  (2 * HTOT * 4)  // 65536 bytes

__global__ void __launch_bounds__(256, 2) mma_gemm_hx(
    int M, int N, int K, float alpha,
    const __half* __restrict__ A0, long planeA, long batA,
    const __half* __restrict__ B0, long planeB, long batB,
    float* __restrict__ C, long batC) {
    extern __shared__ char smraw[];
    uint32_t sbase = (uint32_t)__cvta_generic_to_shared(smraw);

    const int tid  = threadIdx.x;
    const int wid  = tid >> 5;
    const int lane = tid & 31;
    const int lm   = lane >> 2;     // 0..7
    const int lk   = lane & 3;      // 0..3
    const int warp_m = (wid & 1) * 64;
    const int warp_n = (wid >> 1) * 32;
    const int bm = blockIdx.y * 128;
    const int bn = blockIdx.x * 128;
    const int z  = blockIdx.z;

    const __half* Abase = A0 + (size_t)z * batA;
    const __half* Bbase = B0 + (size_t)z * batB;
    float* Cptr = C + (size_t)z * batC + (size_t)(bm + warp_m) * N + bn + warp_n;

    float c[4][4][4];
    #pragma unroll
    for (int mt = 0; mt < 4; mt++)
        #pragma unroll
        for (int nt = 0; nt < 4; nt++)
            #pragma unroll
            for (int i = 0; i < 4; i++) c[mt][nt][i] = 0.f;

    const int nIter = K >> 5;

    auto stage = [&](int it, int buf) {
        const int k0 = it * 32;
        const uint32_t abase = sbase + (uint32_t)(buf * HTOT) * 4u;
        const uint32_t bbase = abase + HBUF * 4u;
        #pragma unroll
        for (int i = 0; i < 4; i++) {
            int id = tid + i * 256;
            int p = id >> 9, rem = id & 511, row = rem >> 2, cc = rem & 3;
            cpa16(abase + (uint32_t)(p * HPLANE + row * 16 + cc * 4) * 4u,
                  Abase + (size_t)p * planeA + (size_t)(bm + row) * K + k0 + cc * 8);
        }
        #pragma unroll
        for (int i = 0; i < 4; i++) {
            int id = tid + i * 256;
            int p = id >> 9, rem = id & 511, row = rem >> 2, cc = rem & 3;
            cpa16(bbase + (uint32_t)(p * HPLANE + row * 16 + cc * 4) * 4u,
                  Bbase + (size_t)p * planeB + (size_t)(bn + row) * K + k0 + cc * 8);
        }
        cp_commit();
    };

    stage(0, 0);

    for (int it = 0; it < nIter; it++) {
        const int buf = it & 1;
        if (it + 1 < nIter) {
            stage(it + 1, buf ^ 1);
            asm volatile("cp.async.wait_group 1;\n" ::: "memory");
        } else {
            asm volatile("cp.async.wait_group 0;\n" ::: "memory");
        }
        __syncthreads();

        const uint32_t abufb = sbase + (uint32_t)(buf * HTOT) * 4u;
        const uint32_t bbufb = abufb + HBUF * 4u;

        // B fragments: one LDS.128 per (nt, plane) covers both k16 slices.
        // .x/.y = kc0 b0/b1 ; .z/.w = kc1 b0/b1
        uint4 b0f[4], b1f[4];
        #pragma unroll
        for (int nt = 0; nt < 4; nt++) {
            uint32_t baddr = bbufb + (uint32_t)(warp_n + nt * 8 + lm) * 64u + lk * 16u;
            b0f[nt] = lds128(baddr);
            b1f[nt] = lds128(baddr + HPLANE * 4u);
        }

        #pragma unroll
        for (int mt = 0; mt < 4; mt++) {
            const uint32_t aaddr = abufb + (uint32_t)(warp_m + mt * 16 + lm) * 64u + lk * 16u;
            // plane0: rows lm (lo) and lm+8 (hi); .x/.y = kc0 reg0/reg2, .z/.w = kc1
            uint4 alo0 = lds128(aaddr);
            uint4 ahi0 = lds128(aaddr + 8u * 64u);
            uint4 alo1 = lds128(aaddr + HPLANE * 4u);
            uint4 ahi1 = lds128(aaddr + HPLANE * 4u + 8u * 64u);
            // kc0 — 3 compensation terms, nt-inner for accumulator independence
            #pragma unroll
            for (int nt = 0; nt < 4; nt++)
                mma_f16(c[mt][nt], alo0.x, ahi0.x, alo0.y, ahi0.y, b0f[nt].x, b0f[nt].y);
            #pragma unroll
            for (int nt = 0; nt < 4; nt++)
                mma_f16(c[mt][nt], alo0.x, ahi0.x, alo0.y, ahi0.y, b1f[nt].x, b1f[nt].y);
            #pragma unroll
            for (int nt = 0; nt < 4; nt++)
                mma_f16(c[mt][nt], alo1.x, ahi1.x, alo1.y, ahi1.y, b0f[nt].x, b0f[nt].y);
            // kc1
            #pragma unroll
            for (int nt = 0; nt < 4; nt++)
                mma_f16(c[mt][nt], alo0.z, ahi0.z, alo0.w, ahi0.w, b0f[nt].z, b0f[nt].w);
            #pragma unroll
            for (int nt = 0; nt < 4; nt++)
                mma_f16(c[mt][nt], alo0.z, ahi0.z, alo0.w, ahi0.w, b1f[nt].z, b1f[nt].w);
            #pragma unroll
            for (int nt = 0; nt < 4; nt++)
                mma_f16(c[mt][nt], alo1.z, ahi1.z, alo1.w, ahi1.w, b0f[nt].z, b0f[nt].w);
        }
        __syncthreads();
    }

    #pragma unroll
    for (int mt = 0; mt < 4; mt++) {
        #pragma unroll
        for (int nt = 0; nt < 4; nt++) {
            int r0 = mt * 16 + lm;
            int cc = nt * 8 + 2 * lk;
            float2 v;
            v.x = c[mt][nt][0] * alpha; v.y = c[mt][nt][1] * alpha;
            *(float2*)(Cptr + (size_t)r0 * N + cc) = v;
            v.x = c[mt][nt][2] * alpha; v.y = c[mt][nt][3] * alpha;
            *(float2*)(Cptr + (size_t)(r0 + 8) * N + cc) = v;
        }
    }
}

// ---------------- split kernels (write permuted k layout) ----------------
__global__ void split_plain(const float* __restrict__ src, __half* dst,
                            long plane, int n) {
    int idx = blockIdx.x * 256 + threadIdx.x;
    if (idx < n) split2(src[idx], dst, (size_t)(idx & ~31), idx & 31, plane);
}

// fused 7-weight concat + transpose + split: out planes [4096][1024]
__global__ void splitT_w7(const float* __restrict__ Wq,  const float* __restrict__ Wck,
                          const float* __restrict__ Wcv, const float* __restrict__ Wcg,
                          const float* __restrict__ Wiq, const float* __restrict__ Wik,
                          const float* __restrict__ Wig, __half* out) {
    __shared__ float tile[32][33];
    int k0 = blockIdx.x * 32, n0 = blockIdx.y * 32;
    int tx = threadIdx.x, ty = threadIdx.y;
    {
        int k = k0 + ty, n = n0 + tx;
        float v;
        if      (n < 1024) v = Wq [k * 1024 + n];
        else if (n < 1536) v = Wck[k * 512 + n - 1024];
        else if (n < 2048) v = Wcv[k * 512 + n - 1536];
        else if (n < 2560) v = Wcg[k * 512 + n - 2048];
        else if (n < 3072) v = Wiq[k * 512 + n - 2560];
        else if (n < 3584) v = Wik[k * 512 + n - 3072];
        else               v = Wig[k * 512 + n - 3584];
        tile[ty][tx] = v;
    }
    __syncthreads();
    int n = n0 + ty, k = k0 + tx;
    split2(tile[tx][ty], out, (size_t)n * 1024 + (k & ~31), k & 31, PL_WT);
}

// generic transpose+split: src [Kd][Nd] -> out planes [Nd][Kd]
__global__ void splitT_gen(const float* __restrict__ src, __half* out,
                           int Kd, int Nd, long plane) {
    __shared__ float tile[32][33];
    int k0 = blockIdx.x * 32, n0 = blockIdx.y * 32;
    int tx = threadIdx.x, ty = threadIdx.y;
    tile[ty][tx] = src[(size_t)(k0 + ty) * Nd + n0 + tx];
    __syncthreads();
    int n = n0 + ty, k = k0 + tx;
    split2(tile[tx][ty], out, (size_t)n * Kd + (k & ~31), k & 31, plane);
}

// ---------------- rope helper ----------------
__device__ __forceinline__ void rope_cs(int i, float pos, float& c, float& s) {
    float f = powf(160000.0f, (float)i * (1.0f / 32.0f));
    float ang = pos / f;
    sincosf(ang, &s, &c);
}

// ---------------- gated compress (coarse KV) + rope on ck ---------------- grid Bb*Gg*HKV, block 128
__global__ void compress_c(const float* __restrict__ ape) {
    int blk = blockIdx.x;
    int h = blk & 3;
    int bg = blk >> 2;
    int g = bg & (Gg - 1);
    int d = threadIdx.x;
    size_t base = (size_t)bg * 4 * NCOL + h * 128 + d;
    float gv[4], m = -1e30f;
    #pragma unroll
    for (int r = 0; r < 4; r++) {
        gv[r] = g_Pall[base + (size_t)r * NCOL + OFF_CG] + ape[(r * HKV + h) * 128 + d];
        m = fmaxf(m, gv[r]);
    }
    float ssum = 0.f;
    #pragma unroll
    for (int r = 0; r < 4; r++) { gv[r] = expf(gv[r] - m); ssum += gv[r]; }
    float inv = 1.f / ssum;
    float ka = 0.f, va = 0.f;
    #pragma unroll
    for (int r = 0; r < 4; r++) {
        float w = gv[r] * inv;
        ka += w * g_Pall[base + (size_t)r * NCOL + OFF_CK];
        va += w * g_Pall[base + (size_t)r * NCOL + OFF_CV];
    }
    __shared__ float sk[128];
    sk[d] = ka;
    __syncthreads();
    float pos = (float)(4 * g + 3);
    float outk = ka;
    if (d >= 64 && d < 96) {
        int i = d - 64; float c, s; rope_cs(i, pos, c, s);
        outk = sk[d] * c - sk[d + 32] * s;
    } else if (d >= 96) {
        int i = d - 96; float c, s; rope_cs(i, pos, c, s);
        outk = sk[d - 32] * s + sk[d] * c;
    }
    size_t ob = ((size_t)bg * 4 + h) * 128 + d;
    g_ck[ob] = outk;
    g_cv[ob] = va;
}

// ---------------- gated compress (index KV) + rmsnorm -> ik splits ---------------- grid Bb*Gg*HIi, block 64
__global__ void compress_i(const float* __restrict__ ape) {
    int blk = blockIdx.x;
    int h = blk & 7;
    int bg = blk >> 3;
    int d = threadIdx.x;
    size_t base = (size_t)bg * 4 * NCOL + h * 64 + d;
    float gv[4], m = -1e30f;
    #pragma unroll
    for (int r = 0; r < 4; r++) {
        gv[r] = g_Pall[base + (size_t)r * NCOL + OFF_IG] + ape[(r * HIi + h) * 64 + d];
        m = fmaxf(m, gv[r]);
    }
    float ssum = 0.f;
    #pragma unroll
    for (int r = 0; r < 4; r++) { gv[r] = expf(gv[r] - m); ssum += gv[r]; }
    float inv = 1.f / ssum;
    float ka = 0.f;
    #pragma unroll
    for (int r = 0; r < 4; r++)
        ka += gv[r] * inv * g_Pall[base + (size_t)r * NCOL + OFF_IK];
    __shared__ float red[64];
    red[d] = ka * ka;
    __syncthreads();
    #pragma unroll
    for (int s2 = 32; s2 > 0; s2 >>= 1) {
        if (d < s2) red[d] += red[d + s2];
        __syncthreads();
    }
    float sc = rsqrtf(red[0] / 64.f + 1e-6f);
    // k index within row = h*64 + d (aligned base h*64+ (d&~31))
    split2(ka * sc, g_iks, (size_t)bg * 512 + h * 64 + (d & ~31), d & 31, PL_IK);
}

// ---------------- per-head rmsnorm of iq -> iq splits ---------------- grid NTOK*HIi, block 64
__global__ void iq_rms() {
    int blk = blockIdx.x;
    int h = blk & 7;
    int row = blk >> 3;
    int d = threadIdx.x;
    float v = g_Pall[(size_t)row * NCOL + OFF_IQ + h * 64 + d];
    __shared__ float red[64];
    red[d] = v * v;
    __syncthreads();
    #pragma unroll
    for (int s2 = 32; s2 > 0; s2 >>= 1) {
        if (d < s2) red[d] += red[d + s2];
        __syncthreads();
    }
    float sc = rsqrtf(red[0] / 64.f + 1e-6f);
    split2(v * sc, g_iqs, (size_t)row * 512 + h * 64 + (d & ~31), d & 31, PL_IQ);
}

// ---------------- in-place partial rope of q ---------------- grid NTOK*Hh, block 32
__global__ void q_rope() {
    int blk = blockIdx.x;
    int h = blk & 7;
    int row = blk >> 3;
    int t = row & (Tt - 1);
    int i = threadIdx.x;
    size_t base = (size_t)row * NCOL + OFF_Q + h * 128;
    float x1 = g_Pall[base + 64 + i];
    float x2 = g_Pall[base + 96 + i];
    float c, s; rope_cs(i, (float)t, c, s);
    g_Pall[base + 64 + i] = x1 * c - x2 * s;
    g_Pall[base + 96 + i] = x1 * s + x2 * c;
}

// ---------------- top-k(64) threshold via bitonic sort ---------------- grid NTOK, block 512
__global__ void topk_thresh() {
    __shared__ float s[512];
    int row = blockIdx.x;
    int t = row & (Tt - 1);
    int tid = threadIdx.x;
    float v = g_isc[(size_t)row * Gg + tid];
    if (4 * tid + 3 > t) v = NEGv;
    s[tid] = v;
    __syncthreads();
    for (int k = 2; k <= 512; k <<= 1) {
        for (int j = k >> 1; j > 0; j >>= 1) {
            int ixj = tid ^ j;
            if (ixj > tid) {
                float a = s[tid], b = s[ixj];
                bool down = ((tid & k) == 0);
                bool sw = down ? (a < b) : (a > b);
                if (sw) { s[tid] = b; s[ixj] = a; }
            }
            __syncthreads();
        }
    }
    if (tid == 0) g_thr[row] = s[63];
}

// ---------------- sparse attention -> at splits ---------------- grid NTOK*Hh, block 128
__global__ void attn_kernel() {
    int blk = blockIdx.x;
    int h = blk & 7;
    int row = blk >> 3;
    int t = row & (Tt - 1);
    int b = row >> 11;
    int tid = threadIdx.x;
    __shared__ int sg[96];
    __shared__ float sw[96];
    __shared__ int cnt;
    __shared__ alignas(16) float qsh[128];
    if (tid == 0) cnt = 0;
    __syncthreads();

    int nc = (t >= 3) ? (((t - 3) >> 2) + 1) : 0;
    float th = g_thr[row];
    const float* iscr = g_isc + (size_t)row * Gg;
    for (int g = tid; g < nc; g += 128) {
        if (iscr[g] >= th) {
            int p = atomicAdd(&cnt, 1);
            if (p < 96) sg[p] = g;
        }
    }
    qsh[tid] = g_Pall[(size_t)row * NCOL + OFF_Q + h * 128 + tid];
    __syncthreads();
    int n = min(cnt, 96);
    int hkv = h >> 1;
    int warp = tid >> 5, lane = tid & 31;
    for (int i = warp; i < n; i += 4) {
        const float* kp = g_ck + ((size_t)(b * Gg + sg[i]) * 4 + hkv) * 128;
        float4 kv = *(const float4*)(kp + lane * 4);
        float4 qv = *(const float4*)(qsh + lane * 4);
        float p = qv.x * kv.x + qv.y * kv.y + qv.z * kv.z + qv.w * kv.w;
        #pragma unroll
        for (int o = 16; o > 0; o >>= 1) p += __shfl_xor_sync(0xffffffffu, p, o);
        if (lane == 0) sw[i] = p * 0.0883883476483184f;
    }
    __syncthreads();
    if (tid == 0 && n > 0) {
        float m = -1e30f;
        for (int i = 0; i < n; i++) m = fmaxf(m, sw[i]);
        float ssum = 0.f;
        for (int i = 0; i < n; i++) { float e = expf(sw[i] - m); sw[i] = e; ssum += e; }
        float inv = 1.f / ssum;
        for (int i = 0; i < n; i++) sw[i] *= inv;
    }
    __syncthreads();
    float acc = 0.f;
    for (int i = 0; i < n; i++)
        acc += sw[i] * g_cv[((size_t)(b * Gg + sg[i]) * 4 + hkv) * 128 + tid];
    split2(acc, g_ats, (size_t)row * 1024 + h * 128 + (tid & ~31), tid & 31, PL_AT);
}

// ---------------- rmsnorm over RANK=512 -> rn splits ---------------- grid NTOK, block 256
__global__ void rmsnorm512() {
    int row = blockIdx.x;
    int tid = threadIdx.x;
    size_t base = (size_t)row * 512;
    float a = g_r[base + tid], b = g_r[base + 256 + tid];
    __shared__ float red[256];
    red[tid] = a * a + b * b;
    __syncthreads();
    #pragma unroll
    for (int s2 = 128; s2 > 0; s2 >>= 1) {
        if (tid < s2) red[tid] += red[tid + s2];
        __syncthreads();
    }
    float sc = rsqrtf(red[0] / 512.f + 1e-6f);
    split2(a * sc, g_rns, base + (tid & ~31), tid & 31, PL_RN);
    split2(b * sc, g_rns, base + 256 + (tid & ~31), tid & 31, PL_RN);
}

// ---------------- launch ----------------
extern "C" void kernel_launch(void* const* d_in, const int* in_sizes, int n_in,
                              void* d_out, int out_size) {
    const float* x     = (const float*)d_in[0];
    const float* Wq    = (const float*)d_in[1];
    const float* Wck   = (const float*)d_in[2];
    const float* Wcv   = (const float*)d_in[3];
    const float* Wcg   = (const float*)d_in[4];
    const float* ape_c = (const float*)d_in[5];
    const float* Wiq   = (const float*)d_in[6];
    const float* Wik   = (const float*)d_in[7];
    const float* Wig   = (const float*)d_in[8];
    const float* ape_i = (const float*)d_in[9];
    const float* Wa    = (const float*)d_in[10];
    const float* Wb    = (const float*)d_in[11];
    float* out = (float*)d_out;

    __half *xs, *WTs, *iks, *iqs, *ats, *Was, *rns, *Wbs;
    float *Pall, *isc, *r;
    cudaGetSymbolAddress((void**)&xs,   g_xs);
    cudaGetSymbolAddress((void**)&WTs,  g_WTs);
    cudaGetSymbolAddress((void**)&Pall, g_Pall);
    cudaGetSymbolAddress((void**)&iks,  g_iks);
    cudaGetSymbolAddress((void**)&iqs,  g_iqs);
    cudaGetSymbolAddress((void**)&isc,  g_isc);
    cudaGetSymbolAddress((void**)&ats,  g_ats);
    cudaGetSymbolAddress((void**)&Was,  g_Was);
    cudaGetSymbolAddress((void**)&r,    g_r);
    cudaGetSymbolAddress((void**)&rns,  g_rns);
    cudaGetSymbolAddress((void**)&Wbs,  g_Wbs);

    static int attr_set = 0;
    if (!attr_set) {
        cudaFuncSetAttribute(mma_gemm_hx, cudaFuncAttributeMaxDynamicSharedMemorySize, HSMEM);
        attr_set = 1;
    }

    // operand splits
    split_plain<<<(NTOK * 1024) / 256, 256>>>(x, xs, PL_X, NTOK * 1024);
    splitT_w7<<<dim3(1024 / 32, NCOL / 32), dim3(32, 32)>>>(Wq, Wck, Wcv, Wcg, Wiq, Wik, Wig, WTs);
    split_plain<<<(512 * 1024) / 256, 256>>>(Wa, Was, PL_WA, 512 * 1024);
    splitT_gen<<<dim3(512 / 32, 1024 / 32), dim3(32, 32)>>>(Wb, Wbs, 512, 1024, PL_WB);

    // fused projection GEMM: Pall = x @ W  (8192 x 4096 x 1024)
    mma_gemm_hx<<<dim3(NCOL / 128, NTOK / 128, 1), 256, HSMEM>>>(
        NTOK, NCOL, 1024, 1.f, xs, PL_X, 0, WTs, PL_WT, 0, Pall, 0);

    // compress + norms + rope
    compress_c<<<Bb * Gg * HKV, 128>>>(ape_c);
    compress_i<<<Bb * Gg * HIi, 64>>>(ape_i);
    iq_rms<<<NTOK * HIi, 64>>>();
    q_rope<<<NTOK * Hh, 32>>>();

    // index scores: batched, alpha = DI^-0.5 / HI = 1/64
    mma_gemm_hx<<<dim3(512 / 128, 2048 / 128, Bb), 256, HSMEM>>>(
        2048, 512, 512, 1.f / 64.f,
        iqs, PL_IQ, (long)2048 * 512,
        iks, PL_IK, (long)512 * 512,
        isc, (long)2048 * 512);

    topk_thresh<<<NTOK, 512>>>();
    attn_kernel<<<NTOK * Hh, 128>>>();

    // r = attn @ Wa^T  (8192 x 512 x 1024)
    mma_gemm_hx<<<dim3(512 / 128, NTOK / 128, 1), 256, HSMEM>>>(
        NTOK, 512, 1024, 1.f, ats, PL_AT, 0, Was, PL_WA, 0, r, 0);

    rmsnorm512<<<NTOK, 256>>>();

    // out = rn @ Wb  (8192 x 1024 x 512)
    mma_gemm_hx<<<dim3(1024 / 128, NTOK / 128, 1), 256, HSMEM>>>(
        NTOK, 1024, 512, 1.f, rns, PL_RN, 0, Wbs, PL_WB, 0, out, 0);
}

// round 12
// speedup vs baseline: 2.3862x; 1.0442x over previous
#include <cuda_runtime.h>
#include <cuda_fp16.h>
#include <math.h>
#include <stdint.h>

// Problem constants
#define Bb 4
#define Tt 2048
#define Cc 1024
#define Hh 8
#define HKV 4
#define Dd 128
#define Gg 512
#define HIi 8
#define DIi 64
#define NEGv (-1e30f)

#define NTOK (Bb*Tt)   // 8192
#define NCOL 4096      // fused projection width: q|ck|cv|cg | ig|iq|ik
#define OFF_Q  0
#define OFF_CK 1024
#define OFF_CV 1536
#define OFF_CG 2048
#define OFF_IG 2560
#define OFF_IQ 3072
#define OFF_IK 3584
#define SPLIT_COL 2560   // [0,2560) 2-term ; [2560,4096) 3-term (selection chain)

// plane strides (elements)
#define PL_X   ((long)NTOK*1024)
#define PL_WT  ((long)NCOL*1024)
#define PL_IQ  ((long)NTOK*512)
#define PL_IK  ((long)Bb*512*512)
#define PL_AT  ((long)NTOK*1024)
#define PL_WA  ((long)512*1024)
#define PL_RN  ((long)NTOK*512)
#define PL_WB  ((long)1024*512)

// ---------------- scratch (static device allocations) ----------------
__device__ alignas(256) __half g_xs [2*PL_X];
__device__ alignas(256) __half g_WTs[2*PL_WT];
__device__ alignas(256) float g_Pall[(size_t)NTOK*NCOL];
__device__ alignas(256) float g_ck [Bb*Gg*HKV*Dd];
__device__ alignas(256) float g_cv [Bb*Gg*HKV*Dd];
__device__ alignas(256) __half g_iks[2*PL_IK];
__device__ alignas(256) __half g_iqs[2*PL_IQ];
__device__ alignas(256) float g_isc[NTOK*Gg];
__device__ alignas(256) float g_thr[NTOK];
__device__ alignas(256) __half g_ats[2*PL_AT];
__device__ alignas(256) __half g_Was[2*PL_WA];
__device__ alignas(256) float g_r  [NTOK*512];
__device__ alignas(256) __half g_rns[2*PL_RN];
__device__ alignas(256) __half g_Wbs[2*PL_WB];

// ---------------- helpers ----------------
__device__ __forceinline__ void cpa16(uint32_t dst, const void* src) {
    asm volatile("cp.async.cg.shared.global [%0], [%1], 16;\n" :: "r"(dst), "l"(src));
}
__device__ __forceinline__ void cp_commit() {
    asm volatile("cp.async.commit_group;\n");
}
// k-permutation within a 32-element group: u32 j -> ((j&3)<<2)|(j>>2)
__device__ __forceinline__ int permk(int idx) {
    int kk = idx & 31;
    int j = kk >> 1;
    int jn = ((j & 3) << 2) | (j >> 2);
    return (idx & ~31) | (jn << 1) | (kk & 1);
}
// fp16 2-way split with permuted k index
__device__ __forceinline__ void split2(float v, __half* p, size_t base, int kidx, long plane) {
    __half h0 = __float2half_rn(v);
    float r1 = v - __half2float(h0);
    size_t idx = base + (size_t)permk(kidx);
    p[idx]         = h0;
    p[idx + plane] = __float2half_rn(r1);
}
__device__ __forceinline__ void mma_f16(float* c,
    uint32_t a0, uint32_t a1, uint32_t a2, uint32_t a3,
    uint32_t b0, uint32_t b1) {
    asm volatile(
        "mma.sync.aligned.m16n8k16.row.col.f32.f16.f16.f32 "
        "{%0,%1,%2,%3},{%4,%5,%6,%7},{%8,%9},{%0,%1,%2,%3};"
        : "+f"(c[0]), "+f"(c[1]), "+f"(c[2]), "+f"(c[3])
        : "r"(a0), "r"(a1), "r"(a2), "r"(a3), "r"(b0), "r"(b1));
}
__device__ __forceinline__ uint4 lds128(uint32_t addr) {
    uint4 v;
    asm volatile("ld.shared.v4.u32 {%0,%1,%2,%3}, [%4];"
                 : "=r"(v.x), "=r"(v.y), "=r"(v.z), "=r"(v.w) : "r"(addr));
    return v;
}

// ---------------- fp16 split MMA GEMM: C = alpha * A[M,K] @ B[N,K]^T ----------------
// NT=3: a0b0+a0b1+a1b0 (fp32-accurate ~2^-24). NT=2: a0b0+a0b1 (~2e-4 rel).
// A, B as 2 fp16 split planes (NT=2 reads only A plane0), k-permuted per 32-group.
// BM=BN=128, BK=32, 256 threads (8 warps 2x4), warp tile 64x32. ldc = C row stride.
#define HPLANE 2048          // 128 rows * 16 u32
#define HBUF   4096          // 2 planes
#define HTOT   8192          // A + B per buffer
#define HSMEM  (2 * HTOT * 4)  // 65536 bytes

template<int NT>
__global__ void __launch_bounds__(256, 2) mma_gemm_hx(
    int M, int N, int K, int ldc, float alpha,
    const __half* __restrict__ A0, long planeA, long batA,
    const __half* __restrict__ B0, long planeB, long batB,
    float* __restrict__ C, long batC) {
    extern __shared__ char smraw[];
    uint32_t sbase = (uint32_t)__cvta_generic_to_shared(smraw);

    const int tid  = threadIdx.x;
    const int wid  = tid >> 5;
    const int lane = tid & 31;
    const int lm   = lane >> 2;     // 0..7
    const int lk   = lane & 3;      // 0..3
    const int warp_m = (wid & 1) * 64;
    const int warp_n = (wid >> 1) * 32;
    const int bm = blockIdx.y * 128;
    const int bn = blockIdx.x * 128;
    const int z  = blockIdx.z;

    const __half* Abase = A0 + (size_t)z * batA;
    const __half* Bbase = B0 + (size_t)z * batB;
    float* Cptr = C + (size_t)z * batC + (size_t)(bm + warp_m) * ldc + bn + warp_n;

    float c[4][4][4];
    #pragma unroll
    for (int mt = 0; mt < 4; mt++)
        #pragma unroll
        for (int nt = 0; nt < 4; nt++)
            #pragma unroll
            for (int i = 0; i < 4; i++) c[mt][nt][i] = 0.f;

    const int nIter = K >> 5;

    auto stage = [&](int it, int buf) {
        const int k0 = it * 32;
        const uint32_t abase = sbase + (uint32_t)(buf * HTOT) * 4u;
        const uint32_t bbase = abase + HBUF * 4u;
        // A: NT==2 stages only plane0 (2 iters); NT==3 both planes (4 iters)
        #pragma unroll
        for (int i = 0; i < (NT == 2 ? 2 : 4); i++) {
            int id = tid + i * 256;
            int p = id >> 9, rem = id & 511, row = rem >> 2, cc = rem & 3;
            cpa16(abase + (uint32_t)(p * HPLANE + row * 16 + cc * 4) * 4u,
                  Abase + (size_t)p * planeA + (size_t)(bm + row) * K + k0 + cc * 8);
        }
        #pragma unroll
        for (int i = 0; i < 4; i++) {
            int id = tid + i * 256;
            int p = id >> 9, rem = id & 511, row = rem >> 2, cc = rem & 3;
            cpa16(bbase + (uint32_t)(p * HPLANE + row * 16 + cc * 4) * 4u,
                  Bbase + (size_t)p * planeB + (size_t)(bn + row) * K + k0 + cc * 8);
        }
        cp_commit();
    };

    stage(0, 0);

    for (int it = 0; it < nIter; it++) {
        const int buf = it & 1;
        if (it + 1 < nIter) {
            stage(it + 1, buf ^ 1);
            asm volatile("cp.async.wait_group 1;\n" ::: "memory");
        } else {
            asm volatile("cp.async.wait_group 0;\n" ::: "memory");
        }
        __syncthreads();

        const uint32_t abufb = sbase + (uint32_t)(buf * HTOT) * 4u;
        const uint32_t bbufb = abufb + HBUF * 4u;

        // B fragments: one LDS.128 per (nt, plane) covers both k16 slices.
        uint4 b0f[4], b1f[4];
        #pragma unroll
        for (int nt = 0; nt < 4; nt++) {
            uint32_t baddr = bbufb + (uint32_t)(warp_n + nt * 8 + lm) * 64u + lk * 16u;
            b0f[nt] = lds128(baddr);
            b1f[nt] = lds128(baddr + HPLANE * 4u);
        }

        #pragma unroll
        for (int mt = 0; mt < 4; mt++) {
            const uint32_t aaddr = abufb + (uint32_t)(warp_m + mt * 16 + lm) * 64u + lk * 16u;
            uint4 alo0 = lds128(aaddr);
            uint4 ahi0 = lds128(aaddr + 8u * 64u);
            // kc0
            #pragma unroll
            for (int nt = 0; nt < 4; nt++)
                mma_f16(c[mt][nt], alo0.x, ahi0.x, alo0.y, ahi0.y, b0f[nt].x, b0f[nt].y);
            #pragma unroll
            for (int nt = 0; nt < 4; nt++)
                mma_f16(c[mt][nt], alo0.x, ahi0.x, alo0.y, ahi0.y, b1f[nt].x, b1f[nt].y);
            // kc1
            #pragma unroll
            for (int nt = 0; nt < 4; nt++)
                mma_f16(c[mt][nt], alo0.z, ahi0.z, alo0.w, ahi0.w, b0f[nt].z, b0f[nt].w);
            #pragma unroll
            for (int nt = 0; nt < 4; nt++)
                mma_f16(c[mt][nt], alo0.z, ahi0.z, alo0.w, ahi0.w, b1f[nt].z, b1f[nt].w);
            if (NT == 3) {
                uint4 alo1 = lds128(aaddr + HPLANE * 4u);
                uint4 ahi1 = lds128(aaddr + HPLANE * 4u + 8u * 64u);
                #pragma unroll
                for (int nt = 0; nt < 4; nt++)
                    mma_f16(c[mt][nt], alo1.x, ahi1.x, alo1.y, ahi1.y, b0f[nt].x, b0f[nt].y);
                #pragma unroll
                for (int nt = 0; nt < 4; nt++)
                    mma_f16(c[mt][nt], alo1.z, ahi1.z, alo1.w, ahi1.w, b0f[nt].z, b0f[nt].w);
            }
        }
        __syncthreads();
    }

    #pragma unroll
    for (int mt = 0; mt < 4; mt++) {
        #pragma unroll
        for (int nt = 0; nt < 4; nt++) {
            int r0 = mt * 16 + lm;
            int cc = nt * 8 + 2 * lk;
            float2 v;
            v.x = c[mt][nt][0] * alpha; v.y = c[mt][nt][1] * alpha;
            *(float2*)(Cptr + (size_t)r0 * ldc + cc) = v;
            v.x = c[mt][nt][2] * alpha; v.y = c[mt][nt][3] * alpha;
            *(float2*)(Cptr + (size_t)(r0 + 8) * ldc + cc) = v;
        }
    }
}

// ---------------- split kernels (write permuted k layout) ----------------
__global__ void split_plain(const float* __restrict__ src, __half* dst,
                            long plane, int n) {
    int idx = blockIdx.x * 256 + threadIdx.x;
    if (idx < n) split2(src[idx], dst, (size_t)(idx & ~31), idx & 31, plane);
}

// fused 7-weight concat + transpose + split: out planes [4096][1024]
// column order: q | ck | cv | cg | ig | iq | ik
__global__ void splitT_w7(const float* __restrict__ Wq,  const float* __restrict__ Wck,
                          const float* __restrict__ Wcv, const float* __restrict__ Wcg,
                          const float* __restrict__ Wig, const float* __restrict__ Wiq,
                          const float* __restrict__ Wik, __half* out) {
    __shared__ float tile[32][33];
    int k0 = blockIdx.x * 32, n0 = blockIdx.y * 32;
    int tx = threadIdx.x, ty = threadIdx.y;
    {
        int k = k0 + ty, n = n0 + tx;
        float v;
        if      (n < 1024) v = Wq [k * 1024 + n];
        else if (n < 1536) v = Wck[k * 512 + n - 1024];
        else if (n < 2048) v = Wcv[k * 512 + n - 1536];
        else if (n < 2560) v = Wcg[k * 512 + n - 2048];
        else if (n < 3072) v = Wig[k * 512 + n - 2560];
        else if (n < 3584) v = Wiq[k * 512 + n - 3072];
        else               v = Wik[k * 512 + n - 3584];
        tile[ty][tx] = v;
    }
    __syncthreads();
    int n = n0 + ty, k = k0 + tx;
    split2(tile[tx][ty], out, (size_t)n * 1024 + (k & ~31), k & 31, PL_WT);
}

// generic transpose+split: src [Kd][Nd] -> out planes [Nd][Kd]
__global__ void splitT_gen(const float* __restrict__ src, __half* out,
                           int Kd, int Nd, long plane) {
    __shared__ float tile[32][33];
    int k0 = blockIdx.x * 32, n0 = blockIdx.y * 32;
    int tx = threadIdx.x, ty = threadIdx.y;
    tile[ty][tx] = src[(size_t)(k0 + ty) * Nd + n0 + tx];
    __syncthreads();
    int n = n0 + ty, k = k0 + tx;
    split2(tile[tx][ty], out, (size_t)n * Kd + (k & ~31), k & 31, plane);
}

// ---------------- rope helper ----------------
__device__ __forceinline__ void rope_cs(int i, float pos, float& c, float& s) {
    float f = powf(160000.0f, (float)i * (1.0f / 32.0f));
    float ang = pos / f;
    sincosf(ang, &s, &c);
}

// ---------------- gated compress (coarse KV) + rope on ck ---------------- grid Bb*Gg*HKV, block 128
__global__ void compress_c(const float* __restrict__ ape) {
    int blk = blockIdx.x;
    int h = blk & 3;
    int bg = blk >> 2;
    int g = bg & (Gg - 1);
    int d = threadIdx.x;
    size_t base = (size_t)bg * 4 * NCOL + h * 128 + d;
    float gv[4], m = -1e30f;
    #pragma unroll
    for (int r = 0; r < 4; r++) {
        gv[r] = g_Pall[base + (size_t)r * NCOL + OFF_CG] + ape[(r * HKV + h) * 128 + d];
        m = fmaxf(m, gv[r]);
    }
    float ssum = 0.f;
    #pragma unroll
    for (int r = 0; r < 4; r++) { gv[r] = expf(gv[r] - m); ssum += gv[r]; }
    float inv = 1.f / ssum;
    float ka = 0.f, va = 0.f;
    #pragma unroll
    for (int r = 0; r < 4; r++) {
        float w = gv[r] * inv;
        ka += w * g_Pall[base + (size_t)r * NCOL + OFF_CK];
        va += w * g_Pall[base + (size_t)r * NCOL + OFF_CV];
    }
    __shared__ float sk[128];
    sk[d] = ka;
    __syncthreads();
    float pos = (float)(4 * g + 3);
    float outk = ka;
    if (d >= 64 && d < 96) {
        int i = d - 64; float c, s; rope_cs(i, pos, c, s);
        outk = sk[d] * c - sk[d + 32] * s;
    } else if (d >= 96) {
        int i = d - 96; float c, s; rope_cs(i, pos, c, s);
        outk = sk[d - 32] * s + sk[d] * c;
    }
    size_t ob = ((size_t)bg * 4 + h) * 128 + d;
    g_ck[ob] = outk;
    g_cv[ob] = va;
}

// ---------------- gated compress (index KV) + rmsnorm -> ik splits ---------------- grid Bb*Gg*HIi, block 64
__global__ void compress_i(const float* __restrict__ ape) {
    int blk = blockIdx.x;
    int h = blk & 7;
    int bg = blk >> 3;
    int d = threadIdx.x;
    size_t base = (size_t)bg * 4 * NCOL + h * 64 + d;
    float gv[4], m = -1e30f;
    #pragma unroll
    for (int r = 0; r < 4; r++) {
        gv[r] = g_Pall[base + (size_t)r * NCOL + OFF_IG] + ape[(r * HIi + h) * 64 + d];
        m = fmaxf(m, gv[r]);
    }
    float ssum = 0.f;
    #pragma unroll
    for (int r = 0; r < 4; r++) { gv[r] = expf(gv[r] - m); ssum += gv[r]; }
    float inv = 1.f / ssum;
    float ka = 0.f;
    #pragma unroll
    for (int r = 0; r < 4; r++)
        ka += gv[r] * inv * g_Pall[base + (size_t)r * NCOL + OFF_IK];
    __shared__ float red[64];
    red[d] = ka * ka;
    __syncthreads();
    #pragma unroll
    for (int s2 = 32; s2 > 0; s2 >>= 1) {
        if (d < s2) red[d] += red[d + s2];
        __syncthreads();
    }
    float sc = rsqrtf(red[0] / 64.f + 1e-6f);
    split2(ka * sc, g_iks, (size_t)bg * 512 + h * 64 + (d & ~31), d & 31, PL_IK);
}

// ---------------- per-head rmsnorm of iq -> iq splits ---------------- grid NTOK*HIi, block 64
__global__ void iq_rms() {
    int blk = blockIdx.x;
    int h = blk & 7;
    int row = blk >> 3;
    int d = threadIdx.x;
    float v = g_Pall[(size_t)row * NCOL + OFF_IQ + h * 64 + d];
    __shared__ float red[64];
    red[d] = v * v;
    __syncthreads();
    #pragma unroll
    for (int s2 = 32; s2 > 0; s2 >>= 1) {
        if (d < s2) red[d] += red[d + s2];
        __syncthreads();
    }
    float sc = rsqrtf(red[0] / 64.f + 1e-6f);
    split2(v * sc, g_iqs, (size_t)row * 512 + h * 64 + (d & ~31), d & 31, PL_IQ);
}

// ---------------- in-place partial rope of q ---------------- grid NTOK*Hh, block 32
__global__ void q_rope() {
    int blk = blockIdx.x;
    int h = blk & 7;
    int row = blk >> 3;
    int t = row & (Tt - 1);
    int i = threadIdx.x;
    size_t base = (size_t)row * NCOL + OFF_Q + h * 128;
    float x1 = g_Pall[base + 64 + i];
    float x2 = g_Pall[base + 96 + i];
    float c, s; rope_cs(i, (float)t, c, s);
    g_Pall[base + 64 + i] = x1 * c - x2 * s;
    g_Pall[base + 96 + i] = x1 * s + x2 * c;
}

// ---------------- top-k(64) threshold via bitonic sort ---------------- grid NTOK, block 512
__global__ void topk_thresh() {
    __shared__ float s[512];
    int row = blockIdx.x;
    int t = row & (Tt - 1);
    int tid = threadIdx.x;
    float v = g_isc[(size_t)row * Gg + tid];
    if (4 * tid + 3 > t) v = NEGv;
    s[tid] = v;
    __syncthreads();
    for (int k = 2; k <= 512; k <<= 1) {
        for (int j = k >> 1; j > 0; j >>= 1) {
            int ixj = tid ^ j;
            if (ixj > tid) {
                float a = s[tid], b = s[ixj];
                bool down = ((tid & k) == 0);
                bool sw = down ? (a < b) : (a > b);
                if (sw) { s[tid] = b; s[ixj] = a; }
            }
            __syncthreads();
        }
    }
    if (tid == 0) g_thr[row] = s[63];
}

// ---------------- sparse attention -> at splits ---------------- grid NTOK*Hh, block 128
__global__ void attn_kernel() {
    int blk = blockIdx.x;
    int h = blk & 7;
    int row = blk >> 3;
    int t = row & (Tt - 1);
    int b = row >> 11;
    int tid = threadIdx.x;
    __shared__ int sg[96];
    __shared__ float sw[96];
    __shared__ int cnt;
    __shared__ alignas(16) float qsh[128];
    if (tid == 0) cnt = 0;
    __syncthreads();

    int nc = (t >= 3) ? (((t - 3) >> 2) + 1) : 0;
    float th = g_thr[row];
    const float* iscr = g_isc + (size_t)row * Gg;
    for (int g = tid; g < nc; g += 128) {
        if (iscr[g] >= th) {
            int p = atomicAdd(&cnt, 1);
            if (p < 96) sg[p] = g;
        }
    }
    qsh[tid] = g_Pall[(size_t)row * NCOL + OFF_Q + h * 128 + tid];
    __syncthreads();
    int n = min(cnt, 96);
    int hkv = h >> 1;
    int warp = tid >> 5, lane = tid & 31;
    for (int i = warp; i < n; i += 4) {
        const float* kp = g_ck + ((size_t)(b * Gg + sg[i]) * 4 + hkv) * 128;
        float4 kv = *(const float4*)(kp + lane * 4);
        float4 qv = *(const float4*)(qsh + lane * 4);
        float p = qv.x * kv.x + qv.y * kv.y + qv.z * kv.z + qv.w * kv.w;
        #pragma unroll
        for (int o = 16; o > 0; o >>= 1) p += __shfl_xor_sync(0xffffffffu, p, o);
        if (lane == 0) sw[i] = p * 0.0883883476483184f;
    }
    __syncthreads();
    if (tid == 0 && n > 0) {
        float m = -1e30f;
        for (int i = 0; i < n; i++) m = fmaxf(m, sw[i]);
        float ssum = 0.f;
        for (int i = 0; i < n; i++) { float e = expf(sw[i] - m); sw[i] = e; ssum += e; }
        float inv = 1.f / ssum;
        for (int i = 0; i < n; i++) sw[i] *= inv;
    }
    __syncthreads();
    float acc = 0.f;
    for (int i = 0; i < n; i++)
        acc += sw[i] * g_cv[((size_t)(b * Gg + sg[i]) * 4 + hkv) * 128 + tid];
    split2(acc, g_ats, (size_t)row * 1024 + h * 128 + (tid & ~31), tid & 31, PL_AT);
}

// ---------------- rmsnorm over RANK=512 -> rn splits ---------------- grid NTOK, block 256
__global__ void rmsnorm512() {
    int row = blockIdx.x;
    int tid = threadIdx.x;
    size_t base = (size_t)row * 512;
    float a = g_r[base + tid], b = g_r[base + 256 + tid];
    __shared__ float red[256];
    red[tid] = a * a + b * b;
    __syncthreads();
    #pragma unroll
    for (int s2 = 128; s2 > 0; s2 >>= 1) {
        if (tid < s2) red[tid] += red[tid + s2];
        __syncthreads();
    }
    float sc = rsqrtf(red[0] / 512.f + 1e-6f);
    split2(a * sc, g_rns, base + (tid & ~31), tid & 31, PL_RN);
    split2(b * sc, g_rns, base + 256 + (tid & ~31), tid & 31, PL_RN);
}

// ---------------- launch ----------------
extern "C" void kernel_launch(void* const* d_in, const int* in_sizes, int n_in,
                              void* d_out, int out_size) {
    const float* x     = (const float*)d_in[0];
    const float* Wq    = (const float*)d_in[1];
    const float* Wck   = (const float*)d_in[2];
    const float* Wcv   = (const float*)d_in[3];
    const float* Wcg   = (const float*)d_in[4];
    const float* ape_c = (const float*)d_in[5];
    const float* Wiq   = (const float*)d_in[6];
    const float* Wik   = (const float*)d_in[7];
    const float* Wig   = (const float*)d_in[8];
    const float* ape_i = (const float*)d_in[9];
    const float* Wa    = (const float*)d_in[10];
    const float* Wb    = (const float*)d_in[11];
    float* out = (float*)d_out;

    __half *xs, *WTs, *iks, *iqs, *ats, *Was, *rns, *Wbs;
    float *Pall, *isc, *r;
    cudaGetSymbolAddress((void**)&xs,   g_xs);
    cudaGetSymbolAddress((void**)&WTs,  g_WTs);
    cudaGetSymbolAddress((void**)&Pall, g_Pall);
    cudaGetSymbolAddress((void**)&iks,  g_iks);
    cudaGetSymbolAddress((void**)&iqs,  g_iqs);
    cudaGetSymbolAddress((void**)&isc,  g_isc);
    cudaGetSymbolAddress((void**)&ats,  g_ats);
    cudaGetSymbolAddress((void**)&Was,  g_Was);
    cudaGetSymbolAddress((void**)&r,    g_r);
    cudaGetSymbolAddress((void**)&rns,  g_rns);
    cudaGetSymbolAddress((void**)&Wbs,  g_Wbs);

    static int attr_set = 0;
    if (!attr_set) {
        cudaFuncSetAttribute(mma_gemm_hx<2>, cudaFuncAttributeMaxDynamicSharedMemorySize, HSMEM);
        cudaFuncSetAttribute(mma_gemm_hx<3>, cudaFuncAttributeMaxDynamicSharedMemorySize, HSMEM);
        attr_set = 1;
    }

    // operand splits
    split_plain<<<(NTOK * 1024) / 256, 256>>>(x, xs, PL_X, NTOK * 1024);
    splitT_w7<<<dim3(1024 / 32, NCOL / 32), dim3(32, 32)>>>(Wq, Wck, Wcv, Wcg, Wig, Wiq, Wik, WTs);
    split_plain<<<(512 * 1024) / 256, 256>>>(Wa, Was, PL_WA, 512 * 1024);
    splitT_gen<<<dim3(512 / 32, 1024 / 32), dim3(32, 32)>>>(Wb, Wbs, 512, 1024, PL_WB);

    // fused projection GEMM, precision-split:
    // cols [0,2560) = q|ck|cv|cg : 2-term (smooth value paths)
    mma_gemm_hx<2><<<dim3(SPLIT_COL / 128, NTOK / 128, 1), 256, HSMEM>>>(
        NTOK, SPLIT_COL, 1024, NCOL, 1.f, xs, PL_X, 0, WTs, PL_WT, 0, Pall, 0);
    // cols [2560,4096) = ig|iq|ik : 3-term (entire top-k selection chain)
    mma_gemm_hx<3><<<dim3((NCOL - SPLIT_COL) / 128, NTOK / 128, 1), 256, HSMEM>>>(
        NTOK, NCOL - SPLIT_COL, 1024, NCOL, 1.f, xs, PL_X, 0,
        WTs + (size_t)SPLIT_COL * 1024, PL_WT, 0, Pall + SPLIT_COL, 0);

    // compress + norms + rope
    compress_c<<<Bb * Gg * HKV, 128>>>(ape_c);
    compress_i<<<Bb * Gg * HIi, 64>>>(ape_i);
    iq_rms<<<NTOK * HIi, 64>>>();
    q_rope<<<NTOK * Hh, 32>>>();

    // index scores: batched, 3-term (selection), alpha = DI^-0.5 / HI = 1/64
    mma_gemm_hx<3><<<dim3(512 / 128, 2048 / 128, Bb), 256, HSMEM>>>(
        2048, 512, 512, 512, 1.f / 64.f,
        iqs, PL_IQ, (long)2048 * 512,
        iks, PL_IK, (long)512 * 512,
        isc, (long)2048 * 512);

    topk_thresh<<<NTOK, 512>>>();
    attn_kernel<<<NTOK * Hh, 128>>>();

    // r = attn @ Wa^T (2-term)
    mma_gemm_hx<2><<<dim3(512 / 128, NTOK / 128, 1), 256, HSMEM>>>(
        NTOK, 512, 1024, 512, 1.f, ats, PL_AT, 0, Was, PL_WA, 0, r, 0);

    rmsnorm512<<<NTOK, 256>>>();

    // out = rn @ Wb (2-term)
    mma_gemm_hx<2><<<dim3(1024 / 128, NTOK / 128, 1), 256, HSMEM>>>(
        NTOK, 1024, 512, 1024, 1.f, rns, PL_RN, 0, Wbs, PL_WB, 0, out, 0);
}

// round 13
// speedup vs baseline: 2.6389x; 1.1059x over previous
#include <cuda_runtime.h>
#include <cuda_fp16.h>
#include <math.h>
#include <stdint.h>

// Problem constants
#define Bb 4
#define Tt 2048
#define Cc 1024
#define Hh 8
#define HKV 4
#define Dd 128
#define Gg 512
#define HIi 8
#define DIi 64
#define NEGv (-1e30f)

#define NTOK (Bb*Tt)   // 8192
#define NCOL 4096      // fused projection width: q|ck|cv|cg | ig|iq|ik
#define OFF_Q  0
#define OFF_CK 1024
#define OFF_CV 1536
#define OFF_CG 2048
#define OFF_IG 2560
#define OFF_IQ 3072
#define OFF_IK 3584
#define SPLIT_COL 2560   // [0,2560) 2-term ; [2560,4096) 3-term (selection chain)

// plane strides (elements)
#define PL_X   ((long)NTOK*1024)
#define PL_WT  ((long)NCOL*1024)
#define PL_IQ  ((long)NTOK*512)
#define PL_IK  ((long)Bb*512*512)
#define PL_AT  ((long)NTOK*1024)
#define PL_WA  ((long)512*1024)
#define PL_RN  ((long)NTOK*512)
#define PL_WB  ((long)1024*512)

// ---------------- scratch (static device allocations) ----------------
__device__ alignas(256) __half g_xs [2*PL_X];
__device__ alignas(256) __half g_WTs[2*PL_WT];
__device__ alignas(256) float g_Pall[(size_t)NTOK*NCOL];
__device__ alignas(256) float g_ck [Bb*Gg*HKV*Dd];
__device__ alignas(256) float g_cv [Bb*Gg*HKV*Dd];
__device__ alignas(256) __half g_iks[2*PL_IK];
__device__ alignas(256) __half g_iqs[2*PL_IQ];
__device__ alignas(256) float g_isc[NTOK*Gg];
__device__ alignas(256) float g_thr[NTOK];
__device__ alignas(256) __half g_ats[2*PL_AT];
__device__ alignas(256) __half g_Was[2*PL_WA];
__device__ alignas(256) float g_r  [NTOK*512];
__device__ alignas(256) __half g_rns[2*PL_RN];
__device__ alignas(256) __half g_Wbs[2*PL_WB];

// ---------------- helpers ----------------
__device__ __forceinline__ void cpa16(uint32_t dst, const void* src) {
    asm volatile("cp.async.cg.shared.global [%0], [%1], 16;\n" :: "r"(dst), "l"(src));
}
__device__ __forceinline__ void cp_commit() {
    asm volatile("cp.async.commit_group;\n");
}
// k-permutation within a 32-element group: u32 j -> ((j&3)<<2)|(j>>2)
__device__ __forceinline__ int permk(int idx) {
    int kk = idx & 31;
    int j = kk >> 1;
    int jn = ((j & 3) << 2) | (j >> 2);
    return (idx & ~31) | (jn << 1) | (kk & 1);
}
// fp16 2-way split with permuted k index
__device__ __forceinline__ void split2(float v, __half* p, size_t base, int kidx, long plane) {
    __half h0 = __float2half_rn(v);
    float r1 = v - __half2float(h0);
    size_t idx = base + (size_t)permk(kidx);
    p[idx]         = h0;
    p[idx + plane] = __float2half_rn(r1);
}
__device__ __forceinline__ void mma_f16(float* c,
    uint32_t a0, uint32_t a1, uint32_t a2, uint32_t a3,
    uint32_t b0, uint32_t b1) {
    asm volatile(
        "mma.sync.aligned.m16n8k16.row.col.f32.f16.f16.f32 "
        "{%0,%1,%2,%3},{%4,%5,%6,%7},{%8,%9},{%0,%1,%2,%3};"
        : "+f"(c[0]), "+f"(c[1]), "+f"(c[2]), "+f"(c[3])
        : "r"(a0), "r"(a1), "r"(a2), "r"(a3), "r"(b0), "r"(b1));
}
__device__ __forceinline__ uint4 lds128(uint32_t addr) {
    uint4 v;
    asm volatile("ld.shared.v4.u32 {%0,%1,%2,%3}, [%4];"
                 : "=r"(v.x), "=r"(v.y), "=r"(v.z), "=r"(v.w) : "r"(addr));
    return v;
}

// ---------------- fp16 split MMA GEMM: C = alpha * A[M,K] @ B[N,K]^T ----------------
// NT=3: a0b0+a0b1+a1b0 (fp32-accurate ~2^-24). NT=2: a0b0+a0b1 (~2e-4 rel).
// A, B as 2 fp16 split planes (NT=2 reads only A plane0), k-permuted per 32-group.
// BM=BN=128, BK=32, 256 threads (8 warps 2x4), warp tile 64x32. ldc = C row stride.
// 3-stage cp.async pipeline.
#define HPLANE 2048          // 128 rows * 16 u32
#define HBUF   4096          // 2 planes
#define HTOT   8192          // A + B per buffer
#define HSMEM  (3 * HTOT * 4)  // 98304 bytes (3 stages)

template<int NT>
__global__ void __launch_bounds__(256, 2) mma_gemm_hx(
    int M, int N, int K, int ldc, float alpha,
    const __half* __restrict__ A0, long planeA, long batA,
    const __half* __restrict__ B0, long planeB, long batB,
    float* __restrict__ C, long batC) {
    extern __shared__ char smraw[];
    uint32_t sbase = (uint32_t)__cvta_generic_to_shared(smraw);

    const int tid  = threadIdx.x;
    const int wid  = tid >> 5;
    const int lane = tid & 31;
    const int lm   = lane >> 2;     // 0..7
    const int lk   = lane & 3;      // 0..3
    const int warp_m = (wid & 1) * 64;
    const int warp_n = (wid >> 1) * 32;
    const int bm = blockIdx.y * 128;
    const int bn = blockIdx.x * 128;
    const int z  = blockIdx.z;

    const __half* Abase = A0 + (size_t)z * batA;
    const __half* Bbase = B0 + (size_t)z * batB;
    float* Cptr = C + (size_t)z * batC + (size_t)(bm + warp_m) * ldc + bn + warp_n;

    float c[4][4][4];
    #pragma unroll
    for (int mt = 0; mt < 4; mt++)
        #pragma unroll
        for (int nt = 0; nt < 4; nt++)
            #pragma unroll
            for (int i = 0; i < 4; i++) c[mt][nt][i] = 0.f;

    const int nIter = K >> 5;

    auto stage = [&](int it, int buf) {
        const int k0 = it * 32;
        const uint32_t abase = sbase + (uint32_t)(buf * HTOT) * 4u;
        const uint32_t bbase = abase + HBUF * 4u;
        // A: NT==2 stages only plane0 (2 iters); NT==3 both planes (4 iters)
        #pragma unroll
        for (int i = 0; i < (NT == 2 ? 2 : 4); i++) {
            int id = tid + i * 256;
            int p = id >> 9, rem = id & 511, row = rem >> 2, cc = rem & 3;
            cpa16(abase + (uint32_t)(p * HPLANE + row * 16 + cc * 4) * 4u,
                  Abase + (size_t)p * planeA + (size_t)(bm + row) * K + k0 + cc * 8);
        }
        #pragma unroll
        for (int i = 0; i < 4; i++) {
            int id = tid + i * 256;
            int p = id >> 9, rem = id & 511, row = rem >> 2, cc = rem & 3;
            cpa16(bbase + (uint32_t)(p * HPLANE + row * 16 + cc * 4) * 4u,
                  Bbase + (size_t)p * planeB + (size_t)(bn + row) * K + k0 + cc * 8);
        }
        cp_commit();
    };

    stage(0, 0);
    if (nIter > 1) stage(1, 1);

    int buf = 0;
    for (int it = 0; it < nIter; it++) {
        if (it + 1 < nIter) {
            asm volatile("cp.async.wait_group 1;\n" ::: "memory");
        } else {
            asm volatile("cp.async.wait_group 0;\n" ::: "memory");
        }
        __syncthreads();
        // all warps are past compute of it-1 -> safe to overwrite buffer (it+2)%3
        if (it + 2 < nIter) stage(it + 2, (buf + 2 >= 3) ? buf - 1 : buf + 2);

        const uint32_t abufb = sbase + (uint32_t)(buf * HTOT) * 4u;
        const uint32_t bbufb = abufb + HBUF * 4u;

        // B fragments: one LDS.128 per (nt, plane) covers both k16 slices.
        uint4 b0f[4], b1f[4];
        #pragma unroll
        for (int nt = 0; nt < 4; nt++) {
            uint32_t baddr = bbufb + (uint32_t)(warp_n + nt * 8 + lm) * 64u + lk * 16u;
            b0f[nt] = lds128(baddr);
            b1f[nt] = lds128(baddr + HPLANE * 4u);
        }

        #pragma unroll
        for (int mt = 0; mt < 4; mt++) {
            const uint32_t aaddr = abufb + (uint32_t)(warp_m + mt * 16 + lm) * 64u + lk * 16u;
            uint4 alo0 = lds128(aaddr);
            uint4 ahi0 = lds128(aaddr + 8u * 64u);
            // kc0
            #pragma unroll
            for (int nt = 0; nt < 4; nt++)
                mma_f16(c[mt][nt], alo0.x, ahi0.x, alo0.y, ahi0.y, b0f[nt].x, b0f[nt].y);
            #pragma unroll
            for (int nt = 0; nt < 4; nt++)
                mma_f16(c[mt][nt], alo0.x, ahi0.x, alo0.y, ahi0.y, b1f[nt].x, b1f[nt].y);
            // kc1
            #pragma unroll
            for (int nt = 0; nt < 4; nt++)
                mma_f16(c[mt][nt], alo0.z, ahi0.z, alo0.w, ahi0.w, b0f[nt].z, b0f[nt].w);
            #pragma unroll
            for (int nt = 0; nt < 4; nt++)
                mma_f16(c[mt][nt], alo0.z, ahi0.z, alo0.w, ahi0.w, b1f[nt].z, b1f[nt].w);
            if (NT == 3) {
                uint4 alo1 = lds128(aaddr + HPLANE * 4u);
                uint4 ahi1 = lds128(aaddr + HPLANE * 4u + 8u * 64u);
                #pragma unroll
                for (int nt = 0; nt < 4; nt++)
                    mma_f16(c[mt][nt], alo1.x, ahi1.x, alo1.y, ahi1.y, b0f[nt].x, b0f[nt].y);
                #pragma unroll
                for (int nt = 0; nt < 4; nt++)
                    mma_f16(c[mt][nt], alo1.z, ahi1.z, alo1.w, ahi1.w, b0f[nt].z, b0f[nt].w);
            }
        }
        buf = (buf + 1 >= 3) ? 0 : buf + 1;
    }

    #pragma unroll
    for (int mt = 0; mt < 4; mt++) {
        #pragma unroll
        for (int nt = 0; nt < 4; nt++) {
            int r0 = mt * 16 + lm;
            int cc = nt * 8 + 2 * lk;
            float2 v;
            v.x = c[mt][nt][0] * alpha; v.y = c[mt][nt][1] * alpha;
            *(float2*)(Cptr + (size_t)r0 * ldc + cc) = v;
            v.x = c[mt][nt][2] * alpha; v.y = c[mt][nt][3] * alpha;
            *(float2*)(Cptr + (size_t)(r0 + 8) * ldc + cc) = v;
        }
    }
}

// ---------------- split kernels (write permuted k layout) ----------------
__global__ void split_plain(const float* __restrict__ src, __half* dst,
                            long plane, int n) {
    int idx = blockIdx.x * 256 + threadIdx.x;
    if (idx < n) split2(src[idx], dst, (size_t)(idx & ~31), idx & 31, plane);
}

// fused 7-weight concat + transpose + split: out planes [4096][1024]
// column order: q | ck | cv | cg | ig | iq | ik
__global__ void splitT_w7(const float* __restrict__ Wq,  const float* __restrict__ Wck,
                          const float* __restrict__ Wcv, const float* __restrict__ Wcg,
                          const float* __restrict__ Wig, const float* __restrict__ Wiq,
                          const float* __restrict__ Wik, __half* out) {
    __shared__ float tile[32][33];
    int k0 = blockIdx.x * 32, n0 = blockIdx.y * 32;
    int tx = threadIdx.x, ty = threadIdx.y;
    {
        int k = k0 + ty, n = n0 + tx;
        float v;
        if      (n < 1024) v = Wq [k * 1024 + n];
        else if (n < 1536) v = Wck[k * 512 + n - 1024];
        else if (n < 2048) v = Wcv[k * 512 + n - 1536];
        else if (n < 2560) v = Wcg[k * 512 + n - 2048];
        else if (n < 3072) v = Wig[k * 512 + n - 2560];
        else if (n < 3584) v = Wiq[k * 512 + n - 3072];
        else               v = Wik[k * 512 + n - 3584];
        tile[ty][tx] = v;
    }
    __syncthreads();
    int n = n0 + ty, k = k0 + tx;
    split2(tile[tx][ty], out, (size_t)n * 1024 + (k & ~31), k & 31, PL_WT);
}

// generic transpose+split: src [Kd][Nd] -> out planes [Nd][Kd]
__global__ void splitT_gen(const float* __restrict__ src, __half* out,
                           int Kd, int Nd, long plane) {
    __shared__ float tile[32][33];
    int k0 = blockIdx.x * 32, n0 = blockIdx.y * 32;
    int tx = threadIdx.x, ty = threadIdx.y;
    tile[ty][tx] = src[(size_t)(k0 + ty) * Nd + n0 + tx];
    __syncthreads();
    int n = n0 + ty, k = k0 + tx;
    split2(tile[tx][ty], out, (size_t)n * Kd + (k & ~31), k & 31, plane);
}

// ---------------- rope helper ----------------
__device__ __forceinline__ void rope_cs(int i, float pos, float& c, float& s) {
    float f = powf(160000.0f, (float)i * (1.0f / 32.0f));
    float ang = pos / f;
    sincosf(ang, &s, &c);
}

// ---------------- gated compress (coarse KV) + rope on ck ---------------- grid Bb*Gg*HKV, block 128
__global__ void compress_c(const float* __restrict__ ape) {
    int blk = blockIdx.x;
    int h = blk & 3;
    int bg = blk >> 2;
    int g = bg & (Gg - 1);
    int d = threadIdx.x;
    size_t base = (size_t)bg * 4 * NCOL + h * 128 + d;
    float gv[4], m = -1e30f;
    #pragma unroll
    for (int r = 0; r < 4; r++) {
        gv[r] = g_Pall[base + (size_t)r * NCOL + OFF_CG] + ape[(r * HKV + h) * 128 + d];
        m = fmaxf(m, gv[r]);
    }
    float ssum = 0.f;
    #pragma unroll
    for (int r = 0; r < 4; r++) { gv[r] = expf(gv[r] - m); ssum += gv[r]; }
    float inv = 1.f / ssum;
    float ka = 0.f, va = 0.f;
    #pragma unroll
    for (int r = 0; r < 4; r++) {
        float w = gv[r] * inv;
        ka += w * g_Pall[base + (size_t)r * NCOL + OFF_CK];
        va += w * g_Pall[base + (size_t)r * NCOL + OFF_CV];
    }
    __shared__ float sk[128];
    sk[d] = ka;
    __syncthreads();
    float pos = (float)(4 * g + 3);
    float outk = ka;
    if (d >= 64 && d < 96) {
        int i = d - 64; float c, s; rope_cs(i, pos, c, s);
        outk = sk[d] * c - sk[d + 32] * s;
    } else if (d >= 96) {
        int i = d - 96; float c, s; rope_cs(i, pos, c, s);
        outk = sk[d - 32] * s + sk[d] * c;
    }
    size_t ob = ((size_t)bg * 4 + h) * 128 + d;
    g_ck[ob] = outk;
    g_cv[ob] = va;
}

// ---------------- gated compress (index KV) + rmsnorm -> ik splits ---------------- grid Bb*Gg*HIi, block 64
__global__ void compress_i(const float* __restrict__ ape) {
    int blk = blockIdx.x;
    int h = blk & 7;
    int bg = blk >> 3;
    int d = threadIdx.x;
    size_t base = (size_t)bg * 4 * NCOL + h * 64 + d;
    float gv[4], m = -1e30f;
    #pragma unroll
    for (int r = 0; r < 4; r++) {
        gv[r] = g_Pall[base + (size_t)r * NCOL + OFF_IG] + ape[(r * HIi + h) * 64 + d];
        m = fmaxf(m, gv[r]);
    }
    float ssum = 0.f;
    #pragma unroll
    for (int r = 0; r < 4; r++) { gv[r] = expf(gv[r] - m); ssum += gv[r]; }
    float inv = 1.f / ssum;
    float ka = 0.f;
    #pragma unroll
    for (int r = 0; r < 4; r++)
        ka += gv[r] * inv * g_Pall[base + (size_t)r * NCOL + OFF_IK];
    __shared__ float red[64];
    red[d] = ka * ka;
    __syncthreads();
    #pragma unroll
    for (int s2 = 32; s2 > 0; s2 >>= 1) {
        if (d < s2) red[d] += red[d + s2];
        __syncthreads();
    }
    float sc = rsqrtf(red[0] / 64.f + 1e-6f);
    split2(ka * sc, g_iks, (size_t)bg * 512 + h * 64 + (d & ~31), d & 31, PL_IK);
}

// ---------------- per-head rmsnorm of iq -> iq splits ---------------- grid NTOK*HIi, block 64
__global__ void iq_rms() {
    int blk = blockIdx.x;
    int h = blk & 7;
    int row = blk >> 3;
    int d = threadIdx.x;
    float v = g_Pall[(size_t)row * NCOL + OFF_IQ + h * 64 + d];
    __shared__ float red[64];
    red[d] = v * v;
    __syncthreads();
    #pragma unroll
    for (int s2 = 32; s2 > 0; s2 >>= 1) {
        if (d < s2) red[d] += red[d + s2];
        __syncthreads();
    }
    float sc = rsqrtf(red[0] / 64.f + 1e-6f);
    split2(v * sc, g_iqs, (size_t)row * 512 + h * 64 + (d & ~31), d & 31, PL_IQ);
}

// ---------------- in-place partial rope of q ---------------- grid NTOK*Hh, block 32
__global__ void q_rope() {
    int blk = blockIdx.x;
    int h = blk & 7;
    int row = blk >> 3;
    int t = row & (Tt - 1);
    int i = threadIdx.x;
    size_t base = (size_t)row * NCOL + OFF_Q + h * 128;
    float x1 = g_Pall[base + 64 + i];
    float x2 = g_Pall[base + 96 + i];
    float c, s; rope_cs(i, (float)t, c, s);
    g_Pall[base + 64 + i] = x1 * c - x2 * s;
    g_Pall[base + 96 + i] = x1 * s + x2 * c;
}

// ---------------- top-k(64) threshold via hybrid bitonic sort ---------------- grid NTOK, block 512
// j<32 stages run in registers via shfl (same compare-exchange); j>=32 via shared.
__global__ void topk_thresh() {
    __shared__ float s[512];
    int row = blockIdx.x;
    int t = row & (Tt - 1);
    int tid = threadIdx.x;
    float v = g_isc[(size_t)row * Gg + tid];
    if (4 * tid + 3 > t) v = NEGv;

    // k = 2..32 entirely in registers
    #pragma unroll
    for (int k = 2; k <= 32; k <<= 1) {
        #pragma unroll
        for (int j = k >> 1; j > 0; j >>= 1) {
            float p = __shfl_xor_sync(0xffffffffu, v, j);
            bool down  = ((tid & k) == 0);
            bool lower = ((tid & j) == 0);
            v = (lower == down) ? fmaxf(v, p) : fminf(v, p);
        }
    }
    s[tid] = v;
    __syncthreads();

    for (int k = 64; k <= 512; k <<= 1) {
        for (int j = k >> 1; j >= 32; j >>= 1) {
            int ixj = tid ^ j;
            if (ixj > tid) {
                float a = s[tid], b = s[ixj];
                bool down = ((tid & k) == 0);
                bool sw = down ? (a < b) : (a > b);
                if (sw) { s[tid] = b; s[ixj] = a; }
            }
            __syncthreads();
        }
        v = s[tid];
        #pragma unroll
        for (int j = 16; j > 0; j >>= 1) {
            float p = __shfl_xor_sync(0xffffffffu, v, j);
            bool down  = ((tid & k) == 0);
            bool lower = ((tid & j) == 0);
            v = (lower == down) ? fmaxf(v, p) : fminf(v, p);
        }
        if (k < 512) { s[tid] = v; __syncthreads(); }
    }
    if (tid == 63) g_thr[row] = v;
}

// ---------------- sparse attention -> at splits ---------------- grid NTOK*Hh, block 128
__global__ void attn_kernel() {
    int blk = blockIdx.x;
    int h = blk & 7;
    int row = blk >> 3;
    int t = row & (Tt - 1);
    int b = row >> 11;
    int tid = threadIdx.x;
    __shared__ int sg[96];
    __shared__ float sw[96];
    __shared__ float red[128];
    __shared__ int cnt;
    __shared__ alignas(16) float qsh[128];
    if (tid == 0) cnt = 0;
    __syncthreads();

    int nc = (t >= 3) ? (((t - 3) >> 2) + 1) : 0;
    float th = g_thr[row];
    const float* iscr = g_isc + (size_t)row * Gg;
    for (int g = tid; g < nc; g += 128) {
        if (iscr[g] >= th) {
            int p = atomicAdd(&cnt, 1);
            if (p < 96) sg[p] = g;
        }
    }
    qsh[tid] = g_Pall[(size_t)row * NCOL + OFF_Q + h * 128 + tid];
    __syncthreads();
    int n = min(cnt, 96);
    int hkv = h >> 1;
    int warp = tid >> 5, lane = tid & 31;
    for (int i = warp; i < n; i += 4) {
        const float* kp = g_ck + ((size_t)(b * Gg + sg[i]) * 4 + hkv) * 128;
        float4 kv = *(const float4*)(kp + lane * 4);
        float4 qv = *(const float4*)(qsh + lane * 4);
        float p = qv.x * kv.x + qv.y * kv.y + qv.z * kv.z + qv.w * kv.w;
        #pragma unroll
        for (int o = 16; o > 0; o >>= 1) p += __shfl_xor_sync(0xffffffffu, p, o);
        if (lane == 0) sw[i] = p * 0.0883883476483184f;
    }
    __syncthreads();

    // parallel softmax over n entries (n <= 96 < 128)
    float myv = (tid < n) ? sw[tid] : -1e30f;
    red[tid] = myv;
    __syncthreads();
    #pragma unroll
    for (int s2 = 64; s2 > 0; s2 >>= 1) {
        if (tid < s2) red[tid] = fmaxf(red[tid], red[tid + s2]);
        __syncthreads();
    }
    float m = red[0];
    __syncthreads();
    float e = (tid < n) ? expf(myv - m) : 0.f;
    red[tid] = e;
    __syncthreads();
    #pragma unroll
    for (int s2 = 64; s2 > 0; s2 >>= 1) {
        if (tid < s2) red[tid] += red[tid + s2];
        __syncthreads();
    }
    float inv = 1.f / red[0];
    if (tid < n) sw[tid] = e * inv;
    __syncthreads();

    // V accumulation, 4x unrolled for MLP
    float acc = 0.f;
    int i = 0;
    for (; i + 4 <= n; i += 4) {
        float v0 = g_cv[((size_t)(b * Gg + sg[i + 0]) * 4 + hkv) * 128 + tid];
        float v1 = g_cv[((size_t)(b * Gg + sg[i + 1]) * 4 + hkv) * 128 + tid];
        float v2 = g_cv[((size_t)(b * Gg + sg[i + 2]) * 4 + hkv) * 128 + tid];
        float v3 = g_cv[((size_t)(b * Gg + sg[i + 3]) * 4 + hkv) * 128 + tid];
        acc += sw[i + 0] * v0 + sw[i + 1] * v1 + sw[i + 2] * v2 + sw[i + 3] * v3;
    }
    for (; i < n; i++)
        acc += sw[i] * g_cv[((size_t)(b * Gg + sg[i]) * 4 + hkv) * 128 + tid];
    split2(acc, g_ats, (size_t)row * 1024 + h * 128 + (tid & ~31), tid & 31, PL_AT);
}

// ---------------- rmsnorm over RANK=512 -> rn splits ---------------- grid NTOK, block 256
__global__ void rmsnorm512() {
    int row = blockIdx.x;
    int tid = threadIdx.x;
    size_t base = (size_t)row * 512;
    float a = g_r[base + tid], b = g_r[base + 256 + tid];
    __shared__ float red[256];
    red[tid] = a * a + b * b;
    __syncthreads();
    #pragma unroll
    for (int s2 = 128; s2 > 0; s2 >>= 1) {
        if (tid < s2) red[tid] += red[tid + s2];
        __syncthreads();
    }
    float sc = rsqrtf(red[0] / 512.f + 1e-6f);
    split2(a * sc, g_rns, base + (tid & ~31), tid & 31, PL_RN);
    split2(b * sc, g_rns, base + 256 + (tid & ~31), tid & 31, PL_RN);
}

// ---------------- launch ----------------
extern "C" void kernel_launch(void* const* d_in, const int* in_sizes, int n_in,
                              void* d_out, int out_size) {
    const float* x     = (const float*)d_in[0];
    const float* Wq    = (const float*)d_in[1];
    const float* Wck   = (const float*)d_in[2];
    const float* Wcv   = (const float*)d_in[3];
    const float* Wcg   = (const float*)d_in[4];
    const float* ape_c = (const float*)d_in[5];
    const float* Wiq   = (const float*)d_in[6];
    const float* Wik   = (const float*)d_in[7];
    const float* Wig   = (const float*)d_in[8];
    const float* ape_i = (const float*)d_in[9];
    const float* Wa    = (const float*)d_in[10];
    const float* Wb    = (const float*)d_in[11];
    float* out = (float*)d_out;

    __half *xs, *WTs, *iks, *iqs, *ats, *Was, *rns, *Wbs;
    float *Pall, *isc, *r;
    cudaGetSymbolAddress((void**)&xs,   g_xs);
    cudaGetSymbolAddress((void**)&WTs,  g_WTs);
    cudaGetSymbolAddress((void**)&Pall, g_Pall);
    cudaGetSymbolAddress((void**)&iks,  g_iks);
    cudaGetSymbolAddress((void**)&iqs,  g_iqs);
    cudaGetSymbolAddress((void**)&isc,  g_isc);
    cudaGetSymbolAddress((void**)&ats,  g_ats);
    cudaGetSymbolAddress((void**)&Was,  g_Was);
    cudaGetSymbolAddress((void**)&r,    g_r);
    cudaGetSymbolAddress((void**)&rns,  g_rns);
    cudaGetSymbolAddress((void**)&Wbs,  g_Wbs);

    static int attr_set = 0;
    if (!attr_set) {
        cudaFuncSetAttribute(mma_gemm_hx<2>, cudaFuncAttributeMaxDynamicSharedMemorySize, HSMEM);
        cudaFuncSetAttribute(mma_gemm_hx<3>, cudaFuncAttributeMaxDynamicSharedMemorySize, HSMEM);
        attr_set = 1;
    }

    // operand splits
    split_plain<<<(NTOK * 1024) / 256, 256>>>(x, xs, PL_X, NTOK * 1024);
    splitT_w7<<<dim3(1024 / 32, NCOL / 32), dim3(32, 32)>>>(Wq, Wck, Wcv, Wcg, Wig, Wiq, Wik, WTs);
    split_plain<<<(512 * 1024) / 256, 256>>>(Wa, Was, PL_WA, 512 * 1024);
    splitT_gen<<<dim3(512 / 32, 1024 / 32), dim3(32, 32)>>>(Wb, Wbs, 512, 1024, PL_WB);

    // fused projection GEMM, precision-split:
    // cols [0,2560) = q|ck|cv|cg : 2-term (smooth value paths)
    mma_gemm_hx<2><<<dim3(SPLIT_COL / 128, NTOK / 128, 1), 256, HSMEM>>>(
        NTOK, SPLIT_COL, 1024, NCOL, 1.f, xs, PL_X, 0, WTs, PL_WT, 0, Pall, 0);
    // cols [2560,4096) = ig|iq|ik : 3-term (entire top-k selection chain)
    mma_gemm_hx<3><<<dim3((NCOL - SPLIT_COL) / 128, NTOK / 128, 1), 256, HSMEM>>>(
        NTOK, NCOL - SPLIT_COL, 1024, NCOL, 1.f, xs, PL_X, 0,
        WTs + (size_t)SPLIT_COL * 1024, PL_WT, 0, Pall + SPLIT_COL, 0);

    // compress + norms + rope
    compress_c<<<Bb * Gg * HKV, 128>>>(ape_c);
    compress_i<<<Bb * Gg * HIi, 64>>>(ape_i);
    iq_rms<<<NTOK * HIi, 64>>>();
    q_rope<<<NTOK * Hh, 32>>>();

    // index scores: batched, 3-term (selection), alpha = DI^-0.5 / HI = 1/64
    mma_gemm_hx<3><<<dim3(512 / 128, 2048 / 128, Bb), 256, HSMEM>>>(
        2048, 512, 512, 512, 1.f / 64.f,
        iqs, PL_IQ, (long)2048 * 512,
        iks, PL_IK, (long)512 * 512,
        isc, (long)2048 * 512);

    topk_thresh<<<NTOK, 512>>>();
    attn_kernel<<<NTOK * Hh, 128>>>();

    // r = attn @ Wa^T (2-term)
    mma_gemm_hx<2><<<dim3(512 / 128, NTOK / 128, 1), 256, HSMEM>>>(
        NTOK, 512, 1024, 512, 1.f, ats, PL_AT, 0, Was, PL_WA, 0, r, 0);

    rmsnorm512<<<NTOK, 256>>>();

    // out = rn @ Wb (2-term)
    mma_gemm_hx<2><<<dim3(1024 / 128, NTOK / 128, 1), 256, HSMEM>>>(
        NTOK, 1024, 512, 1024, 1.f, rns, PL_RN, 0, Wbs, PL_WB, 0, out, 0);
}

// round 14
// speedup vs baseline: 2.9239x; 1.1080x over previous
#include <cuda_runtime.h>
#include <cuda_fp16.h>
#include <math.h>
#include <stdint.h>

// Problem constants
#define Bb 4
#define Tt 2048
#define Cc 1024
#define Hh 8
#define HKV 4
#define Dd 128
#define Gg 512
#define HIi 8
#define DIi 64
#define NEGv (-1e30f)

#define NTOK (Bb*Tt)   // 8192
#define NCOL 4096      // fused projection width: q|ck|cv|cg | ig|iq|ik
#define OFF_Q  0
#define OFF_CK 1024
#define OFF_CV 1536
#define OFF_CG 2048
#define OFF_IG 2560
#define OFF_IQ 3072
#define OFF_IK 3584
#define SPLIT_COL 2560   // [0,2560) 2-term ; [2560,4096) 3-term (selection chain)

// plane strides (elements)
#define PL_X   ((long)NTOK*1024)
#define PL_WT  ((long)NCOL*1024)
#define PL_IQ  ((long)NTOK*512)
#define PL_IK  ((long)Bb*512*512)
#define PL_AT  ((long)NTOK*1024)
#define PL_WA  ((long)512*1024)
#define PL_RN  ((long)NTOK*512)
#define PL_WB  ((long)1024*512)

// ---------------- scratch (static device allocations) ----------------
__device__ alignas(256) __half g_xs [2*PL_X];
__device__ alignas(256) __half g_WTs[2*PL_WT];
__device__ alignas(256) float g_Pall[(size_t)NTOK*NCOL];
__device__ alignas(256) float g_ck [Bb*Gg*HKV*Dd];
__device__ alignas(256) float g_cv [Bb*Gg*HKV*Dd];
__device__ alignas(256) __half g_iks[2*PL_IK];
__device__ alignas(256) __half g_iqs[2*PL_IQ];
__device__ alignas(256) float g_isc[NTOK*Gg];
__device__ alignas(256) float g_thr[NTOK];
__device__ alignas(256) __half g_ats[2*PL_AT];
__device__ alignas(256) __half g_Was[2*PL_WA];
__device__ alignas(256) float g_r  [NTOK*512];
__device__ alignas(256) __half g_rns[2*PL_RN];
__device__ alignas(256) __half g_Wbs[2*PL_WB];

// ---------------- helpers ----------------
__device__ __forceinline__ void cpa16(uint32_t dst, const void* src) {
    asm volatile("cp.async.cg.shared.global [%0], [%1], 16;\n" :: "r"(dst), "l"(src));
}
__device__ __forceinline__ void cp_commit() {
    asm volatile("cp.async.commit_group;\n");
}
// k-permutation within a 32-element group: u32 j -> ((j&3)<<2)|(j>>2)
__device__ __forceinline__ int permk(int idx) {
    int kk = idx & 31;
    int j = kk >> 1;
    int jn = ((j & 3) << 2) | (j >> 2);
    return (idx & ~31) | (jn << 1) | (kk & 1);
}
// fp16 2-way split with permuted k index
__device__ __forceinline__ void split2(float v, __half* p, size_t base, int kidx, long plane) {
    __half h0 = __float2half_rn(v);
    float r1 = v - __half2float(h0);
    size_t idx = base + (size_t)permk(kidx);
    p[idx]         = h0;
    p[idx + plane] = __float2half_rn(r1);
}
__device__ __forceinline__ void mma_f16(float* c,
    uint32_t a0, uint32_t a1, uint32_t a2, uint32_t a3,
    uint32_t b0, uint32_t b1) {
    asm volatile(
        "mma.sync.aligned.m16n8k16.row.col.f32.f16.f16.f32 "
        "{%0,%1,%2,%3},{%4,%5,%6,%7},{%8,%9},{%0,%1,%2,%3};"
        : "+f"(c[0]), "+f"(c[1]), "+f"(c[2]), "+f"(c[3])
        : "r"(a0), "r"(a1), "r"(a2), "r"(a3), "r"(b0), "r"(b1));
}
__device__ __forceinline__ uint4 lds128(uint32_t addr) {
    uint4 v;
    asm volatile("ld.shared.v4.u32 {%0,%1,%2,%3}, [%4];"
                 : "=r"(v.x), "=r"(v.y), "=r"(v.z), "=r"(v.w) : "r"(addr));
    return v;
}

// ---------------- fp16 split MMA GEMM: C = alpha * A[M,K] @ B[N,K]^T ----------------
// NT=3: a0b0+a0b1+a1b0 (fp32-accurate ~2^-24). NT=2: a0b0+a0b1 (~2e-4 rel).
// A, B as 2 fp16 split planes (NT=2 reads only A plane0), k-permuted per 32-group.
// BM=BN=128, BK=32, 256 threads (8 warps 2x4), warp tile 64x32. ldc = C row stride.
// 3-stage cp.async pipeline. causal=1: skip tiles fully above the causal boundary
// (M rows = t, N cols = groups; tile dead iff bm+124 < 4*bn).
#define HPLANE 2048          // 128 rows * 16 u32
#define HBUF   4096          // 2 planes
#define HTOT   8192          // A + B per buffer
#define HSMEM  (3 * HTOT * 4)  // 98304 bytes (3 stages)

template<int NT>
__global__ void __launch_bounds__(256, 2) mma_gemm_hx(
    int M, int N, int K, int ldc, float alpha, int causal,
    const __half* __restrict__ A0, long planeA, long batA,
    const __half* __restrict__ B0, long planeB, long batB,
    float* __restrict__ C, long batC) {
    extern __shared__ char smraw[];
    uint32_t sbase = (uint32_t)__cvta_generic_to_shared(smraw);

    const int tid  = threadIdx.x;
    const int wid  = tid >> 5;
    const int lane = tid & 31;
    const int lm   = lane >> 2;     // 0..7
    const int lk   = lane & 3;      // 0..3
    const int warp_m = (wid & 1) * 64;
    const int warp_n = (wid >> 1) * 32;
    const int bm = blockIdx.y * 128;
    const int bn = blockIdx.x * 128;
    const int z  = blockIdx.z;

    if (causal && (bm + 124 < 4 * bn)) return;   // tile fully causally masked; never read

    const __half* Abase = A0 + (size_t)z * batA;
    const __half* Bbase = B0 + (size_t)z * batB;
    float* Cptr = C + (size_t)z * batC + (size_t)(bm + warp_m) * ldc + bn + warp_n;

    float c[4][4][4];
    #pragma unroll
    for (int mt = 0; mt < 4; mt++)
        #pragma unroll
        for (int nt = 0; nt < 4; nt++)
            #pragma unroll
            for (int i = 0; i < 4; i++) c[mt][nt][i] = 0.f;

    const int nIter = K >> 5;

    auto stage = [&](int it, int buf) {
        const int k0 = it * 32;
        const uint32_t abase = sbase + (uint32_t)(buf * HTOT) * 4u;
        const uint32_t bbase = abase + HBUF * 4u;
        #pragma unroll
        for (int i = 0; i < (NT == 2 ? 2 : 4); i++) {
            int id = tid + i * 256;
            int p = id >> 9, rem = id & 511, row = rem >> 2, cc = rem & 3;
            cpa16(abase + (uint32_t)(p * HPLANE + row * 16 + cc * 4) * 4u,
                  Abase + (size_t)p * planeA + (size_t)(bm + row) * K + k0 + cc * 8);
        }
        #pragma unroll
        for (int i = 0; i < 4; i++) {
            int id = tid + i * 256;
            int p = id >> 9, rem = id & 511, row = rem >> 2, cc = rem & 3;
            cpa16(bbase + (uint32_t)(p * HPLANE + row * 16 + cc * 4) * 4u,
                  Bbase + (size_t)p * planeB + (size_t)(bn + row) * K + k0 + cc * 8);
        }
        cp_commit();
    };

    stage(0, 0);
    if (nIter > 1) stage(1, 1);

    int buf = 0;
    for (int it = 0; it < nIter; it++) {
        if (it + 1 < nIter) {
            asm volatile("cp.async.wait_group 1;\n" ::: "memory");
        } else {
            asm volatile("cp.async.wait_group 0;\n" ::: "memory");
        }
        __syncthreads();
        if (it + 2 < nIter) stage(it + 2, (buf + 2 >= 3) ? buf - 1 : buf + 2);

        const uint32_t abufb = sbase + (uint32_t)(buf * HTOT) * 4u;
        const uint32_t bbufb = abufb + HBUF * 4u;

        uint4 b0f[4], b1f[4];
        #pragma unroll
        for (int nt = 0; nt < 4; nt++) {
            uint32_t baddr = bbufb + (uint32_t)(warp_n + nt * 8 + lm) * 64u + lk * 16u;
            b0f[nt] = lds128(baddr);
            b1f[nt] = lds128(baddr + HPLANE * 4u);
        }

        #pragma unroll
        for (int mt = 0; mt < 4; mt++) {
            const uint32_t aaddr = abufb + (uint32_t)(warp_m + mt * 16 + lm) * 64u + lk * 16u;
            uint4 alo0 = lds128(aaddr);
            uint4 ahi0 = lds128(aaddr + 8u * 64u);
            #pragma unroll
            for (int nt = 0; nt < 4; nt++)
                mma_f16(c[mt][nt], alo0.x, ahi0.x, alo0.y, ahi0.y, b0f[nt].x, b0f[nt].y);
            #pragma unroll
            for (int nt = 0; nt < 4; nt++)
                mma_f16(c[mt][nt], alo0.x, ahi0.x, alo0.y, ahi0.y, b1f[nt].x, b1f[nt].y);
            #pragma unroll
            for (int nt = 0; nt < 4; nt++)
                mma_f16(c[mt][nt], alo0.z, ahi0.z, alo0.w, ahi0.w, b0f[nt].z, b0f[nt].w);
            #pragma unroll
            for (int nt = 0; nt < 4; nt++)
                mma_f16(c[mt][nt], alo0.z, ahi0.z, alo0.w, ahi0.w, b1f[nt].z, b1f[nt].w);
            if (NT == 3) {
                uint4 alo1 = lds128(aaddr + HPLANE * 4u);
                uint4 ahi1 = lds128(aaddr + HPLANE * 4u + 8u * 64u);
                #pragma unroll
                for (int nt = 0; nt < 4; nt++)
                    mma_f16(c[mt][nt], alo1.x, ahi1.x, alo1.y, ahi1.y, b0f[nt].x, b0f[nt].y);
                #pragma unroll
                for (int nt = 0; nt < 4; nt++)
                    mma_f16(c[mt][nt], alo1.z, ahi1.z, alo1.w, ahi1.w, b0f[nt].z, b0f[nt].w);
            }
        }
        buf = (buf + 1 >= 3) ? 0 : buf + 1;
    }

    #pragma unroll
    for (int mt = 0; mt < 4; mt++) {
        #pragma unroll
        for (int nt = 0; nt < 4; nt++) {
            int r0 = mt * 16 + lm;
            int cc = nt * 8 + 2 * lk;
            float2 v;
            v.x = c[mt][nt][0] * alpha; v.y = c[mt][nt][1] * alpha;
            *(float2*)(Cptr + (size_t)r0 * ldc + cc) = v;
            v.x = c[mt][nt][2] * alpha; v.y = c[mt][nt][3] * alpha;
            *(float2*)(Cptr + (size_t)(r0 + 8) * ldc + cc) = v;
        }
    }
}

// ---------------- split kernels (write permuted k layout) ----------------
__global__ void split_plain(const float* __restrict__ src, __half* dst,
                            long plane, int n) {
    int idx = blockIdx.x * 256 + threadIdx.x;
    if (idx < n) split2(src[idx], dst, (size_t)(idx & ~31), idx & 31, plane);
}

// fused 7-weight concat + transpose + split: out planes [4096][1024]
// column order: q | ck | cv | cg | ig | iq | ik
__global__ void splitT_w7(const float* __restrict__ Wq,  const float* __restrict__ Wck,
                          const float* __restrict__ Wcv, const float* __restrict__ Wcg,
                          const float* __restrict__ Wig, const float* __restrict__ Wiq,
                          const float* __restrict__ Wik, __half* out) {
    __shared__ float tile[32][33];
    int k0 = blockIdx.x * 32, n0 = blockIdx.y * 32;
    int tx = threadIdx.x, ty = threadIdx.y;
    {
        int k = k0 + ty, n = n0 + tx;
        float v;
        if      (n < 1024) v = Wq [k * 1024 + n];
        else if (n < 1536) v = Wck[k * 512 + n - 1024];
        else if (n < 2048) v = Wcv[k * 512 + n - 1536];
        else if (n < 2560) v = Wcg[k * 512 + n - 2048];
        else if (n < 3072) v = Wig[k * 512 + n - 2560];
        else if (n < 3584) v = Wiq[k * 512 + n - 3072];
        else               v = Wik[k * 512 + n - 3584];
        tile[ty][tx] = v;
    }
    __syncthreads();
    int n = n0 + ty, k = k0 + tx;
    split2(tile[tx][ty], out, (size_t)n * 1024 + (k & ~31), k & 31, PL_WT);
}

// generic transpose+split: src [Kd][Nd] -> out planes [Nd][Kd]
__global__ void splitT_gen(const float* __restrict__ src, __half* out,
                           int Kd, int Nd, long plane) {
    __shared__ float tile[32][33];
    int k0 = blockIdx.x * 32, n0 = blockIdx.y * 32;
    int tx = threadIdx.x, ty = threadIdx.y;
    tile[ty][tx] = src[(size_t)(k0 + ty) * Nd + n0 + tx];
    __syncthreads();
    int n = n0 + ty, k = k0 + tx;
    split2(tile[tx][ty], out, (size_t)n * Kd + (k & ~31), k & 31, plane);
}

// ---------------- rope helper ----------------
__device__ __forceinline__ void rope_cs(int i, float pos, float& c, float& s) {
    float f = powf(160000.0f, (float)i * (1.0f / 32.0f));
    float ang = pos / f;
    sincosf(ang, &s, &c);
}

// ---------------- gated compress (coarse KV) + rope on ck ---------------- grid Bb*Gg*HKV, block 128
__global__ void compress_c(const float* __restrict__ ape) {
    int blk = blockIdx.x;
    int h = blk & 3;
    int bg = blk >> 2;
    int g = bg & (Gg - 1);
    int d = threadIdx.x;
    size_t base = (size_t)bg * 4 * NCOL + h * 128 + d;
    float gv[4], m = -1e30f;
    #pragma unroll
    for (int r = 0; r < 4; r++) {
        gv[r] = g_Pall[base + (size_t)r * NCOL + OFF_CG] + ape[(r * HKV + h) * 128 + d];
        m = fmaxf(m, gv[r]);
    }
    float ssum = 0.f;
    #pragma unroll
    for (int r = 0; r < 4; r++) { gv[r] = expf(gv[r] - m); ssum += gv[r]; }
    float inv = 1.f / ssum;
    float ka = 0.f, va = 0.f;
    #pragma unroll
    for (int r = 0; r < 4; r++) {
        float w = gv[r] * inv;
        ka += w * g_Pall[base + (size_t)r * NCOL + OFF_CK];
        va += w * g_Pall[base + (size_t)r * NCOL + OFF_CV];
    }
    __shared__ float sk[128];
    sk[d] = ka;
    __syncthreads();
    float pos = (float)(4 * g + 3);
    float outk = ka;
    if (d >= 64 && d < 96) {
        int i = d - 64; float c, s; rope_cs(i, pos, c, s);
        outk = sk[d] * c - sk[d + 32] * s;
    } else if (d >= 96) {
        int i = d - 96; float c, s; rope_cs(i, pos, c, s);
        outk = sk[d - 32] * s + sk[d] * c;
    }
    size_t ob = ((size_t)bg * 4 + h) * 128 + d;
    g_ck[ob] = outk;
    g_cv[ob] = va;
}

// ---------------- gated compress (index KV) + rmsnorm -> ik splits ---------------- grid Bb*Gg*HIi, block 64
__global__ void compress_i(const float* __restrict__ ape) {
    int blk = blockIdx.x;
    int h = blk & 7;
    int bg = blk >> 3;
    int d = threadIdx.x;
    size_t base = (size_t)bg * 4 * NCOL + h * 64 + d;
    float gv[4], m = -1e30f;
    #pragma unroll
    for (int r = 0; r < 4; r++) {
        gv[r] = g_Pall[base + (size_t)r * NCOL + OFF_IG] + ape[(r * HIi + h) * 64 + d];
        m = fmaxf(m, gv[r]);
    }
    float ssum = 0.f;
    #pragma unroll
    for (int r = 0; r < 4; r++) { gv[r] = expf(gv[r] - m); ssum += gv[r]; }
    float inv = 1.f / ssum;
    float ka = 0.f;
    #pragma unroll
    for (int r = 0; r < 4; r++)
        ka += gv[r] * inv * g_Pall[base + (size_t)r * NCOL + OFF_IK];
    __shared__ float red[64];
    red[d] = ka * ka;
    __syncthreads();
    #pragma unroll
    for (int s2 = 32; s2 > 0; s2 >>= 1) {
        if (d < s2) red[d] += red[d + s2];
        __syncthreads();
    }
    float sc = rsqrtf(red[0] / 64.f + 1e-6f);
    split2(ka * sc, g_iks, (size_t)bg * 512 + h * 64 + (d & ~31), d & 31, PL_IK);
}

// ---------------- per-head rmsnorm of iq -> iq splits ---------------- grid NTOK*HIi, block 64
__global__ void iq_rms() {
    int blk = blockIdx.x;
    int h = blk & 7;
    int row = blk >> 3;
    int d = threadIdx.x;
    float v = g_Pall[(size_t)row * NCOL + OFF_IQ + h * 64 + d];
    __shared__ float red[64];
    red[d] = v * v;
    __syncthreads();
    #pragma unroll
    for (int s2 = 32; s2 > 0; s2 >>= 1) {
        if (d < s2) red[d] += red[d + s2];
        __syncthreads();
    }
    float sc = rsqrtf(red[0] / 64.f + 1e-6f);
    split2(v * sc, g_iqs, (size_t)row * 512 + h * 64 + (d & ~31), d & 31, PL_IQ);
}

// ---------------- in-place partial rope of q ---------------- grid NTOK*Hh, block 32
__global__ void q_rope() {
    int blk = blockIdx.x;
    int h = blk & 7;
    int row = blk >> 3;
    int t = row & (Tt - 1);
    int i = threadIdx.x;
    size_t base = (size_t)row * NCOL + OFF_Q + h * 128;
    float x1 = g_Pall[base + 64 + i];
    float x2 = g_Pall[base + 96 + i];
    float c, s; rope_cs(i, (float)t, c, s);
    g_Pall[base + 64 + i] = x1 * c - x2 * s;
    g_Pall[base + 96 + i] = x1 * s + x2 * c;
}

// ---------------- top-k(64) threshold via hybrid bitonic sort ---------------- grid NTOK, block 512
__global__ void topk_thresh() {
    __shared__ float s[512];
    int row = blockIdx.x;
    int t = row & (Tt - 1);
    int tid = threadIdx.x;
    float v = g_isc[(size_t)row * Gg + tid];
    if (4 * tid + 3 > t) v = NEGv;

    #pragma unroll
    for (int k = 2; k <= 32; k <<= 1) {
        #pragma unroll
        for (int j = k >> 1; j > 0; j >>= 1) {
            float p = __shfl_xor_sync(0xffffffffu, v, j);
            bool down  = ((tid & k) == 0);
            bool lower = ((tid & j) == 0);
            v = (lower == down) ? fmaxf(v, p) : fminf(v, p);
        }
    }
    s[tid] = v;
    __syncthreads();

    for (int k = 64; k <= 512; k <<= 1) {
        for (int j = k >> 1; j >= 32; j >>= 1) {
            int ixj = tid ^ j;
            if (ixj > tid) {
                float a = s[tid], b = s[ixj];
                bool down = ((tid & k) == 0);
                bool sw = down ? (a < b) : (a > b);
                if (sw) { s[tid] = b; s[ixj] = a; }
            }
            __syncthreads();
        }
        v = s[tid];
        #pragma unroll
        for (int j = 16; j > 0; j >>= 1) {
            float p = __shfl_xor_sync(0xffffffffu, v, j);
            bool down  = ((tid & k) == 0);
            bool lower = ((tid & j) == 0);
            v = (lower == down) ? fmaxf(v, p) : fminf(v, p);
        }
        if (k < 512) { s[tid] = v; __syncthreads(); }
    }
    if (tid == 63) g_thr[row] = v;
}

// ---------------- sparse attention, all 8 heads per block -> at splits ----------------
// grid NTOK, block 256. Warp w computes scores+softmax for head w (hkv=w>>1).
// V phase: thread (j0 = tid>>7, d = tid&127) accumulates heads {2j0,2j0+1,2j0+4,2j0+5}.
__global__ void __launch_bounds__(256) attn_kernel() {
    int row = blockIdx.x;
    int t = row & (Tt - 1);
    int b = row >> 11;
    int tid = threadIdx.x;
    int warp = tid >> 5, lane = tid & 31;
    __shared__ int sg[96];
    __shared__ float sw[8][96];
    __shared__ alignas(16) float qsh[1024];
    __shared__ int cnt;
    if (tid == 0) cnt = 0;
    __syncthreads();

    int nc = (t >= 3) ? (((t - 3) >> 2) + 1) : 0;
    float th = g_thr[row];
    const float* iscr = g_isc + (size_t)row * Gg;
    for (int g = tid; g < nc; g += 256) {
        if (iscr[g] >= th) {
            int p = atomicAdd(&cnt, 1);
            if (p < 96) sg[p] = g;
        }
    }
    #pragma unroll
    for (int i = 0; i < 4; i++)
        qsh[tid + i * 256] = g_Pall[(size_t)row * NCOL + OFF_Q + tid + i * 256];
    __syncthreads();
    int n = min(cnt, 96);

    // scores: warp w = head w
    {
        int hkv = warp >> 1;
        float4 qv = *(const float4*)(qsh + warp * 128 + lane * 4);
        for (int i = 0; i < n; i++) {
            const float* kp = g_ck + ((size_t)(b * Gg + sg[i]) * 4 + hkv) * 128;
            float4 kv = *(const float4*)(kp + lane * 4);
            float p = qv.x * kv.x + qv.y * kv.y + qv.z * kv.z + qv.w * kv.w;
            #pragma unroll
            for (int o = 16; o > 0; o >>= 1) p += __shfl_xor_sync(0xffffffffu, p, o);
            if (lane == 0) sw[warp][i] = p * 0.0883883476483184f;
        }
    }
    __syncthreads();

    // per-head warp softmax over n entries (n <= 96)
    {
        float v0 = (lane      < n) ? sw[warp][lane]      : -1e30f;
        float v1 = (lane + 32 < n) ? sw[warp][lane + 32] : -1e30f;
        float v2 = (lane + 64 < n) ? sw[warp][lane + 64] : -1e30f;
        float m = fmaxf(v0, fmaxf(v1, v2));
        #pragma unroll
        for (int o = 16; o > 0; o >>= 1) m = fmaxf(m, __shfl_xor_sync(0xffffffffu, m, o));
        float e0 = (lane      < n) ? expf(v0 - m) : 0.f;
        float e1 = (lane + 32 < n) ? expf(v1 - m) : 0.f;
        float e2 = (lane + 64 < n) ? expf(v2 - m) : 0.f;
        float ssum = e0 + e1 + e2;
        #pragma unroll
        for (int o = 16; o > 0; o >>= 1) ssum += __shfl_xor_sync(0xffffffffu, ssum, o);
        float inv = 1.f / ssum;
        if (lane      < n) sw[warp][lane]      = e0 * inv;
        if (lane + 32 < n) sw[warp][lane + 32] = e1 * inv;
        if (lane + 64 < n) sw[warp][lane + 64] = e2 * inv;
    }
    __syncthreads();

    // V accumulation: 4 outputs per thread, V row shared by head pairs
    {
        int d = tid & 127;
        int j0 = tid >> 7;               // hkv j0 and j0+2
        float a0 = 0.f, a1 = 0.f, a2 = 0.f, a3 = 0.f;
        for (int i = 0; i < n; i++) {
            size_t vb = (size_t)(b * Gg + sg[i]) * 4;
            float v0 = g_cv[(vb + j0) * 128 + d];
            float v1 = g_cv[(vb + j0 + 2) * 128 + d];
            a0 += sw[2 * j0][i]     * v0;
            a1 += sw[2 * j0 + 1][i] * v0;
            a2 += sw[2 * j0 + 4][i] * v1;
            a3 += sw[2 * j0 + 5][i] * v1;
        }
        size_t ob = (size_t)row * 1024 + (d & ~31);
        int kb = d & 31;
        split2(a0, g_ats, ob + (2 * j0) * 128,     kb, PL_AT);
        split2(a1, g_ats, ob + (2 * j0 + 1) * 128, kb, PL_AT);
        split2(a2, g_ats, ob + (2 * j0 + 4) * 128, kb, PL_AT);
        split2(a3, g_ats, ob + (2 * j0 + 5) * 128, kb, PL_AT);
    }
}

// ---------------- rmsnorm over RANK=512 -> rn splits ---------------- grid NTOK, block 256
__global__ void rmsnorm512() {
    int row = blockIdx.x;
    int tid = threadIdx.x;
    size_t base = (size_t)row * 512;
    float a = g_r[base + tid], b = g_r[base + 256 + tid];
    __shared__ float red[256];
    red[tid] = a * a + b * b;
    __syncthreads();
    #pragma unroll
    for (int s2 = 128; s2 > 0; s2 >>= 1) {
        if (tid < s2) red[tid] += red[tid + s2];
        __syncthreads();
    }
    float sc = rsqrtf(red[0] / 512.f + 1e-6f);
    split2(a * sc, g_rns, base + (tid & ~31), tid & 31, PL_RN);
    split2(b * sc, g_rns, base + 256 + (tid & ~31), tid & 31, PL_RN);
}

// ---------------- launch ----------------
extern "C" void kernel_launch(void* const* d_in, const int* in_sizes, int n_in,
                              void* d_out, int out_size) {
    const float* x     = (const float*)d_in[0];
    const float* Wq    = (const float*)d_in[1];
    const float* Wck   = (const float*)d_in[2];
    const float* Wcv   = (const float*)d_in[3];
    const float* Wcg   = (const float*)d_in[4];
    const float* ape_c = (const float*)d_in[5];
    const float* Wiq   = (const float*)d_in[6];
    const float* Wik   = (const float*)d_in[7];
    const float* Wig   = (const float*)d_in[8];
    const float* ape_i = (const float*)d_in[9];
    const float* Wa    = (const float*)d_in[10];
    const float* Wb    = (const float*)d_in[11];
    float* out = (float*)d_out;

    __half *xs, *WTs, *iks, *iqs, *ats, *Was, *rns, *Wbs;
    float *Pall, *isc, *r;
    cudaGetSymbolAddress((void**)&xs,   g_xs);
    cudaGetSymbolAddress((void**)&WTs,  g_WTs);
    cudaGetSymbolAddress((void**)&Pall, g_Pall);
    cudaGetSymbolAddress((void**)&iks,  g_iks);
    cudaGetSymbolAddress((void**)&iqs,  g_iqs);
    cudaGetSymbolAddress((void**)&isc,  g_isc);
    cudaGetSymbolAddress((void**)&ats,  g_ats);
    cudaGetSymbolAddress((void**)&Was,  g_Was);
    cudaGetSymbolAddress((void**)&r,    g_r);
    cudaGetSymbolAddress((void**)&rns,  g_rns);
    cudaGetSymbolAddress((void**)&Wbs,  g_Wbs);

    static int attr_set = 0;
    if (!attr_set) {
        cudaFuncSetAttribute(mma_gemm_hx<2>, cudaFuncAttributeMaxDynamicSharedMemorySize, HSMEM);
        cudaFuncSetAttribute(mma_gemm_hx<3>, cudaFuncAttributeMaxDynamicSharedMemorySize, HSMEM);
        attr_set = 1;
    }

    // operand splits
    split_plain<<<(NTOK * 1024) / 256, 256>>>(x, xs, PL_X, NTOK * 1024);
    splitT_w7<<<dim3(1024 / 32, NCOL / 32), dim3(32, 32)>>>(Wq, Wck, Wcv, Wcg, Wig, Wiq, Wik, WTs);
    split_plain<<<(512 * 1024) / 256, 256>>>(Wa, Was, PL_WA, 512 * 1024);
    splitT_gen<<<dim3(512 / 32, 1024 / 32), dim3(32, 32)>>>(Wb, Wbs, 512, 1024, PL_WB);

    // fused projection GEMM, precision-split:
    mma_gemm_hx<2><<<dim3(SPLIT_COL / 128, NTOK / 128, 1), 256, HSMEM>>>(
        NTOK, SPLIT_COL, 1024, NCOL, 1.f, 0, xs, PL_X, 0, WTs, PL_WT, 0, Pall, 0);
    mma_gemm_hx<3><<<dim3((NCOL - SPLIT_COL) / 128, NTOK / 128, 1), 256, HSMEM>>>(
        NTOK, NCOL - SPLIT_COL, 1024, NCOL, 1.f, 0, xs, PL_X, 0,
        WTs + (size_t)SPLIT_COL * 1024, PL_WT, 0, Pall + SPLIT_COL, 0);

    // compress + norms + rope
    compress_c<<<Bb * Gg * HKV, 128>>>(ape_c);
    compress_i<<<Bb * Gg * HIi, 64>>>(ape_i);
    iq_rms<<<NTOK * HIi, 64>>>();
    q_rope<<<NTOK * Hh, 32>>>();

    // index scores: batched, 3-term, causal tile skip, alpha = DI^-0.5 / HI = 1/64
    mma_gemm_hx<3><<<dim3(512 / 128, 2048 / 128, Bb), 256, HSMEM>>>(
        2048, 512, 512, 512, 1.f / 64.f, 1,
        iqs, PL_IQ, (long)2048 * 512,
        iks, PL_IK, (long)512 * 512,
        isc, (long)2048 * 512);

    topk_thresh<<<NTOK, 512>>>();
    attn_kernel<<<NTOK, 256>>>();

    // r = attn @ Wa^T (2-term)
    mma_gemm_hx<2><<<dim3(512 / 128, NTOK / 128, 1), 256, HSMEM>>>(
        NTOK, 512, 1024, 512, 1.f, 0, ats, PL_AT, 0, Was, PL_WA, 0, r, 0);

    rmsnorm512<<<NTOK, 256>>>();

    // out = rn @ Wb (2-term)
    mma_gemm_hx<2><<<dim3(1024 / 128, NTOK / 128, 1), 256, HSMEM>>>(
        NTOK, 1024, 512, 1024, 1.f, 0, rns, PL_RN, 0, Wbs, PL_WB, 0, out, 0);
}

// round 15
// speedup vs baseline: 2.9930x; 1.0237x over previous
#include <cuda_runtime.h>
#include <cuda_fp16.h>
#include <math.h>
#include <stdint.h>

// Problem constants
#define Bb 4
#define Tt 2048
#define Cc 1024
#define Hh 8
#define HKV 4
#define Dd 128
#define Gg 512
#define HIi 8
#define DIi 64
#define NEGv (-1e30f)

#define NTOK (Bb*Tt)   // 8192
#define NCOL 4096      // fused projection width: q|ck|cv|cg | ig|iq|ik
#define OFF_Q  0
#define OFF_CK 1024
#define OFF_CV 1536
#define OFF_CG 2048
#define OFF_IG 2560
#define OFF_IQ 3072
#define OFF_IK 3584
#define SPLIT_COL 2560   // [0,2560) 2-term ; [2560,4096) 3-term (selection chain)

// plane strides (elements)
#define PL_X   ((long)NTOK*1024)
#define PL_WT  ((long)NCOL*1024)
#define PL_IQ  ((long)NTOK*512)
#define PL_IK  ((long)Bb*512*512)
#define PL_AT  ((long)NTOK*1024)
#define PL_WA  ((long)512*1024)
#define PL_RN  ((long)NTOK*512)
#define PL_WB  ((long)1024*512)

// ---------------- scratch (static device allocations) ----------------
__device__ alignas(256) __half g_xs [2*PL_X];
__device__ alignas(256) __half g_WTs[2*PL_WT];
__device__ alignas(256) float g_Pall[(size_t)NTOK*NCOL];
__device__ alignas(256) float g_ck [Bb*Gg*HKV*Dd];
__device__ alignas(256) float g_cv [Bb*Gg*HKV*Dd];
__device__ alignas(256) __half g_iks[2*PL_IK];
__device__ alignas(256) __half g_iqs[2*PL_IQ];
__device__ alignas(256) float g_isc[NTOK*Gg];
__device__ alignas(256) float g_thr[NTOK];
__device__ alignas(256) __half g_ats[2*PL_AT];
__device__ alignas(256) __half g_Was[2*PL_WA];
__device__ alignas(256) float g_r  [NTOK*512];
__device__ alignas(256) __half g_rns[2*PL_RN];
__device__ alignas(256) __half g_Wbs[2*PL_WB];

// ---------------- helpers ----------------
__device__ __forceinline__ void cpa16(uint32_t dst, const void* src) {
    asm volatile("cp.async.cg.shared.global [%0], [%1], 16;\n" :: "r"(dst), "l"(src));
}
__device__ __forceinline__ void cp_commit() {
    asm volatile("cp.async.commit_group;\n");
}
// k-permutation within a 32-element group: u32 j -> ((j&3)<<2)|(j>>2)
__device__ __forceinline__ int permk(int idx) {
    int kk = idx & 31;
    int j = kk >> 1;
    int jn = ((j & 3) << 2) | (j >> 2);
    return (idx & ~31) | (jn << 1) | (kk & 1);
}
// fp16 2-way split with permuted k index
__device__ __forceinline__ void split2(float v, __half* p, size_t base, int kidx, long plane) {
    __half h0 = __float2half_rn(v);
    float r1 = v - __half2float(h0);
    size_t idx = base + (size_t)permk(kidx);
    p[idx]         = h0;
    p[idx + plane] = __float2half_rn(r1);
}
__device__ __forceinline__ void mma_f16(float* c,
    uint32_t a0, uint32_t a1, uint32_t a2, uint32_t a3,
    uint32_t b0, uint32_t b1) {
    asm volatile(
        "mma.sync.aligned.m16n8k16.row.col.f32.f16.f16.f32 "
        "{%0,%1,%2,%3},{%4,%5,%6,%7},{%8,%9},{%0,%1,%2,%3};"
        : "+f"(c[0]), "+f"(c[1]), "+f"(c[2]), "+f"(c[3])
        : "r"(a0), "r"(a1), "r"(a2), "r"(a3), "r"(b0), "r"(b1));
}
__device__ __forceinline__ uint4 lds128(uint32_t addr) {
    uint4 v;
    asm volatile("ld.shared.v4.u32 {%0,%1,%2,%3}, [%4];"
                 : "=r"(v.x), "=r"(v.y), "=r"(v.z), "=r"(v.w) : "r"(addr));
    return v;
}

// ---------------- fp16 split MMA GEMM: C = alpha * A[M,K] @ B[N,K]^T ----------------
// NT=3: a0b0+a0b1+a1b0 (fp32-accurate ~2^-24). NT=2: a0b0+a0b1 (~2e-4 rel).
// NT=0: mixed — per-column-tile: 2-term for bn < SPLIT_COL, 3-term otherwise.
// A, B as 2 fp16 split planes, k-permuted per 32-group.
// BM=BN=128, BK=32, 256 threads (8 warps 2x4), warp tile 64x32. ldc = C row stride.
// 3-stage cp.async pipeline. causal=1: skip tiles with bm+124 < 4*bn (never read).
#define HPLANE 2048          // 128 rows * 16 u32
#define HBUF   4096          // 2 planes
#define HTOT   8192          // A + B per buffer
#define HSMEM  (3 * HTOT * 4)  // 98304 bytes (3 stages)

template<int NT>
__global__ void __launch_bounds__(256, 2) mma_gemm_hx(
    int M, int N, int K, int ldc, float alpha, int causal,
    const __half* __restrict__ A0, long planeA, long batA,
    const __half* __restrict__ B0, long planeB, long batB,
    float* __restrict__ C, long batC) {
    extern __shared__ char smraw[];
    uint32_t sbase = (uint32_t)__cvta_generic_to_shared(smraw);

    const int tid  = threadIdx.x;
    const int wid  = tid >> 5;
    const int lane = tid & 31;
    const int lm   = lane >> 2;     // 0..7
    const int lk   = lane & 3;      // 0..3
    const int warp_m = (wid & 1) * 64;
    const int warp_n = (wid >> 1) * 32;
    const int bm = blockIdx.y * 128;
    const int bn = blockIdx.x * 128;
    const int z  = blockIdx.z;

    if (causal && (bm + 124 < 4 * bn)) return;   // tile fully causally masked

    const bool nt3 = (NT == 3) || (NT == 0 && bn >= SPLIT_COL);

    const __half* Abase = A0 + (size_t)z * batA;
    const __half* Bbase = B0 + (size_t)z * batB;
    float* Cptr = C + (size_t)z * batC + (size_t)(bm + warp_m) * ldc + bn + warp_n;

    float c[4][4][4];
    #pragma unroll
    for (int mt = 0; mt < 4; mt++)
        #pragma unroll
        for (int nt = 0; nt < 4; nt++)
            #pragma unroll
            for (int i = 0; i < 4; i++) c[mt][nt][i] = 0.f;

    const int nIter = K >> 5;

    auto stage = [&](int it, int buf) {
        const int k0 = it * 32;
        const uint32_t abase = sbase + (uint32_t)(buf * HTOT) * 4u;
        const uint32_t bbase = abase + HBUF * 4u;
        // A plane0
        #pragma unroll
        for (int i = 0; i < 2; i++) {
            int rem = tid + i * 256;
            int row = rem >> 2, cc = rem & 3;
            cpa16(abase + (uint32_t)(row * 16 + cc * 4) * 4u,
                  Abase + (size_t)(bm + row) * K + k0 + cc * 8);
        }
        // A plane1 (3-term tiles only)
        if (nt3) {
            #pragma unroll
            for (int i = 0; i < 2; i++) {
                int rem = tid + i * 256;
                int row = rem >> 2, cc = rem & 3;
                cpa16(abase + (uint32_t)(HPLANE + row * 16 + cc * 4) * 4u,
                      Abase + planeA + (size_t)(bm + row) * K + k0 + cc * 8);
            }
        }
        #pragma unroll
        for (int i = 0; i < 4; i++) {
            int id = tid + i * 256;
            int p = id >> 9, rem = id & 511, row = rem >> 2, cc = rem & 3;
            cpa16(bbase + (uint32_t)(p * HPLANE + row * 16 + cc * 4) * 4u,
                  Bbase + (size_t)p * planeB + (size_t)(bn + row) * K + k0 + cc * 8);
        }
        cp_commit();
    };

    stage(0, 0);
    if (nIter > 1) stage(1, 1);

    int buf = 0;
    for (int it = 0; it < nIter; it++) {
        if (it + 1 < nIter) {
            asm volatile("cp.async.wait_group 1;\n" ::: "memory");
        } else {
            asm volatile("cp.async.wait_group 0;\n" ::: "memory");
        }
        __syncthreads();
        if (it + 2 < nIter) stage(it + 2, (buf + 2 >= 3) ? buf - 1 : buf + 2);

        const uint32_t abufb = sbase + (uint32_t)(buf * HTOT) * 4u;
        const uint32_t bbufb = abufb + HBUF * 4u;

        uint4 b0f[4], b1f[4];
        #pragma unroll
        for (int nt = 0; nt < 4; nt++) {
            uint32_t baddr = bbufb + (uint32_t)(warp_n + nt * 8 + lm) * 64u + lk * 16u;
            b0f[nt] = lds128(baddr);
            b1f[nt] = lds128(baddr + HPLANE * 4u);
        }

        #pragma unroll
        for (int mt = 0; mt < 4; mt++) {
            const uint32_t aaddr = abufb + (uint32_t)(warp_m + mt * 16 + lm) * 64u + lk * 16u;
            uint4 alo0 = lds128(aaddr);
            uint4 ahi0 = lds128(aaddr + 8u * 64u);
            #pragma unroll
            for (int nt = 0; nt < 4; nt++)
                mma_f16(c[mt][nt], alo0.x, ahi0.x, alo0.y, ahi0.y, b0f[nt].x, b0f[nt].y);
            #pragma unroll
            for (int nt = 0; nt < 4; nt++)
                mma_f16(c[mt][nt], alo0.x, ahi0.x, alo0.y, ahi0.y, b1f[nt].x, b1f[nt].y);
            #pragma unroll
            for (int nt = 0; nt < 4; nt++)
                mma_f16(c[mt][nt], alo0.z, ahi0.z, alo0.w, ahi0.w, b0f[nt].z, b0f[nt].w);
            #pragma unroll
            for (int nt = 0; nt < 4; nt++)
                mma_f16(c[mt][nt], alo0.z, ahi0.z, alo0.w, ahi0.w, b1f[nt].z, b1f[nt].w);
            if (nt3) {
                uint4 alo1 = lds128(aaddr + HPLANE * 4u);
                uint4 ahi1 = lds128(aaddr + HPLANE * 4u + 8u * 64u);
                #pragma unroll
                for (int nt = 0; nt < 4; nt++)
                    mma_f16(c[mt][nt], alo1.x, ahi1.x, alo1.y, ahi1.y, b0f[nt].x, b0f[nt].y);
                #pragma unroll
                for (int nt = 0; nt < 4; nt++)
                    mma_f16(c[mt][nt], alo1.z, ahi1.z, alo1.w, ahi1.w, b0f[nt].z, b0f[nt].w);
            }
        }
        buf = (buf + 1 >= 3) ? 0 : buf + 1;
    }

    #pragma unroll
    for (int mt = 0; mt < 4; mt++) {
        #pragma unroll
        for (int nt = 0; nt < 4; nt++) {
            int r0 = mt * 16 + lm;
            int cc = nt * 8 + 2 * lk;
            float2 v;
            v.x = c[mt][nt][0] * alpha; v.y = c[mt][nt][1] * alpha;
            *(float2*)(Cptr + (size_t)r0 * ldc + cc) = v;
            v.x = c[mt][nt][2] * alpha; v.y = c[mt][nt][3] * alpha;
            *(float2*)(Cptr + (size_t)(r0 + 8) * ldc + cc) = v;
        }
    }
}

// ---------------- split kernels (write permuted k layout) ----------------
__global__ void split_plain(const float* __restrict__ src, __half* dst,
                            long plane, int n) {
    int idx = blockIdx.x * 256 + threadIdx.x;
    if (idx < n) split2(src[idx], dst, (size_t)(idx & ~31), idx & 31, plane);
}

// fused 7-weight concat + transpose + split: out planes [4096][1024]
// column order: q | ck | cv | cg | ig | iq | ik
__global__ void splitT_w7(const float* __restrict__ Wq,  const float* __restrict__ Wck,
                          const float* __restrict__ Wcv, const float* __restrict__ Wcg,
                          const float* __restrict__ Wig, const float* __restrict__ Wiq,
                          const float* __restrict__ Wik, __half* out) {
    __shared__ float tile[32][33];
    int k0 = blockIdx.x * 32, n0 = blockIdx.y * 32;
    int tx = threadIdx.x, ty = threadIdx.y;
    {
        int k = k0 + ty, n = n0 + tx;
        float v;
        if      (n < 1024) v = Wq [k * 1024 + n];
        else if (n < 1536) v = Wck[k * 512 + n - 1024];
        else if (n < 2048) v = Wcv[k * 512 + n - 1536];
        else if (n < 2560) v = Wcg[k * 512 + n - 2048];
        else if (n < 3072) v = Wig[k * 512 + n - 2560];
        else if (n < 3584) v = Wiq[k * 512 + n - 3072];
        else               v = Wik[k * 512 + n - 3584];
        tile[ty][tx] = v;
    }
    __syncthreads();
    int n = n0 + ty, k = k0 + tx;
    split2(tile[tx][ty], out, (size_t)n * 1024 + (k & ~31), k & 31, PL_WT);
}

// generic transpose+split: src [Kd][Nd] -> out planes [Nd][Kd]
__global__ void splitT_gen(const float* __restrict__ src, __half* out,
                           int Kd, int Nd, long plane) {
    __shared__ float tile[32][33];
    int k0 = blockIdx.x * 32, n0 = blockIdx.y * 32;
    int tx = threadIdx.x, ty = threadIdx.y;
    tile[ty][tx] = src[(size_t)(k0 + ty) * Nd + n0 + tx];
    __syncthreads();
    int n = n0 + ty, k = k0 + tx;
    split2(tile[tx][ty], out, (size_t)n * Kd + (k & ~31), k & 31, plane);
}

// ---------------- rope helper ----------------
__device__ __forceinline__ void rope_cs(int i, float pos, float& c, float& s) {
    float f = powf(160000.0f, (float)i * (1.0f / 32.0f));
    float ang = pos / f;
    sincosf(ang, &s, &c);
}

// ---------------- gated compress (coarse KV) + rope on ck ---------------- grid Bb*Gg*HKV, block 128
__global__ void compress_c(const float* __restrict__ ape) {
    int blk = blockIdx.x;
    int h = blk & 3;
    int bg = blk >> 2;
    int g = bg & (Gg - 1);
    int d = threadIdx.x;
    size_t base = (size_t)bg * 4 * NCOL + h * 128 + d;
    float gv[4], m = -1e30f;
    #pragma unroll
    for (int r = 0; r < 4; r++) {
        gv[r] = g_Pall[base + (size_t)r * NCOL + OFF_CG] + ape[(r * HKV + h) * 128 + d];
        m = fmaxf(m, gv[r]);
    }
    float ssum = 0.f;
    #pragma unroll
    for (int r = 0; r < 4; r++) { gv[r] = expf(gv[r] - m); ssum += gv[r]; }
    float inv = 1.f / ssum;
    float ka = 0.f, va = 0.f;
    #pragma unroll
    for (int r = 0; r < 4; r++) {
        float w = gv[r] * inv;
        ka += w * g_Pall[base + (size_t)r * NCOL + OFF_CK];
        va += w * g_Pall[base + (size_t)r * NCOL + OFF_CV];
    }
    __shared__ float sk[128];
    sk[d] = ka;
    __syncthreads();
    float pos = (float)(4 * g + 3);
    float outk = ka;
    if (d >= 64 && d < 96) {
        int i = d - 64; float c, s; rope_cs(i, pos, c, s);
        outk = sk[d] * c - sk[d + 32] * s;
    } else if (d >= 96) {
        int i = d - 96; float c, s; rope_cs(i, pos, c, s);
        outk = sk[d - 32] * s + sk[d] * c;
    }
    size_t ob = ((size_t)bg * 4 + h) * 128 + d;
    g_ck[ob] = outk;
    g_cv[ob] = va;
}

// ---------------- gated compress (index KV) + rmsnorm -> ik splits ---------------- grid Bb*Gg*HIi, block 64
__global__ void compress_i(const float* __restrict__ ape) {
    int blk = blockIdx.x;
    int h = blk & 7;
    int bg = blk >> 3;
    int d = threadIdx.x;
    size_t base = (size_t)bg * 4 * NCOL + h * 64 + d;
    float gv[4], m = -1e30f;
    #pragma unroll
    for (int r = 0; r < 4; r++) {
        gv[r] = g_Pall[base + (size_t)r * NCOL + OFF_IG] + ape[(r * HIi + h) * 64 + d];
        m = fmaxf(m, gv[r]);
    }
    float ssum = 0.f;
    #pragma unroll
    for (int r = 0; r < 4; r++) { gv[r] = expf(gv[r] - m); ssum += gv[r]; }
    float inv = 1.f / ssum;
    float ka = 0.f;
    #pragma unroll
    for (int r = 0; r < 4; r++)
        ka += gv[r] * inv * g_Pall[base + (size_t)r * NCOL + OFF_IK];
    __shared__ float red[64];
    red[d] = ka * ka;
    __syncthreads();
    #pragma unroll
    for (int s2 = 32; s2 > 0; s2 >>= 1) {
        if (d < s2) red[d] += red[d + s2];
        __syncthreads();
    }
    float sc = rsqrtf(red[0] / 64.f + 1e-6f);
    split2(ka * sc, g_iks, (size_t)bg * 512 + h * 64 + (d & ~31), d & 31, PL_IK);
}

// ---------------- per-head rmsnorm of iq -> iq splits ---------------- grid NTOK*HIi, block 64
__global__ void iq_rms() {
    int blk = blockIdx.x;
    int h = blk & 7;
    int row = blk >> 3;
    int d = threadIdx.x;
    float v = g_Pall[(size_t)row * NCOL + OFF_IQ + h * 64 + d];
    __shared__ float red[64];
    red[d] = v * v;
    __syncthreads();
    #pragma unroll
    for (int s2 = 32; s2 > 0; s2 >>= 1) {
        if (d < s2) red[d] += red[d + s2];
        __syncthreads();
    }
    float sc = rsqrtf(red[0] / 64.f + 1e-6f);
    split2(v * sc, g_iqs, (size_t)row * 512 + h * 64 + (d & ~31), d & 31, PL_IQ);
}

// ---------------- in-place partial rope of q ---------------- grid NTOK*Hh, block 32
__global__ void q_rope() {
    int blk = blockIdx.x;
    int h = blk & 7;
    int row = blk >> 3;
    int t = row & (Tt - 1);
    int i = threadIdx.x;
    size_t base = (size_t)row * NCOL + OFF_Q + h * 128;
    float x1 = g_Pall[base + 64 + i];
    float x2 = g_Pall[base + 96 + i];
    float c, s; rope_cs(i, (float)t, c, s);
    g_Pall[base + 64 + i] = x1 * c - x2 * s;
    g_Pall[base + 96 + i] = x1 * s + x2 * c;
}

// ---------------- top-k(64) threshold via hybrid bitonic sort ---------------- grid NTOK, block 512
__global__ void topk_thresh() {
    __shared__ float s[512];
    int row = blockIdx.x;
    int t = row & (Tt - 1);
    int tid = threadIdx.x;
    float v = g_isc[(size_t)row * Gg + tid];
    if (4 * tid + 3 > t) v = NEGv;

    #pragma unroll
    for (int k = 2; k <= 32; k <<= 1) {
        #pragma unroll
        for (int j = k >> 1; j > 0; j >>= 1) {
            float p = __shfl_xor_sync(0xffffffffu, v, j);
            bool down  = ((tid & k) == 0);
            bool lower = ((tid & j) == 0);
            v = (lower == down) ? fmaxf(v, p) : fminf(v, p);
        }
    }
    s[tid] = v;
    __syncthreads();

    for (int k = 64; k <= 512; k <<= 1) {
        for (int j = k >> 1; j >= 32; j >>= 1) {
            int ixj = tid ^ j;
            if (ixj > tid) {
                float a = s[tid], b = s[ixj];
                bool down = ((tid & k) == 0);
                bool sw = down ? (a < b) : (a > b);
                if (sw) { s[tid] = b; s[ixj] = a; }
            }
            __syncthreads();
        }
        v = s[tid];
        #pragma unroll
        for (int j = 16; j > 0; j >>= 1) {
            float p = __shfl_xor_sync(0xffffffffu, v, j);
            bool down  = ((tid & k) == 0);
            bool lower = ((tid & j) == 0);
            v = (lower == down) ? fmaxf(v, p) : fminf(v, p);
        }
        if (k < 512) { s[tid] = v; __syncthreads(); }
    }
    if (tid == 63) g_thr[row] = v;
}

// ---------------- sparse attention, all 8 heads per block -> at splits ----------------
// grid NTOK, block 256. Warp w computes scores+softmax for head w (hkv=w>>1).
// V phase: thread (j0 = tid>>7, d = tid&127) accumulates heads {2j0,2j0+1,2j0+4,2j0+5}.
__global__ void __launch_bounds__(256) attn_kernel() {
    int row = blockIdx.x;
    int t = row & (Tt - 1);
    int b = row >> 11;
    int tid = threadIdx.x;
    int warp = tid >> 5, lane = tid & 31;
    __shared__ int sg[96];
    __shared__ float sw[8][96];
    __shared__ alignas(16) float qsh[1024];
    __shared__ int cnt;
    if (tid == 0) cnt = 0;
    __syncthreads();

    int nc = (t >= 3) ? (((t - 3) >> 2) + 1) : 0;
    float th = g_thr[row];
    const float* iscr = g_isc + (size_t)row * Gg;
    for (int g = tid; g < nc; g += 256) {
        if (iscr[g] >= th) {
            int p = atomicAdd(&cnt, 1);
            if (p < 96) sg[p] = g;
        }
    }
    #pragma unroll
    for (int i = 0; i < 4; i++)
        qsh[tid + i * 256] = g_Pall[(size_t)row * NCOL + OFF_Q + tid + i * 256];
    __syncthreads();
    int n = min(cnt, 96);

    // scores: warp w = head w
    {
        int hkv = warp >> 1;
        float4 qv = *(const float4*)(qsh + warp * 128 + lane * 4);
        for (int i = 0; i < n; i++) {
            const float* kp = g_ck + ((size_t)(b * Gg + sg[i]) * 4 + hkv) * 128;
            float4 kv = *(const float4*)(kp + lane * 4);
            float p = qv.x * kv.x + qv.y * kv.y + qv.z * kv.z + qv.w * kv.w;
            #pragma unroll
            for (int o = 16; o > 0; o >>= 1) p += __shfl_xor_sync(0xffffffffu, p, o);
            if (lane == 0) sw[warp][i] = p * 0.0883883476483184f;
        }
    }
    __syncthreads();

    // per-head warp softmax over n entries (n <= 96)
    {
        float v0 = (lane      < n) ? sw[warp][lane]      : -1e30f;
        float v1 = (lane + 32 < n) ? sw[warp][lane + 32] : -1e30f;
        float v2 = (lane + 64 < n) ? sw[warp][lane + 64] : -1e30f;
        float m = fmaxf(v0, fmaxf(v1, v2));
        #pragma unroll
        for (int o = 16; o > 0; o >>= 1) m = fmaxf(m, __shfl_xor_sync(0xffffffffu, m, o));
        float e0 = (lane      < n) ? expf(v0 - m) : 0.f;
        float e1 = (lane + 32 < n) ? expf(v1 - m) : 0.f;
        float e2 = (lane + 64 < n) ? expf(v2 - m) : 0.f;
        float ssum = e0 + e1 + e2;
        #pragma unroll
        for (int o = 16; o > 0; o >>= 1) ssum += __shfl_xor_sync(0xffffffffu, ssum, o);
        float inv = 1.f / ssum;
        if (lane      < n) sw[warp][lane]      = e0 * inv;
        if (lane + 32 < n) sw[warp][lane + 32] = e1 * inv;
        if (lane + 64 < n) sw[warp][lane + 64] = e2 * inv;
    }
    __syncthreads();

    // V accumulation: 4 outputs per thread, V row shared by head pairs
    {
        int d = tid & 127;
        int j0 = tid >> 7;               // hkv j0 and j0+2
        float a0 = 0.f, a1 = 0.f, a2 = 0.f, a3 = 0.f;
        for (int i = 0; i < n; i++) {
            size_t vb = (size_t)(b * Gg + sg[i]) * 4;
            float v0 = g_cv[(vb + j0) * 128 + d];
            float v1 = g_cv[(vb + j0 + 2) * 128 + d];
            a0 += sw[2 * j0][i]     * v0;
            a1 += sw[2 * j0 + 1][i] * v0;
            a2 += sw[2 * j0 + 4][i] * v1;
            a3 += sw[2 * j0 + 5][i] * v1;
        }
        size_t ob = (size_t)row * 1024 + (d & ~31);
        int kb = d & 31;
        split2(a0, g_ats, ob + (2 * j0) * 128,     kb, PL_AT);
        split2(a1, g_ats, ob + (2 * j0 + 1) * 128, kb, PL_AT);
        split2(a2, g_ats, ob + (2 * j0 + 4) * 128, kb, PL_AT);
        split2(a3, g_ats, ob + (2 * j0 + 5) * 128, kb, PL_AT);
    }
}

// ---------------- rmsnorm over RANK=512 -> rn splits ---------------- grid NTOK, block 256
__global__ void rmsnorm512() {
    int row = blockIdx.x;
    int tid = threadIdx.x;
    size_t base = (size_t)row * 512;
    float a = g_r[base + tid], b = g_r[base + 256 + tid];
    __shared__ float red[256];
    red[tid] = a * a + b * b;
    __syncthreads();
    #pragma unroll
    for (int s2 = 128; s2 > 0; s2 >>= 1) {
        if (tid < s2) red[tid] += red[tid + s2];
        __syncthreads();
    }
    float sc = rsqrtf(red[0] / 512.f + 1e-6f);
    split2(a * sc, g_rns, base + (tid & ~31), tid & 31, PL_RN);
    split2(b * sc, g_rns, base + 256 + (tid & ~31), tid & 31, PL_RN);
}

// ---------------- launch ----------------
extern "C" void kernel_launch(void* const* d_in, const int* in_sizes, int n_in,
                              void* d_out, int out_size) {
    const float* x     = (const float*)d_in[0];
    const float* Wq    = (const float*)d_in[1];
    const float* Wck   = (const float*)d_in[2];
    const float* Wcv   = (const float*)d_in[3];
    const float* Wcg   = (const float*)d_in[4];
    const float* ape_c = (const float*)d_in[5];
    const float* Wiq   = (const float*)d_in[6];
    const float* Wik   = (const float*)d_in[7];
    const float* Wig   = (const float*)d_in[8];
    const float* ape_i = (const float*)d_in[9];
    const float* Wa    = (const float*)d_in[10];
    const float* Wb    = (const float*)d_in[11];
    float* out = (float*)d_out;

    __half *xs, *WTs, *iks, *iqs, *ats, *Was, *rns, *Wbs;
    float *Pall, *isc, *r;
    cudaGetSymbolAddress((void**)&xs,   g_xs);
    cudaGetSymbolAddress((void**)&WTs,  g_WTs);
    cudaGetSymbolAddress((void**)&Pall, g_Pall);
    cudaGetSymbolAddress((void**)&iks,  g_iks);
    cudaGetSymbolAddress((void**)&iqs,  g_iqs);
    cudaGetSymbolAddress((void**)&isc,  g_isc);
    cudaGetSymbolAddress((void**)&ats,  g_ats);
    cudaGetSymbolAddress((void**)&Was,  g_Was);
    cudaGetSymbolAddress((void**)&r,    g_r);
    cudaGetSymbolAddress((void**)&rns,  g_rns);
    cudaGetSymbolAddress((void**)&Wbs,  g_Wbs);

    static cudaStream_t s2 = 0;
    static cudaEvent_t evA, evB, evC;
    static int attr_set = 0;
    if (!attr_set) {
        cudaFuncSetAttribute(mma_gemm_hx<0>, cudaFuncAttributeMaxDynamicSharedMemorySize, HSMEM);
        cudaFuncSetAttribute(mma_gemm_hx<2>, cudaFuncAttributeMaxDynamicSharedMemorySize, HSMEM);
        cudaFuncSetAttribute(mma_gemm_hx<3>, cudaFuncAttributeMaxDynamicSharedMemorySize, HSMEM);
        cudaStreamCreateWithFlags(&s2, cudaStreamNonBlocking);
        cudaEventCreateWithFlags(&evA, cudaEventDisableTiming);
        cudaEventCreateWithFlags(&evB, cudaEventDisableTiming);
        cudaEventCreateWithFlags(&evC, cudaEventDisableTiming);
        attr_set = 1;
    }

    // fork: side stream handles Wa/Wb splits (independent of main chain)
    cudaEventRecord(evA, 0);
    cudaStreamWaitEvent(s2, evA, 0);
    split_plain<<<(512 * 1024) / 256, 256, 0, s2>>>(Wa, Was, PL_WA, 512 * 1024);
    splitT_gen<<<dim3(512 / 32, 1024 / 32), dim3(32, 32), 0, s2>>>(Wb, Wbs, 512, 1024, PL_WB);

    // main: x/W splits + merged projection GEMM (per-tile 2-/3-term)
    split_plain<<<(NTOK * 1024) / 256, 256>>>(x, xs, PL_X, NTOK * 1024);
    splitT_w7<<<dim3(1024 / 32, NCOL / 32), dim3(32, 32)>>>(Wq, Wck, Wcv, Wcg, Wig, Wiq, Wik, WTs);
    mma_gemm_hx<0><<<dim3(NCOL / 128, NTOK / 128, 1), 256, HSMEM>>>(
        NTOK, NCOL, 1024, NCOL, 1.f, 0, xs, PL_X, 0, WTs, PL_WT, 0, Pall, 0);

    // fork: value-path prep on s2, concurrent with selection chain on main
    cudaEventRecord(evB, 0);
    cudaStreamWaitEvent(s2, evB, 0);
    compress_c<<<Bb * Gg * HKV, 128, 0, s2>>>(ape_c);
    q_rope<<<NTOK * Hh, 32, 0, s2>>>();
    cudaEventRecord(evC, s2);

    // main: selection chain
    compress_i<<<Bb * Gg * HIi, 64>>>(ape_i);
    iq_rms<<<NTOK * HIi, 64>>>();
    mma_gemm_hx<3><<<dim3(512 / 128, 2048 / 128, Bb), 256, HSMEM>>>(
        2048, 512, 512, 512, 1.f / 64.f, 1,
        iqs, PL_IQ, (long)2048 * 512,
        iks, PL_IK, (long)512 * 512,
        isc, (long)2048 * 512);
    topk_thresh<<<NTOK, 512>>>();

    // join: attn needs ck/cv/q (s2) + thr/isc (main)
    cudaStreamWaitEvent(0, evC, 0);
    attn_kernel<<<NTOK, 256>>>();

    // r = attn @ Wa^T (2-term)
    mma_gemm_hx<2><<<dim3(512 / 128, NTOK / 128, 1), 256, HSMEM>>>(
        NTOK, 512, 1024, 512, 1.f, 0, ats, PL_AT, 0, Was, PL_WA, 0, r, 0);

    rmsnorm512<<<NTOK, 256>>>();

    // out = rn @ Wb (2-term)
    mma_gemm_hx<2><<<dim3(1024 / 128, NTOK / 128, 1), 256, HSMEM>>>(
        NTOK, 1024, 512, 1024, 1.f, 0, rns, PL_RN, 0, Wbs, PL_WB, 0, out, 0);
}

// round 16
// speedup vs baseline: 3.1214x; 1.0429x over previous
#include <cuda_runtime.h>
#include <cuda_fp16.h>
#include <math.h>
#include <stdint.h>

// Problem constants
#define Bb 4
#define Tt 2048
#define Cc 1024
#define Hh 8
#define HKV 4
#define Dd 128
#define Gg 512
#define HIi 8
#define DIi 64
#define NEGv (-1e30f)

#define NTOK (Bb*Tt)   // 8192
#define NCOL 4096      // fused projection width: q|ck|cv|cg | ig|iq|ik
#define OFF_Q  0
#define OFF_CK 1024
#define OFF_CV 1536
#define OFF_CG 2048
#define OFF_IG 2560
#define OFF_IQ 3072
#define OFF_IK 3584
#define SPLIT_COL 2560   // [0,2560) 2-term ; [2560,4096) 3-term (selection chain)

// plane strides (elements)
#define PL_X   ((long)NTOK*1024)
#define PL_WT  ((long)NCOL*1024)
#define PL_IQ  ((long)NTOK*512)
#define PL_IK  ((long)Bb*512*512)
#define PL_AT  ((long)NTOK*1024)
#define PL_WA  ((long)512*1024)
#define PL_RN  ((long)NTOK*512)
#define PL_WB  ((long)1024*512)

// ---------------- scratch (static device allocations) ----------------
__device__ alignas(256) __half g_xs [2*PL_X];
__device__ alignas(256) __half g_WTs[2*PL_WT];
__device__ alignas(256) float g_Pall[(size_t)NTOK*NCOL];
__device__ alignas(256) float g_ck [Bb*Gg*HKV*Dd];
__device__ alignas(256) float g_cv [Bb*Gg*HKV*Dd];
__device__ alignas(256) __half g_iks[2*PL_IK];
__device__ alignas(256) __half g_iqs[2*PL_IQ];
__device__ alignas(256) float g_isc[NTOK*Gg];
__device__ alignas(256) float g_thr[NTOK];
__device__ alignas(256) __half g_ats[2*PL_AT];
__device__ alignas(256) __half g_Was[2*PL_WA];
__device__ alignas(256) float g_r  [NTOK*512];
__device__ alignas(256) __half g_rns[2*PL_RN];
__device__ alignas(256) __half g_Wbs[2*PL_WB];

// ---------------- helpers ----------------
__device__ __forceinline__ void cpa16(uint32_t dst, const void* src) {
    asm volatile("cp.async.cg.shared.global [%0], [%1], 16;\n" :: "r"(dst), "l"(src));
}
__device__ __forceinline__ void cp_commit() {
    asm volatile("cp.async.commit_group;\n");
}
// k-permutation within a 32-element group: u32 j -> ((j&3)<<2)|(j>>2)
__device__ __forceinline__ int permk(int idx) {
    int kk = idx & 31;
    int j = kk >> 1;
    int jn = ((j & 3) << 2) | (j >> 2);
    return (idx & ~31) | (jn << 1) | (kk & 1);
}
// fp16 2-way split with permuted k index
__device__ __forceinline__ void split2(float v, __half* p, size_t base, int kidx, long plane) {
    __half h0 = __float2half_rn(v);
    float r1 = v - __half2float(h0);
    size_t idx = base + (size_t)permk(kidx);
    p[idx]         = h0;
    p[idx + plane] = __float2half_rn(r1);
}
__device__ __forceinline__ void mma_f16(float* c,
    uint32_t a0, uint32_t a1, uint32_t a2, uint32_t a3,
    uint32_t b0, uint32_t b1) {
    asm volatile(
        "mma.sync.aligned.m16n8k16.row.col.f32.f16.f16.f32 "
        "{%0,%1,%2,%3},{%4,%5,%6,%7},{%8,%9},{%0,%1,%2,%3};"
        : "+f"(c[0]), "+f"(c[1]), "+f"(c[2]), "+f"(c[3])
        : "r"(a0), "r"(a1), "r"(a2), "r"(a3), "r"(b0), "r"(b1));
}
__device__ __forceinline__ uint4 lds128(uint32_t addr) {
    uint4 v;
    asm volatile("ld.shared.v4.u32 {%0,%1,%2,%3}, [%4];"
                 : "=r"(v.x), "=r"(v.y), "=r"(v.z), "=r"(v.w) : "r"(addr));
    return v;
}

// ---------------- fp16 split MMA GEMM: C = alpha * A[M,K] @ B[N,K]^T ----------------
// NT=3: a0b0+a0b1+a1b0 (fp32-accurate ~2^-24). NT=2: a0b0+a0b1 (~2e-4 rel).
// A, B as 2 fp16 split planes (NT=2 reads only A plane0), k-permuted per 32-group.
// BM=BN=128, BK=32, 256 threads (8 warps 2x4), warp tile 64x32. ldc = C row stride.
// 3-stage cp.async pipeline. causal=1: skip tiles with bm+124 < 4*bn (never read).
#define HPLANE 2048          // 128 rows * 16 u32
#define HBUF   4096          // 2 planes
#define HTOT   8192          // A + B per buffer
#define HSMEM  (3 * HTOT * 4)  // 98304 bytes (3 stages)

template<int NT>
__global__ void __launch_bounds__(256, 2) mma_gemm_hx(
    int M, int N, int K, int ldc, float alpha, int causal,
    const __half* __restrict__ A0, long planeA, long batA,
    const __half* __restrict__ B0, long planeB, long batB,
    float* __restrict__ C, long batC) {
    extern __shared__ char smraw[];
    uint32_t sbase = (uint32_t)__cvta_generic_to_shared(smraw);

    const int tid  = threadIdx.x;
    const int wid  = tid >> 5;
    const int lane = tid & 31;
    const int lm   = lane >> 2;     // 0..7
    const int lk   = lane & 3;      // 0..3
    const int warp_m = (wid & 1) * 64;
    const int warp_n = (wid >> 1) * 32;
    const int bm = blockIdx.y * 128;
    const int bn = blockIdx.x * 128;
    const int z  = blockIdx.z;

    if (causal && (bm + 124 < 4 * bn)) return;   // tile fully causally masked

    const __half* Abase = A0 + (size_t)z * batA;
    const __half* Bbase = B0 + (size_t)z * batB;
    float* Cptr = C + (size_t)z * batC + (size_t)(bm + warp_m) * ldc + bn + warp_n;

    float c[4][4][4];
    #pragma unroll
    for (int mt = 0; mt < 4; mt++)
        #pragma unroll
        for (int nt = 0; nt < 4; nt++)
            #pragma unroll
            for (int i = 0; i < 4; i++) c[mt][nt][i] = 0.f;

    const int nIter = K >> 5;

    auto stage = [&](int it, int buf) {
        const int k0 = it * 32;
        const uint32_t abase = sbase + (uint32_t)(buf * HTOT) * 4u;
        const uint32_t bbase = abase + HBUF * 4u;
        #pragma unroll
        for (int i = 0; i < (NT == 2 ? 2 : 4); i++) {
            int id = tid + i * 256;
            int p = id >> 9, rem = id & 511, row = rem >> 2, cc = rem & 3;
            cpa16(abase + (uint32_t)(p * HPLANE + row * 16 + cc * 4) * 4u,
                  Abase + (size_t)p * planeA + (size_t)(bm + row) * K + k0 + cc * 8);
        }
        #pragma unroll
        for (int i = 0; i < 4; i++) {
            int id = tid + i * 256;
            int p = id >> 9, rem = id & 511, row = rem >> 2, cc = rem & 3;
            cpa16(bbase + (uint32_t)(p * HPLANE + row * 16 + cc * 4) * 4u,
                  Bbase + (size_t)p * planeB + (size_t)(bn + row) * K + k0 + cc * 8);
        }
        cp_commit();
    };

    stage(0, 0);
    if (nIter > 1) stage(1, 1);

    int buf = 0;
    for (int it = 0; it < nIter; it++) {
        if (it + 1 < nIter) {
            asm volatile("cp.async.wait_group 1;\n" ::: "memory");
        } else {
            asm volatile("cp.async.wait_group 0;\n" ::: "memory");
        }
        __syncthreads();
        if (it + 2 < nIter) stage(it + 2, (buf + 2 >= 3) ? buf - 1 : buf + 2);

        const uint32_t abufb = sbase + (uint32_t)(buf * HTOT) * 4u;
        const uint32_t bbufb = abufb + HBUF * 4u;

        uint4 b0f[4], b1f[4];
        #pragma unroll
        for (int nt = 0; nt < 4; nt++) {
            uint32_t baddr = bbufb + (uint32_t)(warp_n + nt * 8 + lm) * 64u + lk * 16u;
            b0f[nt] = lds128(baddr);
            b1f[nt] = lds128(baddr + HPLANE * 4u);
        }

        #pragma unroll
        for (int mt = 0; mt < 4; mt++) {
            const uint32_t aaddr = abufb + (uint32_t)(warp_m + mt * 16 + lm) * 64u + lk * 16u;
            uint4 alo0 = lds128(aaddr);
            uint4 ahi0 = lds128(aaddr + 8u * 64u);
            #pragma unroll
            for (int nt = 0; nt < 4; nt++)
                mma_f16(c[mt][nt], alo0.x, ahi0.x, alo0.y, ahi0.y, b0f[nt].x, b0f[nt].y);
            #pragma unroll
            for (int nt = 0; nt < 4; nt++)
                mma_f16(c[mt][nt], alo0.x, ahi0.x, alo0.y, ahi0.y, b1f[nt].x, b1f[nt].y);
            #pragma unroll
            for (int nt = 0; nt < 4; nt++)
                mma_f16(c[mt][nt], alo0.z, ahi0.z, alo0.w, ahi0.w, b0f[nt].z, b0f[nt].w);
            #pragma unroll
            for (int nt = 0; nt < 4; nt++)
                mma_f16(c[mt][nt], alo0.z, ahi0.z, alo0.w, ahi0.w, b1f[nt].z, b1f[nt].w);
            if (NT == 3) {
                uint4 alo1 = lds128(aaddr + HPLANE * 4u);
                uint4 ahi1 = lds128(aaddr + HPLANE * 4u + 8u * 64u);
                #pragma unroll
                for (int nt = 0; nt < 4; nt++)
                    mma_f16(c[mt][nt], alo1.x, ahi1.x, alo1.y, ahi1.y, b0f[nt].x, b0f[nt].y);
                #pragma unroll
                for (int nt = 0; nt < 4; nt++)
                    mma_f16(c[mt][nt], alo1.z, ahi1.z, alo1.w, ahi1.w, b0f[nt].z, b0f[nt].w);
            }
        }
        buf = (buf + 1 >= 3) ? 0 : buf + 1;
    }

    #pragma unroll
    for (int mt = 0; mt < 4; mt++) {
        #pragma unroll
        for (int nt = 0; nt < 4; nt++) {
            int r0 = mt * 16 + lm;
            int cc = nt * 8 + 2 * lk;
            float2 v;
            v.x = c[mt][nt][0] * alpha; v.y = c[mt][nt][1] * alpha;
            *(float2*)(Cptr + (size_t)r0 * ldc + cc) = v;
            v.x = c[mt][nt][2] * alpha; v.y = c[mt][nt][3] * alpha;
            *(float2*)(Cptr + (size_t)(r0 + 8) * ldc + cc) = v;
        }
    }
}

// ---------------- split kernels (write permuted k layout) ----------------
__global__ void split_plain(const float* __restrict__ src, __half* dst,
                            long plane, int n) {
    int idx = blockIdx.x * 256 + threadIdx.x;
    if (idx < n) split2(src[idx], dst, (size_t)(idx & ~31), idx & 31, plane);
}

// fused 7-weight concat + transpose + split: out planes [4096][1024]
// column order: q | ck | cv | cg | ig | iq | ik
__global__ void splitT_w7(const float* __restrict__ Wq,  const float* __restrict__ Wck,
                          const float* __restrict__ Wcv, const float* __restrict__ Wcg,
                          const float* __restrict__ Wig, const float* __restrict__ Wiq,
                          const float* __restrict__ Wik, __half* out) {
    __shared__ float tile[32][33];
    int k0 = blockIdx.x * 32, n0 = blockIdx.y * 32;
    int tx = threadIdx.x, ty = threadIdx.y;
    {
        int k = k0 + ty, n = n0 + tx;
        float v;
        if      (n < 1024) v = Wq [k * 1024 + n];
        else if (n < 1536) v = Wck[k * 512 + n - 1024];
        else if (n < 2048) v = Wcv[k * 512 + n - 1536];
        else if (n < 2560) v = Wcg[k * 512 + n - 2048];
        else if (n < 3072) v = Wig[k * 512 + n - 2560];
        else if (n < 3584) v = Wiq[k * 512 + n - 3072];
        else               v = Wik[k * 512 + n - 3584];
        tile[ty][tx] = v;
    }
    __syncthreads();
    int n = n0 + ty, k = k0 + tx;
    split2(tile[tx][ty], out, (size_t)n * 1024 + (k & ~31), k & 31, PL_WT);
}

// generic transpose+split: src [Kd][Nd] -> out planes [Nd][Kd]
__global__ void splitT_gen(const float* __restrict__ src, __half* out,
                           int Kd, int Nd, long plane) {
    __shared__ float tile[32][33];
    int k0 = blockIdx.x * 32, n0 = blockIdx.y * 32;
    int tx = threadIdx.x, ty = threadIdx.y;
    tile[ty][tx] = src[(size_t)(k0 + ty) * Nd + n0 + tx];
    __syncthreads();
    int n = n0 + ty, k = k0 + tx;
    split2(tile[tx][ty], out, (size_t)n * Kd + (k & ~31), k & 31, plane);
}

// ---------------- rope helper ----------------
__device__ __forceinline__ void rope_cs(int i, float pos, float& c, float& s) {
    float f = powf(160000.0f, (float)i * (1.0f / 32.0f));
    float ang = pos / f;
    sincosf(ang, &s, &c);
}

// ---------------- gated compress (coarse KV) + rope on ck ---------------- grid Bb*Gg*HKV, block 128
__global__ void compress_c(const float* __restrict__ ape) {
    int blk = blockIdx.x;
    int h = blk & 3;
    int bg = blk >> 2;
    int g = bg & (Gg - 1);
    int d = threadIdx.x;
    size_t base = (size_t)bg * 4 * NCOL + h * 128 + d;
    float gv[4], m = -1e30f;
    #pragma unroll
    for (int r = 0; r < 4; r++) {
        gv[r] = g_Pall[base + (size_t)r * NCOL + OFF_CG] + ape[(r * HKV + h) * 128 + d];
        m = fmaxf(m, gv[r]);
    }
    float ssum = 0.f;
    #pragma unroll
    for (int r = 0; r < 4; r++) { gv[r] = expf(gv[r] - m); ssum += gv[r]; }
    float inv = 1.f / ssum;
    float ka = 0.f, va = 0.f;
    #pragma unroll
    for (int r = 0; r < 4; r++) {
        float w = gv[r] * inv;
        ka += w * g_Pall[base + (size_t)r * NCOL + OFF_CK];
        va += w * g_Pall[base + (size_t)r * NCOL + OFF_CV];
    }
    __shared__ float sk[128];
    sk[d] = ka;
    __syncthreads();
    float pos = (float)(4 * g + 3);
    float outk = ka;
    if (d >= 64 && d < 96) {
        int i = d - 64; float c, s; rope_cs(i, pos, c, s);
        outk = sk[d] * c - sk[d + 32] * s;
    } else if (d >= 96) {
        int i = d - 96; float c, s; rope_cs(i, pos, c, s);
        outk = sk[d - 32] * s + sk[d] * c;
    }
    size_t ob = ((size_t)bg * 4 + h) * 128 + d;
    g_ck[ob] = outk;
    g_cv[ob] = va;
}

// ---------------- gated compress (index KV) + rmsnorm -> ik splits ---------------- grid Bb*Gg*HIi, block 64
__global__ void compress_i(const float* __restrict__ ape) {
    int blk = blockIdx.x;
    int h = blk & 7;
    int bg = blk >> 3;
    int d = threadIdx.x;
    size_t base = (size_t)bg * 4 * NCOL + h * 64 + d;
    float gv[4], m = -1e30f;
    #pragma unroll
    for (int r = 0; r < 4; r++) {
        gv[r] = g_Pall[base + (size_t)r * NCOL + OFF_IG] + ape[(r * HIi + h) * 64 + d];
        m = fmaxf(m, gv[r]);
    }
    float ssum = 0.f;
    #pragma unroll
    for (int r = 0; r < 4; r++) { gv[r] = expf(gv[r] - m); ssum += gv[r]; }
    float inv = 1.f / ssum;
    float ka = 0.f;
    #pragma unroll
    for (int r = 0; r < 4; r++)
        ka += gv[r] * inv * g_Pall[base + (size_t)r * NCOL + OFF_IK];
    __shared__ float red[64];
    red[d] = ka * ka;
    __syncthreads();
    #pragma unroll
    for (int s2 = 32; s2 > 0; s2 >>= 1) {
        if (d < s2) red[d] += red[d + s2];
        __syncthreads();
    }
    float sc = rsqrtf(red[0] / 64.f + 1e-6f);
    split2(ka * sc, g_iks, (size_t)bg * 512 + h * 64 + (d & ~31), d & 31, PL_IK);
}

// ---------------- per-head rmsnorm of iq -> iq splits ---------------- grid NTOK*HIi, block 64
__global__ void iq_rms() {
    int blk = blockIdx.x;
    int h = blk & 7;
    int row = blk >> 3;
    int d = threadIdx.x;
    float v = g_Pall[(size_t)row * NCOL + OFF_IQ + h * 64 + d];
    __shared__ float red[64];
    red[d] = v * v;
    __syncthreads();
    #pragma unroll
    for (int s2 = 32; s2 > 0; s2 >>= 1) {
        if (d < s2) red[d] += red[d + s2];
        __syncthreads();
    }
    float sc = rsqrtf(red[0] / 64.f + 1e-6f);
    split2(v * sc, g_iqs, (size_t)row * 512 + h * 64 + (d & ~31), d & 31, PL_IQ);
}

// ---------------- in-place partial rope of q ---------------- grid NTOK*Hh, block 32
__global__ void q_rope() {
    int blk = blockIdx.x;
    int h = blk & 7;
    int row = blk >> 3;
    int t = row & (Tt - 1);
    int i = threadIdx.x;
    size_t base = (size_t)row * NCOL + OFF_Q + h * 128;
    float x1 = g_Pall[base + 64 + i];
    float x2 = g_Pall[base + 96 + i];
    float c, s; rope_cs(i, (float)t, c, s);
    g_Pall[base + 64 + i] = x1 * c - x2 * s;
    g_Pall[base + 96 + i] = x1 * s + x2 * c;
}

// ---------------- top-k(64) threshold via hybrid bitonic sort ---------------- grid NTOK, block 512
__global__ void topk_thresh() {
    __shared__ float s[512];
    int row = blockIdx.x;
    int t = row & (Tt - 1);
    int tid = threadIdx.x;
    float v = g_isc[(size_t)row * Gg + tid];
    if (4 * tid + 3 > t) v = NEGv;

    #pragma unroll
    for (int k = 2; k <= 32; k <<= 1) {
        #pragma unroll
        for (int j = k >> 1; j > 0; j >>= 1) {
            float p = __shfl_xor_sync(0xffffffffu, v, j);
            bool down  = ((tid & k) == 0);
            bool lower = ((tid & j) == 0);
            v = (lower == down) ? fmaxf(v, p) : fminf(v, p);
        }
    }
    s[tid] = v;
    __syncthreads();

    for (int k = 64; k <= 512; k <<= 1) {
        for (int j = k >> 1; j >= 32; j >>= 1) {
            int ixj = tid ^ j;
            if (ixj > tid) {
                float a = s[tid], b = s[ixj];
                bool down = ((tid & k) == 0);
                bool sw = down ? (a < b) : (a > b);
                if (sw) { s[tid] = b; s[ixj] = a; }
            }
            __syncthreads();
        }
        v = s[tid];
        #pragma unroll
        for (int j = 16; j > 0; j >>= 1) {
            float p = __shfl_xor_sync(0xffffffffu, v, j);
            bool down  = ((tid & k) == 0);
            bool lower = ((tid & j) == 0);
            v = (lower == down) ? fmaxf(v, p) : fminf(v, p);
        }
        if (k < 512) { s[tid] = v; __syncthreads(); }
    }
    if (tid == 63) g_thr[row] = v;
}

// ---------------- sparse attention, all 8 heads per block -> at splits ----------------
// grid NTOK, block 256. Warp w computes scores+softmax for head w (hkv=w>>1).
// V phase: thread (j0 = tid>>7, d = tid&127) accumulates heads {2j0,2j0+1,2j0+4,2j0+5}.
__global__ void __launch_bounds__(256) attn_kernel() {
    int row = blockIdx.x;
    int t = row & (Tt - 1);
    int b = row >> 11;
    int tid = threadIdx.x;
    int warp = tid >> 5, lane = tid & 31;
    __shared__ int sg[96];
    __shared__ float sw[8][96];
    __shared__ alignas(16) float qsh[1024];
    __shared__ int cnt;
    if (tid == 0) cnt = 0;
    __syncthreads();

    int nc = (t >= 3) ? (((t - 3) >> 2) + 1) : 0;
    float th = g_thr[row];
    const float* iscr = g_isc + (size_t)row * Gg;
    for (int g = tid; g < nc; g += 256) {
        if (iscr[g] >= th) {
            int p = atomicAdd(&cnt, 1);
            if (p < 96) sg[p] = g;
        }
    }
    #pragma unroll
    for (int i = 0; i < 4; i++)
        qsh[tid + i * 256] = g_Pall[(size_t)row * NCOL + OFF_Q + tid + i * 256];
    __syncthreads();
    int n = min(cnt, 96);

    // scores: warp w = head w
    {
        int hkv = warp >> 1;
        float4 qv = *(const float4*)(qsh + warp * 128 + lane * 4);
        #pragma unroll 2
        for (int i = 0; i < n; i++) {
            const float* kp = g_ck + ((size_t)(b * Gg + sg[i]) * 4 + hkv) * 128;
            float4 kv = *(const float4*)(kp + lane * 4);
            float p = qv.x * kv.x + qv.y * kv.y + qv.z * kv.z + qv.w * kv.w;
            #pragma unroll
            for (int o = 16; o > 0; o >>= 1) p += __shfl_xor_sync(0xffffffffu, p, o);
            if (lane == 0) sw[warp][i] = p * 0.0883883476483184f;
        }
    }
    __syncthreads();

    // per-head warp softmax over n entries (n <= 96)
    {
        float v0 = (lane      < n) ? sw[warp][lane]      : -1e30f;
        float v1 = (lane + 32 < n) ? sw[warp][lane + 32] : -1e30f;
        float v2 = (lane + 64 < n) ? sw[warp][lane + 64] : -1e30f;
        float m = fmaxf(v0, fmaxf(v1, v2));
        #pragma unroll
        for (int o = 16; o > 0; o >>= 1) m = fmaxf(m, __shfl_xor_sync(0xffffffffu, m, o));
        float e0 = (lane      < n) ? expf(v0 - m) : 0.f;
        float e1 = (lane + 32 < n) ? expf(v1 - m) : 0.f;
        float e2 = (lane + 64 < n) ? expf(v2 - m) : 0.f;
        float ssum = e0 + e1 + e2;
        #pragma unroll
        for (int o = 16; o > 0; o >>= 1) ssum += __shfl_xor_sync(0xffffffffu, ssum, o);
        float inv = 1.f / ssum;
        if (lane      < n) sw[warp][lane]      = e0 * inv;
        if (lane + 32 < n) sw[warp][lane + 32] = e1 * inv;
        if (lane + 64 < n) sw[warp][lane + 64] = e2 * inv;
    }
    __syncthreads();

    // V accumulation: 4 outputs per thread, V row shared by head pairs
    {
        int d = tid & 127;
        int j0 = tid >> 7;               // hkv j0 and j0+2
        float a0 = 0.f, a1 = 0.f, a2 = 0.f, a3 = 0.f;
        #pragma unroll 2
        for (int i = 0; i < n; i++) {
            size_t vb = (size_t)(b * Gg + sg[i]) * 4;
            float v0 = g_cv[(vb + j0) * 128 + d];
            float v1 = g_cv[(vb + j0 + 2) * 128 + d];
            a0 += sw[2 * j0][i]     * v0;
            a1 += sw[2 * j0 + 1][i] * v0;
            a2 += sw[2 * j0 + 4][i] * v1;
            a3 += sw[2 * j0 + 5][i] * v1;
        }
        size_t ob = (size_t)row * 1024 + (d & ~31);
        int kb = d & 31;
        split2(a0, g_ats, ob + (2 * j0) * 128,     kb, PL_AT);
        split2(a1, g_ats, ob + (2 * j0 + 1) * 128, kb, PL_AT);
        split2(a2, g_ats, ob + (2 * j0 + 4) * 128, kb, PL_AT);
        split2(a3, g_ats, ob + (2 * j0 + 5) * 128, kb, PL_AT);
    }
}

// ---------------- rmsnorm over RANK=512 -> rn splits ---------------- grid NTOK, block 256
__global__ void rmsnorm512() {
    int row = blockIdx.x;
    int tid = threadIdx.x;
    size_t base = (size_t)row * 512;
    float a = g_r[base + tid], b = g_r[base + 256 + tid];
    __shared__ float red[256];
    red[tid] = a * a + b * b;
    __syncthreads();
    #pragma unroll
    for (int s2 = 128; s2 > 0; s2 >>= 1) {
        if (tid < s2) red[tid] += red[tid + s2];
        __syncthreads();
    }
    float sc = rsqrtf(red[0] / 512.f + 1e-6f);
    split2(a * sc, g_rns, base + (tid & ~31), tid & 31, PL_RN);
    split2(b * sc, g_rns, base + 256 + (tid & ~31), tid & 31, PL_RN);
}

// ---------------- launch ----------------
extern "C" void kernel_launch(void* const* d_in, const int* in_sizes, int n_in,
                              void* d_out, int out_size) {
    const float* x     = (const float*)d_in[0];
    const float* Wq    = (const float*)d_in[1];
    const float* Wck   = (const float*)d_in[2];
    const float* Wcv   = (const float*)d_in[3];
    const float* Wcg   = (const float*)d_in[4];
    const float* ape_c = (const float*)d_in[5];
    const float* Wiq   = (const float*)d_in[6];
    const float* Wik   = (const float*)d_in[7];
    const float* Wig   = (const float*)d_in[8];
    const float* ape_i = (const float*)d_in[9];
    const float* Wa    = (const float*)d_in[10];
    const float* Wb    = (const float*)d_in[11];
    float* out = (float*)d_out;

    __half *xs, *WTs, *iks, *iqs, *ats, *Was, *rns, *Wbs;
    float *Pall, *isc, *r;
    cudaGetSymbolAddress((void**)&xs,   g_xs);
    cudaGetSymbolAddress((void**)&WTs,  g_WTs);
    cudaGetSymbolAddress((void**)&Pall, g_Pall);
    cudaGetSymbolAddress((void**)&iks,  g_iks);
    cudaGetSymbolAddress((void**)&iqs,  g_iqs);
    cudaGetSymbolAddress((void**)&isc,  g_isc);
    cudaGetSymbolAddress((void**)&ats,  g_ats);
    cudaGetSymbolAddress((void**)&Was,  g_Was);
    cudaGetSymbolAddress((void**)&r,    g_r);
    cudaGetSymbolAddress((void**)&rns,  g_rns);
    cudaGetSymbolAddress((void**)&Wbs,  g_Wbs);

    static cudaStream_t s2 = 0;
    static cudaEvent_t evA, evX, ev3, evSel;
    static int attr_set = 0;
    if (!attr_set) {
        cudaFuncSetAttribute(mma_gemm_hx<2>, cudaFuncAttributeMaxDynamicSharedMemorySize, HSMEM);
        cudaFuncSetAttribute(mma_gemm_hx<3>, cudaFuncAttributeMaxDynamicSharedMemorySize, HSMEM);
        cudaStreamCreateWithFlags(&s2, cudaStreamNonBlocking);
        cudaEventCreateWithFlags(&evA,   cudaEventDisableTiming);
        cudaEventCreateWithFlags(&evX,   cudaEventDisableTiming);
        cudaEventCreateWithFlags(&ev3,   cudaEventDisableTiming);
        cudaEventCreateWithFlags(&evSel, cudaEventDisableTiming);
        attr_set = 1;
    }

    // fork: s2 does x split (needed by proj) then Wa/Wb splits
    cudaEventRecord(evA, 0);
    cudaStreamWaitEvent(s2, evA, 0);
    split_plain<<<(NTOK * 1024) / 256, 256, 0, s2>>>(x, xs, PL_X, NTOK * 1024);
    cudaEventRecord(evX, s2);
    split_plain<<<(512 * 1024) / 256, 256, 0, s2>>>(Wa, Was, PL_WA, 512 * 1024);
    splitT_gen<<<dim3(512 / 32, 1024 / 32), dim3(32, 32), 0, s2>>>(Wb, Wbs, 512, 1024, PL_WB);

    // main: weight concat/split, then 3-term projection FIRST (selection columns)
    splitT_w7<<<dim3(1024 / 32, NCOL / 32), dim3(32, 32)>>>(Wq, Wck, Wcv, Wcg, Wig, Wiq, Wik, WTs);
    cudaStreamWaitEvent(0, evX, 0);
    mma_gemm_hx<3><<<dim3((NCOL - SPLIT_COL) / 128, NTOK / 128, 1), 256, HSMEM>>>(
        NTOK, NCOL - SPLIT_COL, 1024, NCOL, 1.f, 0, xs, PL_X, 0,
        WTs + (size_t)SPLIT_COL * 1024, PL_WT, 0, Pall + SPLIT_COL, 0);
    cudaEventRecord(ev3, 0);

    // s2: selection chain runs concurrently with the 2-term projection below
    cudaStreamWaitEvent(s2, ev3, 0);
    compress_i<<<Bb * Gg * HIi, 64, 0, s2>>>(ape_i);
    iq_rms<<<NTOK * HIi, 64, 0, s2>>>();
    mma_gemm_hx<3><<<dim3(512 / 128, 2048 / 128, Bb), 256, HSMEM, s2>>>(
        2048, 512, 512, 512, 1.f / 64.f, 1,
        iqs, PL_IQ, (long)2048 * 512,
        iks, PL_IK, (long)512 * 512,
        isc, (long)2048 * 512);
    topk_thresh<<<NTOK, 512, 0, s2>>>();
    cudaEventRecord(evSel, s2);

    // main: 2-term projection (value columns) + value prep
    mma_gemm_hx<2><<<dim3(SPLIT_COL / 128, NTOK / 128, 1), 256, HSMEM>>>(
        NTOK, SPLIT_COL, 1024, NCOL, 1.f, 0, xs, PL_X, 0, WTs, PL_WT, 0, Pall, 0);
    compress_c<<<Bb * Gg * HKV, 128>>>(ape_c);
    q_rope<<<NTOK * Hh, 32>>>();

    // join: attn needs selection (s2) + values (main)
    cudaStreamWaitEvent(0, evSel, 0);
    attn_kernel<<<NTOK, 256>>>();

    // r = attn @ Wa^T (2-term)
    mma_gemm_hx<2><<<dim3(512 / 128, NTOK / 128, 1), 256, HSMEM>>>(
        NTOK, 512, 1024, 512, 1.f, 0, ats, PL_AT, 0, Was, PL_WA, 0, r, 0);

    rmsnorm512<<<NTOK, 256>>>();

    // out = rn @ Wb (2-term)
    mma_gemm_hx<2><<<dim3(1024 / 128, NTOK / 128, 1), 256, HSMEM>>>(
        NTOK, 1024, 512, 1024, 1.f, 0, rns, PL_RN, 0, Wbs, PL_WB, 0, out, 0);
}